// round 1
// baseline (speedup 1.0000x reference)
#include <cuda_runtime.h>
#include <math.h>

// Problem constants (fixed by the reference)
#define BATCH   2
#define SEQ     2048
#define DMODEL  1024
#define NH      16
#define HD      64
#define TOKENS  (BATCH*SEQ)          // 4096

// Scratch: __device__ globals (allocation inside kernel_launch is forbidden)
__device__ float g_qkv[(size_t)TOKENS * 3 * DMODEL];  // [4096, 3072]
__device__ float g_h  [(size_t)TOKENS * DMODEL];      // [4096, 1024]

// ---------------------------------------------------------------------------
// SGEMM: C[M,N] = A[M,K] @ B[N,K]^T   (both row-major; B is a [N,K] weight)
// 128x128 block tile, 8x8 per thread, 256 threads, BK=16.
// All dims here are multiples of the tile sizes (4096/3072/1024/1024).
// ---------------------------------------------------------------------------
#define GBM 128
#define GBN 128
#define GBK 16
#define GTM 8
#define GTN 8

__global__ __launch_bounds__(256) void sgemm_nt(const float* __restrict__ A,
                                                const float* __restrict__ B,
                                                float* __restrict__ C,
                                                int M, int N, int K) {
    __shared__ float As[GBK][GBM];
    __shared__ float Bs[GBK][GBN];

    const int tid  = threadIdx.x;
    const int brow = blockIdx.y;
    const int bcol = blockIdx.x;

    const float* Ab = A + (size_t)brow * GBM * K;
    const float* Bb = B + (size_t)bcol * GBN * K;

    // Loader mapping: each thread loads 2 float4 from A and 2 from B per k-step
    const int lr = tid >> 2;          // 0..63 (row within tile, +64 for second)
    const int lc = (tid & 3) << 2;    // 0,4,8,12 (col within BK)

    // Compute mapping: 16x16 thread grid, 8x8 accumulator
    const int trow = (tid >> 4) * GTM;
    const int tcol = (tid & 15) * GTN;

    float acc[GTM][GTN] = {};

    for (int k0 = 0; k0 < K; k0 += GBK) {
        #pragma unroll
        for (int r = 0; r < 2; ++r) {
            const int row = lr + 64 * r;
            float4 va = *(const float4*)(Ab + (size_t)row * K + k0 + lc);
            As[lc + 0][row] = va.x;
            As[lc + 1][row] = va.y;
            As[lc + 2][row] = va.z;
            As[lc + 3][row] = va.w;
            float4 vb = *(const float4*)(Bb + (size_t)row * K + k0 + lc);
            Bs[lc + 0][row] = vb.x;
            Bs[lc + 1][row] = vb.y;
            Bs[lc + 2][row] = vb.z;
            Bs[lc + 3][row] = vb.w;
        }
        __syncthreads();

        #pragma unroll
        for (int k = 0; k < GBK; ++k) {
            float ra[GTM], rb[GTN];
            float4 a0 = *(const float4*)&As[k][trow];
            float4 a1 = *(const float4*)&As[k][trow + 4];
            ra[0]=a0.x; ra[1]=a0.y; ra[2]=a0.z; ra[3]=a0.w;
            ra[4]=a1.x; ra[5]=a1.y; ra[6]=a1.z; ra[7]=a1.w;
            float4 b0 = *(const float4*)&Bs[k][tcol];
            float4 b1 = *(const float4*)&Bs[k][tcol + 4];
            rb[0]=b0.x; rb[1]=b0.y; rb[2]=b0.z; rb[3]=b0.w;
            rb[4]=b1.x; rb[5]=b1.y; rb[6]=b1.z; rb[7]=b1.w;
            #pragma unroll
            for (int i = 0; i < GTM; ++i)
                #pragma unroll
                for (int j = 0; j < GTN; ++j)
                    acc[i][j] += ra[i] * rb[j];
        }
        __syncthreads();
    }

    float* Cb = C + (size_t)(brow * GBM + trow) * N + bcol * GBN + tcol;
    #pragma unroll
    for (int i = 0; i < GTM; ++i) {
        #pragma unroll
        for (int j = 0; j < GTN; j += 4) {
            float4 v = make_float4(acc[i][j], acc[i][j+1], acc[i][j+2], acc[i][j+3]);
            *(float4*)(Cb + (size_t)i * N + j) = v;
        }
    }
}

// ---------------------------------------------------------------------------
// Flash attention, fp32, causal.
// Block = 64 queries of one (batch, head). 128 threads.
// K tiles of 32. Online softmax fully in registers via shfl butterflies.
// Q/K stored d-major ([HD][q], pad 68/36 for aligned LDS.128); P stored
// k-major; V natural. All GEMM inner-loop reads are contiguous float4.
// ---------------------------------------------------------------------------
#define AQ  64
#define AKT 32
#define QPAD 68
#define KPAD 36
#define VPAD 68
#define PPAD 68
#define NEG_BIG (-1e30f)

__global__ __launch_bounds__(128) void attn_kernel(float* __restrict__ hout) {
    __shared__ float Qst[HD][QPAD];    // Q^T, pre-scaled
    __shared__ float Kst[HD][KPAD];    // K^T
    __shared__ float Vs [AKT][VPAD];   // V natural [k][d]
    __shared__ float Pt [AKT][PPAD];   // P^T [k][q]

    const int tid  = threadIdx.x;
    const int qi   = blockIdx.x;   // q tile index, 0..31
    const int hh   = blockIdx.y;   // head
    const int b    = blockIdx.z;   // batch
    const int trow = tid >> 3;     // 0..15  -> 4 query rows
    const int tcol = tid & 7;      // 0..7

    const size_t rowstride = 3 * DMODEL;
    const float* qkv = g_qkv;
    const float* Qg = qkv + ((size_t)b * SEQ + (size_t)qi * AQ) * rowstride + hh * HD;
    const float* Kg = qkv + (size_t)b * SEQ * rowstride + DMODEL     + hh * HD;
    const float* Vg = qkv + (size_t)b * SEQ * rowstride + 2 * DMODEL + hh * HD;

    const float scale = 0.125f;  // 1/sqrt(64)

    // Load Q tile (transposed, pre-scaled): 64 rows x 16 float4
    #pragma unroll
    for (int it = 0; it < 8; ++it) {
        int idx = it * 128 + tid;       // 0..1023
        int q   = idx >> 4;             // 0..63
        int d4  = (idx & 15) << 2;      // 0..60
        float4 v = *(const float4*)(Qg + (size_t)q * rowstride + d4);
        Qst[d4 + 0][q] = v.x * scale;
        Qst[d4 + 1][q] = v.y * scale;
        Qst[d4 + 2][q] = v.z * scale;
        Qst[d4 + 3][q] = v.w * scale;
    }

    float m_i[4], l_i[4], o[4][8];
    #pragma unroll
    for (int i = 0; i < 4; ++i) {
        m_i[i] = NEG_BIG; l_i[i] = 0.f;
        #pragma unroll
        for (int j = 0; j < 8; ++j) o[i][j] = 0.f;
    }

    const int ntiles = 2 * qi + 2;   // causal: keys up to (qi+1)*64-1

    for (int jt = 0; jt < ntiles; ++jt) {
        __syncthreads();  // prev PV-gemm done reading Vs/Pt before overwrite

        // Load K tile (transposed) and V tile: 32 rows x 16 float4 each
        #pragma unroll
        for (int it = 0; it < 4; ++it) {
            int idx = it * 128 + tid;   // 0..511
            int k   = idx >> 4;         // 0..31
            int d4  = (idx & 15) << 2;
            float4 kv = *(const float4*)(Kg + (size_t)(jt * AKT + k) * rowstride + d4);
            Kst[d4 + 0][k] = kv.x;
            Kst[d4 + 1][k] = kv.y;
            Kst[d4 + 2][k] = kv.z;
            Kst[d4 + 3][k] = kv.w;
            float4 vv = *(const float4*)(Vg + (size_t)(jt * AKT + k) * rowstride + d4);
            *(float4*)&Vs[k][d4] = vv;
        }
        __syncthreads();

        // S = (Q*scale) @ K^T : per-thread 4x4
        float s[4][4] = {};
        #pragma unroll
        for (int d = 0; d < HD; ++d) {
            float4 rq = *(const float4*)&Qst[d][trow * 4];
            float4 rk = *(const float4*)&Kst[d][tcol * 4];
            float qa[4] = {rq.x, rq.y, rq.z, rq.w};
            float ka[4] = {rk.x, rk.y, rk.z, rk.w};
            #pragma unroll
            for (int i = 0; i < 4; ++i)
                #pragma unroll
                for (int j = 0; j < 4; ++j)
                    s[i][j] += qa[i] * ka[j];
        }

        // Causal mask: only the (up to two) diagonal tiles need it
        if (jt >= 2 * qi) {
            #pragma unroll
            for (int i = 0; i < 4; ++i) {
                int qg = qi * AQ + trow * 4 + i;
                #pragma unroll
                for (int j = 0; j < 4; ++j) {
                    int kg = jt * AKT + tcol * 4 + j;
                    if (kg > qg) s[i][j] = NEG_BIG;
                }
            }
        }

        // Online softmax, all in registers.
        // The 8 threads with the same trow (consecutive lanes) own one 4-row
        // group; 3-step butterflies reduce across them.
        #pragma unroll
        for (int i = 0; i < 4; ++i) {
            float rm = fmaxf(fmaxf(s[i][0], s[i][1]), fmaxf(s[i][2], s[i][3]));
            rm = fmaxf(rm, __shfl_xor_sync(0xffffffffu, rm, 1));
            rm = fmaxf(rm, __shfl_xor_sync(0xffffffffu, rm, 2));
            rm = fmaxf(rm, __shfl_xor_sync(0xffffffffu, rm, 4));
            float mnew = fmaxf(m_i[i], rm);           // finite always
            float corr = __expf(m_i[i] - mnew);       // 0 on first tile
            float rs = 0.f;
            #pragma unroll
            for (int j = 0; j < 4; ++j) {
                float p = __expf(s[i][j] - mnew);
                s[i][j] = p;
                rs += p;
            }
            rs += __shfl_xor_sync(0xffffffffu, rs, 1);
            rs += __shfl_xor_sync(0xffffffffu, rs, 2);
            rs += __shfl_xor_sync(0xffffffffu, rs, 4);
            l_i[i] = l_i[i] * corr + rs;
            m_i[i] = mnew;
            #pragma unroll
            for (int j = 0; j < 8; ++j) o[i][j] *= corr;
        }

        // Publish P^T for the PV gemm
        #pragma unroll
        for (int i = 0; i < 4; ++i)
            #pragma unroll
            for (int j = 0; j < 4; ++j)
                Pt[tcol * 4 + j][trow * 4 + i] = s[i][j];
        __syncthreads();

        // O[q][d] += sum_k P^T[k][q] * V[k][d] : per-thread 4x8
        #pragma unroll
        for (int kk = 0; kk < AKT; ++kk) {
            float4 rp  = *(const float4*)&Pt[kk][trow * 4];
            float4 rv0 = *(const float4*)&Vs[kk][tcol * 8];
            float4 rv1 = *(const float4*)&Vs[kk][tcol * 8 + 4];
            float pa[4] = {rp.x, rp.y, rp.z, rp.w};
            float va[8] = {rv0.x, rv0.y, rv0.z, rv0.w, rv1.x, rv1.y, rv1.z, rv1.w};
            #pragma unroll
            for (int i = 0; i < 4; ++i)
                #pragma unroll
                for (int j = 0; j < 8; ++j)
                    o[i][j] += pa[i] * va[j];
        }
    }

    // Epilogue: normalize and write h in [B, S, D] layout (head-interleaved)
    #pragma unroll
    for (int i = 0; i < 4; ++i) {
        float inv = 1.f / l_i[i];
        int q = qi * AQ + trow * 4 + i;
        float* op = hout + ((size_t)b * SEQ + q) * DMODEL + hh * HD + tcol * 8;
        float4 v0 = make_float4(o[i][0]*inv, o[i][1]*inv, o[i][2]*inv, o[i][3]*inv);
        float4 v1 = make_float4(o[i][4]*inv, o[i][5]*inv, o[i][6]*inv, o[i][7]*inv);
        *(float4*)(op)     = v0;
        *(float4*)(op + 4) = v1;
    }
}

// ---------------------------------------------------------------------------
// Launch: qkv = x @ Wqkv^T ; flash attention ; out = h @ Wo^T
// Stream-ordered, graph-capturable, allocation-free.
// ---------------------------------------------------------------------------
extern "C" void kernel_launch(void* const* d_in, const int* in_sizes, int n_in,
                              void* d_out, int out_size) {
    const float* x    = (const float*)d_in[0];  // [2,2048,1024]
    const float* Wqkv = (const float*)d_in[1];  // [3072,1024]
    const float* Wo   = (const float*)d_in[2];  // [1024,1024]
    float* out = (float*)d_out;                 // [2,2048,1024]

    float *qkv_ptr = nullptr, *h_ptr = nullptr;
    cudaGetSymbolAddress((void**)&qkv_ptr, g_qkv);
    cudaGetSymbolAddress((void**)&h_ptr,   g_h);

    // 1) QKV projection: [4096,1024] @ [3072,1024]^T -> [4096,3072]
    {
        dim3 grid(3 * DMODEL / GBN, TOKENS / GBM);   // (24, 32)
        sgemm_nt<<<grid, 256>>>(x, Wqkv, qkv_ptr, TOKENS, 3 * DMODEL, DMODEL);
    }
    // 2) Causal flash attention -> g_h [4096,1024]
    {
        dim3 grid(SEQ / AQ, NH, BATCH);              // (32, 16, 2)
        attn_kernel<<<grid, 128>>>(h_ptr);
    }
    // 3) Output projection: [4096,1024] @ [1024,1024]^T -> out
    {
        dim3 grid(DMODEL / GBN, TOKENS / GBM);       // (8, 32)
        sgemm_nt<<<grid, 256>>>(h_ptr, Wo, out, TOKENS, DMODEL, DMODEL);
    }
}

// round 3
// speedup vs baseline: 1.4303x; 1.4303x over previous
#include <cuda_runtime.h>
#include <cuda_bf16.h>
#include <cstdint>
#include <math.h>

// Problem constants (fixed by the reference)
#define BATCH   2
#define SEQ     2048
#define DMODEL  1024
#define NH      16
#define HD      64
#define TOKENS  (BATCH*SEQ)          // 4096

// ---------------------------------------------------------------------------
// Scratch (__device__ globals; allocation in kernel_launch is forbidden)
// ---------------------------------------------------------------------------
__device__ float g_qkv[(size_t)TOKENS * 3 * DMODEL];  // [4096, 3072]
__device__ float g_h  [(size_t)TOKENS * DMODEL];      // [4096, 1024]

__device__ __nv_bfloat16 g_xs_hi[(size_t)TOKENS * DMODEL];
__device__ __nv_bfloat16 g_xs_lo[(size_t)TOKENS * DMODEL];
__device__ __nv_bfloat16 g_wq_hi[(size_t)3 * DMODEL * DMODEL];
__device__ __nv_bfloat16 g_wq_lo[(size_t)3 * DMODEL * DMODEL];
__device__ __nv_bfloat16 g_wo_hi[(size_t)DMODEL * DMODEL];
__device__ __nv_bfloat16 g_wo_lo[(size_t)DMODEL * DMODEL];
__device__ __nv_bfloat16 g_hs_hi[(size_t)TOKENS * DMODEL];
__device__ __nv_bfloat16 g_hs_lo[(size_t)TOKENS * DMODEL];

// ---------------------------------------------------------------------------
// PTX helpers (sm_80-era instructions only — compute_100-safe)
// ---------------------------------------------------------------------------
__device__ __forceinline__ uint32_t smem_u32(const void* p) {
    uint32_t a;
    asm("{ .reg .u64 t; cvta.to.shared.u64 t, %1; cvt.u32.u64 %0, t; }"
        : "=r"(a) : "l"(p));
    return a;
}

#define CP_ASYNC16(dst, src) \
    asm volatile("cp.async.cg.shared.global [%0], [%1], 16;" \
                 :: "r"(dst), "l"(src) : "memory")
#define CP_COMMIT() asm volatile("cp.async.commit_group;" ::: "memory")
#define CP_WAIT(N)  asm volatile("cp.async.wait_group %0;" :: "n"(N) : "memory")

__device__ __forceinline__ void ldsm_x4(uint32_t& r0, uint32_t& r1,
                                        uint32_t& r2, uint32_t& r3, uint32_t addr) {
    asm volatile("ldmatrix.sync.aligned.m8n8.x4.shared.b16 {%0,%1,%2,%3}, [%4];"
                 : "=r"(r0), "=r"(r1), "=r"(r2), "=r"(r3) : "r"(addr));
}

__device__ __forceinline__ void mma16816(float* c, uint32_t a0, uint32_t a1,
                                         uint32_t a2, uint32_t a3,
                                         uint32_t b0, uint32_t b1) {
    asm volatile(
        "mma.sync.aligned.m16n8k16.row.col.f32.bf16.bf16.f32 "
        "{%0,%1,%2,%3}, {%4,%5,%6,%7}, {%8,%9}, {%0,%1,%2,%3};"
        : "+f"(c[0]), "+f"(c[1]), "+f"(c[2]), "+f"(c[3])
        : "r"(a0), "r"(a1), "r"(a2), "r"(a3), "r"(b0), "r"(b1));
}

// ---------------------------------------------------------------------------
// Split: fp32 -> bf16 hi + bf16 lo (residual). n multiple of 2048.
// ---------------------------------------------------------------------------
__global__ __launch_bounds__(256) void split_bf16(const float* __restrict__ in,
                                                  __nv_bfloat16* __restrict__ hi,
                                                  __nv_bfloat16* __restrict__ lo,
                                                  int n) {
    int base = (blockIdx.x * 256 + threadIdx.x) * 8;
    if (base >= n) return;
    float4 f0 = *(const float4*)(in + base);
    float4 f1 = *(const float4*)(in + base + 4);
    float f[8] = {f0.x, f0.y, f0.z, f0.w, f1.x, f1.y, f1.z, f1.w};
    uint32_t h[4], l[4];
    #pragma unroll
    for (int j = 0; j < 4; ++j) {
        __nv_bfloat162 h2 = __float22bfloat162_rn(make_float2(f[2*j], f[2*j+1]));
        float2 hf = __bfloat1622float2(h2);
        __nv_bfloat162 l2 = __float22bfloat162_rn(
            make_float2(f[2*j] - hf.x, f[2*j+1] - hf.y));
        h[j] = *(uint32_t*)&h2;
        l[j] = *(uint32_t*)&l2;
    }
    *(uint4*)(hi + base) = make_uint4(h[0], h[1], h[2], h[3]);
    *(uint4*)(lo + base) = make_uint4(l[0], l[1], l[2], l[3]);
}

// ---------------------------------------------------------------------------
// bf16x3 warp-MMA GEMM: C[M,N] = A[M,K] @ B[N,K]^T (pre-split bf16 operands,
// fp32 out). CTA tile 128x128, BK=32, 256 threads = 8 warps of 64x32.
// Double-buffered smem via cp.async. hh+hl+lh accumulation (~1e-5 err).
// ---------------------------------------------------------------------------
#define ROWB 80                      // smem row stride bytes (32 bf16 + pad)
#define TILEB (128 * ROWB)           // 10240 per tile
#define STAGEB (4 * TILEB)           // Ahi,Alo,Bhi,Blo = 40960
#define GEMM_SMEM (2 * STAGEB)       // 81920

__device__ __forceinline__ void issue_chunk(
    uint32_t stage, const __nv_bfloat16* __restrict__ Ahi,
    const __nv_bfloat16* __restrict__ Alo,
    const __nv_bfloat16* __restrict__ Bhi,
    const __nv_bfloat16* __restrict__ Blo,
    int kc, int K, int tid) {
    const __nv_bfloat16* srcs[4] = {Ahi, Alo, Bhi, Blo};
    #pragma unroll
    for (int t = 0; t < 4; ++t) {
        const __nv_bfloat16* p = srcs[t] + kc * 32;
        uint32_t tbase = stage + t * TILEB;
        #pragma unroll
        for (int j = 0; j < 2; ++j) {
            int gid = tid * 2 + j;          // 0..511
            int row = gid >> 2;
            int gc  = gid & 3;
            const __nv_bfloat16* src = p + (size_t)row * K + gc * 8;
            uint32_t dst = tbase + row * ROWB + gc * 16;
            CP_ASYNC16(dst, src);
        }
    }
}

__global__ __launch_bounds__(256, 2) void gemm_bf16x3(
    const __nv_bfloat16* __restrict__ Ahi, const __nv_bfloat16* __restrict__ Alo,
    const __nv_bfloat16* __restrict__ Bhi, const __nv_bfloat16* __restrict__ Blo,
    float* __restrict__ C, int M, int N, int K) {
    extern __shared__ char smem[];
    const uint32_t sb = smem_u32(smem);

    const int tid = threadIdx.x;
    const int wid = tid >> 5;
    const int lid = tid & 31;
    const int wm  = wid & 1;       // 0..1  -> 64 rows
    const int wn  = wid >> 1;      // 0..3  -> 32 cols

    const int brow = blockIdx.y;
    const int bcol = blockIdx.x;

    const __nv_bfloat16* Ah = Ahi + (size_t)brow * 128 * K;
    const __nv_bfloat16* Al = Alo + (size_t)brow * 128 * K;
    const __nv_bfloat16* Bh = Bhi + (size_t)bcol * 128 * K;
    const __nv_bfloat16* Bl = Blo + (size_t)bcol * 128 * K;

    // Per-lane ldmatrix offsets (row stride ROWB):
    // A x4 at (M0,k16): row = M0 + ((l>>3)&1)*8 + (l&7), kcol = k16 + (l>>4)*8
    const uint32_t offA = (((lid >> 3) & 1) * 8 + (lid & 7)) * ROWB + (lid >> 4) * 16;
    // B x4 at (N0,k16): n = N0 + (l>>4)*8 + (l&7), kcol = k16 + ((l>>3)&1)*8
    const uint32_t offB = ((lid >> 4) * 8 + (lid & 7)) * ROWB + ((lid >> 3) & 1) * 16;

    float acc[4][4][4];
    #pragma unroll
    for (int i = 0; i < 4; ++i)
        #pragma unroll
        for (int j = 0; j < 4; ++j)
            #pragma unroll
            for (int e = 0; e < 4; ++e) acc[i][j][e] = 0.f;

    const int nch = K / 32;
    issue_chunk(sb, Ah, Al, Bh, Bl, 0, K, tid);
    CP_COMMIT();

    for (int kc = 0; kc < nch; ++kc) {
        uint32_t cur = sb + (kc & 1) * STAGEB;
        if (kc + 1 < nch) {
            issue_chunk(sb + ((kc + 1) & 1) * STAGEB, Ah, Al, Bh, Bl, kc + 1, K, tid);
            CP_COMMIT();
            CP_WAIT(1);
        } else {
            CP_WAIT(0);
        }
        __syncthreads();

        const uint32_t aHiB = cur + 0 * TILEB + wm * 64 * ROWB + offA;
        const uint32_t aLoB = cur + 1 * TILEB + wm * 64 * ROWB + offA;
        const uint32_t bHiB = cur + 2 * TILEB + wn * 32 * ROWB + offB;
        const uint32_t bLoB = cur + 3 * TILEB + wn * 32 * ROWB + offB;

        #pragma unroll
        for (int k16 = 0; k16 < 2; ++k16) {
            const uint32_t ko = k16 * 32;  // 16 bf16 = 32 bytes

            uint32_t bh[8], bl[8];
            ldsm_x4(bh[0], bh[1], bh[2], bh[3], bHiB + ko);
            ldsm_x4(bh[4], bh[5], bh[6], bh[7], bHiB + 16 * ROWB + ko);
            ldsm_x4(bl[0], bl[1], bl[2], bl[3], bLoB + ko);
            ldsm_x4(bl[4], bl[5], bl[6], bl[7], bLoB + 16 * ROWB + ko);

            #pragma unroll
            for (int mt = 0; mt < 4; ++mt) {
                uint32_t ah[4], al[4];
                ldsm_x4(ah[0], ah[1], ah[2], ah[3], aHiB + mt * 16 * ROWB + ko);
                ldsm_x4(al[0], al[1], al[2], al[3], aLoB + mt * 16 * ROWB + ko);
                #pragma unroll
                for (int nt = 0; nt < 4; ++nt) {
                    // hi*hi
                    mma16816(acc[mt][nt], ah[0], ah[1], ah[2], ah[3],
                             bh[nt * 2], bh[nt * 2 + 1]);
                    // hi*lo
                    mma16816(acc[mt][nt], ah[0], ah[1], ah[2], ah[3],
                             bl[nt * 2], bl[nt * 2 + 1]);
                    // lo*hi
                    mma16816(acc[mt][nt], al[0], al[1], al[2], al[3],
                             bh[nt * 2], bh[nt * 2 + 1]);
                }
            }
        }
        __syncthreads();
    }

    // Epilogue
    const int r0 = brow * 128 + wm * 64 + (lid >> 2);
    const int c0 = bcol * 128 + wn * 32 + (lid & 3) * 2;
    #pragma unroll
    for (int mt = 0; mt < 4; ++mt) {
        #pragma unroll
        for (int nt = 0; nt < 4; ++nt) {
            float* p = C + (size_t)(r0 + mt * 16) * N + c0 + nt * 8;
            *(float2*)p                      = make_float2(acc[mt][nt][0], acc[mt][nt][1]);
            *(float2*)(p + (size_t)8 * N)    = make_float2(acc[mt][nt][2], acc[mt][nt][3]);
        }
    }
}

// ---------------------------------------------------------------------------
// Flash attention, fp32, causal (unchanged from R1).
// ---------------------------------------------------------------------------
#define AQ  64
#define AKT 32
#define QPAD 68
#define KPAD 36
#define VPAD 68
#define PPAD 68
#define NEG_BIG (-1e30f)

__global__ __launch_bounds__(128) void attn_kernel(float* __restrict__ hout) {
    __shared__ float Qst[HD][QPAD];
    __shared__ float Kst[HD][KPAD];
    __shared__ float Vs [AKT][VPAD];
    __shared__ float Pt [AKT][PPAD];

    const int tid  = threadIdx.x;
    const int qi   = blockIdx.x;
    const int hh   = blockIdx.y;
    const int b    = blockIdx.z;
    const int trow = tid >> 3;
    const int tcol = tid & 7;

    const size_t rowstride = 3 * DMODEL;
    const float* qkv = g_qkv;
    const float* Qg = qkv + ((size_t)b * SEQ + (size_t)qi * AQ) * rowstride + hh * HD;
    const float* Kg = qkv + (size_t)b * SEQ * rowstride + DMODEL     + hh * HD;
    const float* Vg = qkv + (size_t)b * SEQ * rowstride + 2 * DMODEL + hh * HD;

    const float scale = 0.125f;

    #pragma unroll
    for (int it = 0; it < 8; ++it) {
        int idx = it * 128 + tid;
        int q   = idx >> 4;
        int d4  = (idx & 15) << 2;
        float4 v = *(const float4*)(Qg + (size_t)q * rowstride + d4);
        Qst[d4 + 0][q] = v.x * scale;
        Qst[d4 + 1][q] = v.y * scale;
        Qst[d4 + 2][q] = v.z * scale;
        Qst[d4 + 3][q] = v.w * scale;
    }

    float m_i[4], l_i[4], o[4][8];
    #pragma unroll
    for (int i = 0; i < 4; ++i) {
        m_i[i] = NEG_BIG; l_i[i] = 0.f;
        #pragma unroll
        for (int j = 0; j < 8; ++j) o[i][j] = 0.f;
    }

    const int ntiles = 2 * qi + 2;

    for (int jt = 0; jt < ntiles; ++jt) {
        __syncthreads();

        #pragma unroll
        for (int it = 0; it < 4; ++it) {
            int idx = it * 128 + tid;
            int k   = idx >> 4;
            int d4  = (idx & 15) << 2;
            float4 kv = *(const float4*)(Kg + (size_t)(jt * AKT + k) * rowstride + d4);
            Kst[d4 + 0][k] = kv.x;
            Kst[d4 + 1][k] = kv.y;
            Kst[d4 + 2][k] = kv.z;
            Kst[d4 + 3][k] = kv.w;
            float4 vv = *(const float4*)(Vg + (size_t)(jt * AKT + k) * rowstride + d4);
            *(float4*)&Vs[k][d4] = vv;
        }
        __syncthreads();

        float s[4][4] = {};
        #pragma unroll
        for (int d = 0; d < HD; ++d) {
            float4 rq = *(const float4*)&Qst[d][trow * 4];
            float4 rk = *(const float4*)&Kst[d][tcol * 4];
            float qa[4] = {rq.x, rq.y, rq.z, rq.w};
            float ka[4] = {rk.x, rk.y, rk.z, rk.w};
            #pragma unroll
            for (int i = 0; i < 4; ++i)
                #pragma unroll
                for (int j = 0; j < 4; ++j)
                    s[i][j] += qa[i] * ka[j];
        }

        if (jt >= 2 * qi) {
            #pragma unroll
            for (int i = 0; i < 4; ++i) {
                int qg = qi * AQ + trow * 4 + i;
                #pragma unroll
                for (int j = 0; j < 4; ++j) {
                    int kg = jt * AKT + tcol * 4 + j;
                    if (kg > qg) s[i][j] = NEG_BIG;
                }
            }
        }

        #pragma unroll
        for (int i = 0; i < 4; ++i) {
            float rm = fmaxf(fmaxf(s[i][0], s[i][1]), fmaxf(s[i][2], s[i][3]));
            rm = fmaxf(rm, __shfl_xor_sync(0xffffffffu, rm, 1));
            rm = fmaxf(rm, __shfl_xor_sync(0xffffffffu, rm, 2));
            rm = fmaxf(rm, __shfl_xor_sync(0xffffffffu, rm, 4));
            float mnew = fmaxf(m_i[i], rm);
            float corr = __expf(m_i[i] - mnew);
            float rs = 0.f;
            #pragma unroll
            for (int j = 0; j < 4; ++j) {
                float p = __expf(s[i][j] - mnew);
                s[i][j] = p;
                rs += p;
            }
            rs += __shfl_xor_sync(0xffffffffu, rs, 1);
            rs += __shfl_xor_sync(0xffffffffu, rs, 2);
            rs += __shfl_xor_sync(0xffffffffu, rs, 4);
            l_i[i] = l_i[i] * corr + rs;
            m_i[i] = mnew;
            #pragma unroll
            for (int j = 0; j < 8; ++j) o[i][j] *= corr;
        }

        #pragma unroll
        for (int i = 0; i < 4; ++i)
            #pragma unroll
            for (int j = 0; j < 4; ++j)
                Pt[tcol * 4 + j][trow * 4 + i] = s[i][j];
        __syncthreads();

        #pragma unroll
        for (int kk = 0; kk < AKT; ++kk) {
            float4 rp  = *(const float4*)&Pt[kk][trow * 4];
            float4 rv0 = *(const float4*)&Vs[kk][tcol * 8];
            float4 rv1 = *(const float4*)&Vs[kk][tcol * 8 + 4];
            float pa[4] = {rp.x, rp.y, rp.z, rp.w};
            float va[8] = {rv0.x, rv0.y, rv0.z, rv0.w, rv1.x, rv1.y, rv1.z, rv1.w};
            #pragma unroll
            for (int i = 0; i < 4; ++i)
                #pragma unroll
                for (int j = 0; j < 8; ++j)
                    o[i][j] += pa[i] * va[j];
        }
    }

    #pragma unroll
    for (int i = 0; i < 4; ++i) {
        float inv = 1.f / l_i[i];
        int q = qi * AQ + trow * 4 + i;
        float* op = hout + ((size_t)b * SEQ + q) * DMODEL + hh * HD + tcol * 8;
        float4 v0 = make_float4(o[i][0]*inv, o[i][1]*inv, o[i][2]*inv, o[i][3]*inv);
        float4 v1 = make_float4(o[i][4]*inv, o[i][5]*inv, o[i][6]*inv, o[i][7]*inv);
        *(float4*)(op)     = v0;
        *(float4*)(op + 4) = v1;
    }
}

// ---------------------------------------------------------------------------
// Launch
// ---------------------------------------------------------------------------
extern "C" void kernel_launch(void* const* d_in, const int* in_sizes, int n_in,
                              void* d_out, int out_size) {
    const float* x    = (const float*)d_in[0];  // [2,2048,1024]
    const float* Wqkv = (const float*)d_in[1];  // [3072,1024]
    const float* Wo   = (const float*)d_in[2];  // [1024,1024]
    float* out = (float*)d_out;                 // [2,2048,1024]

    float *qkv_ptr = nullptr, *h_ptr = nullptr;
    cudaGetSymbolAddress((void**)&qkv_ptr, g_qkv);
    cudaGetSymbolAddress((void**)&h_ptr,   g_h);
    __nv_bfloat16 *xs_hi, *xs_lo, *wq_hi, *wq_lo, *wo_hi, *wo_lo, *hs_hi, *hs_lo;
    cudaGetSymbolAddress((void**)&xs_hi, g_xs_hi);
    cudaGetSymbolAddress((void**)&xs_lo, g_xs_lo);
    cudaGetSymbolAddress((void**)&wq_hi, g_wq_hi);
    cudaGetSymbolAddress((void**)&wq_lo, g_wq_lo);
    cudaGetSymbolAddress((void**)&wo_hi, g_wo_hi);
    cudaGetSymbolAddress((void**)&wo_lo, g_wo_lo);
    cudaGetSymbolAddress((void**)&hs_hi, g_hs_hi);
    cudaGetSymbolAddress((void**)&hs_lo, g_hs_lo);

    cudaFuncSetAttribute(gemm_bf16x3, cudaFuncAttributeMaxDynamicSharedMemorySize,
                         GEMM_SMEM);

    const int n_x  = TOKENS * DMODEL;       // 4194304
    const int n_wq = 3 * DMODEL * DMODEL;   // 3145728
    const int n_wo = DMODEL * DMODEL;       // 1048576

    // Pre-split operands to bf16 hi/lo
    split_bf16<<<n_x  / 2048, 256>>>(x,    xs_hi, xs_lo, n_x);
    split_bf16<<<n_wq / 2048, 256>>>(Wqkv, wq_hi, wq_lo, n_wq);
    split_bf16<<<n_wo / 2048, 256>>>(Wo,   wo_hi, wo_lo, n_wo);

    // 1) QKV projection: [4096,1024] @ [3072,1024]^T -> [4096,3072]
    {
        dim3 grid(3 * DMODEL / 128, TOKENS / 128);   // (24, 32)
        gemm_bf16x3<<<grid, 256, GEMM_SMEM>>>(xs_hi, xs_lo, wq_hi, wq_lo,
                                              qkv_ptr, TOKENS, 3 * DMODEL, DMODEL);
    }
    // 2) Causal flash attention -> g_h [4096,1024]
    {
        dim3 grid(SEQ / AQ, NH, BATCH);              // (32, 16, 2)
        attn_kernel<<<grid, 128>>>(h_ptr);
    }
    // 3) Output projection: split h, then [4096,1024] @ [1024,1024]^T -> out
    split_bf16<<<n_x / 2048, 256>>>(h_ptr, hs_hi, hs_lo, n_x);
    {
        dim3 grid(DMODEL / 128, TOKENS / 128);       // (8, 32)
        gemm_bf16x3<<<grid, 256, GEMM_SMEM>>>(hs_hi, hs_lo, wo_hi, wo_lo,
                                              out, TOKENS, DMODEL, DMODEL);
    }
}

// round 5
// speedup vs baseline: 2.6506x; 1.8531x over previous
#include <cuda_runtime.h>
#include <cuda_bf16.h>
#include <cstdint>
#include <math.h>

// Problem constants (fixed by the reference)
#define BATCH   2
#define SEQ     2048
#define DMODEL  1024
#define NH      16
#define HD      64
#define TOKENS  (BATCH*SEQ)          // 4096
#define NHEADS_TOTAL (BATCH*NH)      // 32

// ---------------------------------------------------------------------------
// Scratch (__device__ globals; allocation in kernel_launch is forbidden)
// ---------------------------------------------------------------------------
__device__ float g_qkv[(size_t)TOKENS * 3 * DMODEL];  // [4096, 3072]
__device__ float g_h  [(size_t)TOKENS * DMODEL];      // [4096, 1024]

__device__ __nv_bfloat16 g_xs_hi[(size_t)TOKENS * DMODEL];
__device__ __nv_bfloat16 g_xs_lo[(size_t)TOKENS * DMODEL];
__device__ __nv_bfloat16 g_wq_hi[(size_t)3 * DMODEL * DMODEL];
__device__ __nv_bfloat16 g_wq_lo[(size_t)3 * DMODEL * DMODEL];
__device__ __nv_bfloat16 g_wo_hi[(size_t)DMODEL * DMODEL];
__device__ __nv_bfloat16 g_wo_lo[(size_t)DMODEL * DMODEL];
__device__ __nv_bfloat16 g_hs_hi[(size_t)TOKENS * DMODEL];
__device__ __nv_bfloat16 g_hs_lo[(size_t)TOKENS * DMODEL];

// Per-head attention operands (bf16 hi/lo)
// Q,K: [head][s][64]; VT: [head][64][s] (transposed)
#define HEADELEMS ((size_t)NHEADS_TOTAL * SEQ * HD)
__device__ __nv_bfloat16 g_q_hi[HEADELEMS];
__device__ __nv_bfloat16 g_q_lo[HEADELEMS];
__device__ __nv_bfloat16 g_k_hi[HEADELEMS];
__device__ __nv_bfloat16 g_k_lo[HEADELEMS];
__device__ __nv_bfloat16 g_vt_hi[HEADELEMS];
__device__ __nv_bfloat16 g_vt_lo[HEADELEMS];

// ---------------------------------------------------------------------------
// PTX helpers (sm_80-era instructions only — compute_100-safe)
// ---------------------------------------------------------------------------
__device__ __forceinline__ uint32_t smem_u32(const void* p) {
    uint32_t a;
    asm("{ .reg .u64 t; cvta.to.shared.u64 t, %1; cvt.u32.u64 %0, t; }"
        : "=r"(a) : "l"(p));
    return a;
}

#define CP_ASYNC16(dst, src) \
    asm volatile("cp.async.cg.shared.global [%0], [%1], 16;" \
                 :: "r"(dst), "l"(src) : "memory")
#define CP_COMMIT() asm volatile("cp.async.commit_group;" ::: "memory")
#define CP_WAIT(N)  asm volatile("cp.async.wait_group %0;" :: "n"(N) : "memory")

__device__ __forceinline__ void ldsm_x4(uint32_t& r0, uint32_t& r1,
                                        uint32_t& r2, uint32_t& r3, uint32_t addr) {
    asm volatile("ldmatrix.sync.aligned.m8n8.x4.shared.b16 {%0,%1,%2,%3}, [%4];"
                 : "=r"(r0), "=r"(r1), "=r"(r2), "=r"(r3) : "r"(addr));
}

__device__ __forceinline__ void mma16816(float* c, uint32_t a0, uint32_t a1,
                                         uint32_t a2, uint32_t a3,
                                         uint32_t b0, uint32_t b1) {
    asm volatile(
        "mma.sync.aligned.m16n8k16.row.col.f32.bf16.bf16.f32 "
        "{%0,%1,%2,%3}, {%4,%5,%6,%7}, {%8,%9}, {%0,%1,%2,%3};"
        : "+f"(c[0]), "+f"(c[1]), "+f"(c[2]), "+f"(c[3])
        : "r"(a0), "r"(a1), "r"(a2), "r"(a3), "r"(b0), "r"(b1));
}

__device__ __forceinline__ uint32_t pack_bf16x2(float a, float b) {
    __nv_bfloat162 h2 = __float22bfloat162_rn(make_float2(a, b));
    return *(uint32_t*)&h2;
}

// ---------------------------------------------------------------------------
// Split: fp32 -> bf16 hi + bf16 lo (residual). n multiple of 2048.
// ---------------------------------------------------------------------------
__global__ __launch_bounds__(256) void split_bf16(const float* __restrict__ in,
                                                  __nv_bfloat16* __restrict__ hi,
                                                  __nv_bfloat16* __restrict__ lo,
                                                  int n) {
    int base = (blockIdx.x * 256 + threadIdx.x) * 8;
    if (base >= n) return;
    float4 f0 = *(const float4*)(in + base);
    float4 f1 = *(const float4*)(in + base + 4);
    float f[8] = {f0.x, f0.y, f0.z, f0.w, f1.x, f1.y, f1.z, f1.w};
    uint32_t h[4], l[4];
    #pragma unroll
    for (int j = 0; j < 4; ++j) {
        __nv_bfloat162 h2 = __float22bfloat162_rn(make_float2(f[2*j], f[2*j+1]));
        float2 hf = __bfloat1622float2(h2);
        __nv_bfloat162 l2 = __float22bfloat162_rn(
            make_float2(f[2*j] - hf.x, f[2*j+1] - hf.y));
        h[j] = *(uint32_t*)&h2;
        l[j] = *(uint32_t*)&l2;
    }
    *(uint4*)(hi + base) = make_uint4(h[0], h[1], h[2], h[3]);
    *(uint4*)(lo + base) = make_uint4(l[0], l[1], l[2], l[3]);
}

// ---------------------------------------------------------------------------
// split_qkv: g_qkv [4096,3072] fp32 -> per-head bf16 hi/lo tensors.
// Q scaled by 1/8 before splitting. V transposed per head via smem.
// Grid (SEQ/64, NH, BATCH), 256 threads.
// ---------------------------------------------------------------------------
__global__ __launch_bounds__(256, 4) void split_qkv(
    __nv_bfloat16* __restrict__ qhi, __nv_bfloat16* __restrict__ qlo,
    __nv_bfloat16* __restrict__ khi, __nv_bfloat16* __restrict__ klo,
    __nv_bfloat16* __restrict__ vthi, __nv_bfloat16* __restrict__ vtlo) {
    __shared__ __nv_bfloat16 vt_h[64][72];
    __shared__ __nv_bfloat16 vt_l[64][72];

    const int tid = threadIdx.x;
    const int s0  = blockIdx.x * 64;
    const int h   = blockIdx.y;
    const int b   = blockIdx.z;
    const int head = b * NH + h;

    #pragma unroll
    for (int it = 0; it < 2; ++it) {
        int unit = it * 256 + tid;       // 0..511
        int sl   = unit >> 3;            // 0..63
        int d0   = (unit & 7) * 8;
        int s    = s0 + sl;
        const float* base = g_qkv + ((size_t)(b * SEQ + s)) * (3 * DMODEL) + h * HD + d0;
        size_t qkidx = ((size_t)head * SEQ + s) * HD + d0;

        // ---- Q (scaled) ----
        {
            float4 f0 = *(const float4*)(base);
            float4 f1 = *(const float4*)(base + 4);
            float f[8] = {f0.x, f0.y, f0.z, f0.w, f1.x, f1.y, f1.z, f1.w};
            uint32_t hh[4], ll[4];
            #pragma unroll
            for (int j = 0; j < 4; ++j) {
                float a = f[2*j] * 0.125f, c = f[2*j+1] * 0.125f;
                __nv_bfloat162 h2 = __float22bfloat162_rn(make_float2(a, c));
                float2 hf = __bfloat1622float2(h2);
                __nv_bfloat162 l2 = __float22bfloat162_rn(make_float2(a - hf.x, c - hf.y));
                hh[j] = *(uint32_t*)&h2;
                ll[j] = *(uint32_t*)&l2;
            }
            *(uint4*)(qhi + qkidx) = make_uint4(hh[0], hh[1], hh[2], hh[3]);
            *(uint4*)(qlo + qkidx) = make_uint4(ll[0], ll[1], ll[2], ll[3]);
        }
        // ---- K ----
        {
            float4 f0 = *(const float4*)(base + DMODEL);
            float4 f1 = *(const float4*)(base + DMODEL + 4);
            float f[8] = {f0.x, f0.y, f0.z, f0.w, f1.x, f1.y, f1.z, f1.w};
            uint32_t hh[4], ll[4];
            #pragma unroll
            for (int j = 0; j < 4; ++j) {
                __nv_bfloat162 h2 = __float22bfloat162_rn(make_float2(f[2*j], f[2*j+1]));
                float2 hf = __bfloat1622float2(h2);
                __nv_bfloat162 l2 = __float22bfloat162_rn(
                    make_float2(f[2*j] - hf.x, f[2*j+1] - hf.y));
                hh[j] = *(uint32_t*)&h2;
                ll[j] = *(uint32_t*)&l2;
            }
            *(uint4*)(khi + qkidx) = make_uint4(hh[0], hh[1], hh[2], hh[3]);
            *(uint4*)(klo + qkidx) = make_uint4(ll[0], ll[1], ll[2], ll[3]);
        }
        // ---- V -> smem transpose ----
        {
            float4 f0 = *(const float4*)(base + 2 * DMODEL);
            float4 f1 = *(const float4*)(base + 2 * DMODEL + 4);
            float f[8] = {f0.x, f0.y, f0.z, f0.w, f1.x, f1.y, f1.z, f1.w};
            #pragma unroll
            for (int j = 0; j < 8; ++j) {
                __nv_bfloat16 hv = __float2bfloat16(f[j]);
                __nv_bfloat16 lv = __float2bfloat16(f[j] - __bfloat162float(hv));
                vt_h[d0 + j][sl] = hv;
                vt_l[d0 + j][sl] = lv;
            }
        }
    }
    __syncthreads();

    // Write out VT rows: 2 prec x 64 rows x 8 uint4 = 1024 writes
    #pragma unroll
    for (int it = 0; it < 4; ++it) {
        int idx  = it * 256 + tid;       // 0..1023
        int prec = idx >> 9;
        int rem  = idx & 511;
        int r    = rem >> 3;
        int c    = (rem & 7) * 8;
        uint4 v = prec ? *(uint4*)&vt_l[r][c] : *(uint4*)&vt_h[r][c];
        __nv_bfloat16* dst = (prec ? vtlo : vthi) +
                             ((size_t)head * HD + r) * SEQ + s0 + c;
        *(uint4*)dst = v;
    }
}

// ---------------------------------------------------------------------------
// bf16x3 warp-MMA GEMM (unchanged from R3): C[M,N] = A[M,K] @ B[N,K]^T
// ---------------------------------------------------------------------------
#define ROWB 80
#define TILEB (128 * ROWB)
#define STAGEB (4 * TILEB)
#define GEMM_SMEM (2 * STAGEB)

__device__ __forceinline__ void issue_chunk(
    uint32_t stage, const __nv_bfloat16* __restrict__ Ahi,
    const __nv_bfloat16* __restrict__ Alo,
    const __nv_bfloat16* __restrict__ Bhi,
    const __nv_bfloat16* __restrict__ Blo,
    int kc, int K, int tid) {
    const __nv_bfloat16* srcs[4] = {Ahi, Alo, Bhi, Blo};
    #pragma unroll
    for (int t = 0; t < 4; ++t) {
        const __nv_bfloat16* p = srcs[t] + kc * 32;
        uint32_t tbase = stage + t * TILEB;
        #pragma unroll
        for (int j = 0; j < 2; ++j) {
            int gid = tid * 2 + j;
            int row = gid >> 2;
            int gc  = gid & 3;
            const __nv_bfloat16* src = p + (size_t)row * K + gc * 8;
            uint32_t dst = tbase + row * ROWB + gc * 16;
            CP_ASYNC16(dst, src);
        }
    }
}

__global__ __launch_bounds__(256, 2) void gemm_bf16x3(
    const __nv_bfloat16* __restrict__ Ahi, const __nv_bfloat16* __restrict__ Alo,
    const __nv_bfloat16* __restrict__ Bhi, const __nv_bfloat16* __restrict__ Blo,
    float* __restrict__ C, int M, int N, int K) {
    extern __shared__ char smem[];
    const uint32_t sb = smem_u32(smem);

    const int tid = threadIdx.x;
    const int wid = tid >> 5;
    const int lid = tid & 31;
    const int wm  = wid & 1;
    const int wn  = wid >> 1;

    const int brow = blockIdx.y;
    const int bcol = blockIdx.x;

    const __nv_bfloat16* Ah = Ahi + (size_t)brow * 128 * K;
    const __nv_bfloat16* Al = Alo + (size_t)brow * 128 * K;
    const __nv_bfloat16* Bh = Bhi + (size_t)bcol * 128 * K;
    const __nv_bfloat16* Bl = Blo + (size_t)bcol * 128 * K;

    const uint32_t offA = (((lid >> 3) & 1) * 8 + (lid & 7)) * ROWB + (lid >> 4) * 16;
    const uint32_t offB = ((lid >> 4) * 8 + (lid & 7)) * ROWB + ((lid >> 3) & 1) * 16;

    float acc[4][4][4];
    #pragma unroll
    for (int i = 0; i < 4; ++i)
        #pragma unroll
        for (int j = 0; j < 4; ++j)
            #pragma unroll
            for (int e = 0; e < 4; ++e) acc[i][j][e] = 0.f;

    const int nch = K / 32;
    issue_chunk(sb, Ah, Al, Bh, Bl, 0, K, tid);
    CP_COMMIT();

    for (int kc = 0; kc < nch; ++kc) {
        uint32_t cur = sb + (kc & 1) * STAGEB;
        if (kc + 1 < nch) {
            issue_chunk(sb + ((kc + 1) & 1) * STAGEB, Ah, Al, Bh, Bl, kc + 1, K, tid);
            CP_COMMIT();
            CP_WAIT(1);
        } else {
            CP_WAIT(0);
        }
        __syncthreads();

        const uint32_t aHiB = cur + 0 * TILEB + wm * 64 * ROWB + offA;
        const uint32_t aLoB = cur + 1 * TILEB + wm * 64 * ROWB + offA;
        const uint32_t bHiB = cur + 2 * TILEB + wn * 32 * ROWB + offB;
        const uint32_t bLoB = cur + 3 * TILEB + wn * 32 * ROWB + offB;

        #pragma unroll
        for (int k16 = 0; k16 < 2; ++k16) {
            const uint32_t ko = k16 * 32;

            uint32_t bh[8], bl[8];
            ldsm_x4(bh[0], bh[1], bh[2], bh[3], bHiB + ko);
            ldsm_x4(bh[4], bh[5], bh[6], bh[7], bHiB + 16 * ROWB + ko);
            ldsm_x4(bl[0], bl[1], bl[2], bl[3], bLoB + ko);
            ldsm_x4(bl[4], bl[5], bl[6], bl[7], bLoB + 16 * ROWB + ko);

            #pragma unroll
            for (int mt = 0; mt < 4; ++mt) {
                uint32_t ah[4], al[4];
                ldsm_x4(ah[0], ah[1], ah[2], ah[3], aHiB + mt * 16 * ROWB + ko);
                ldsm_x4(al[0], al[1], al[2], al[3], aLoB + mt * 16 * ROWB + ko);
                #pragma unroll
                for (int nt = 0; nt < 4; ++nt) {
                    mma16816(acc[mt][nt], ah[0], ah[1], ah[2], ah[3],
                             bh[nt * 2], bh[nt * 2 + 1]);
                    mma16816(acc[mt][nt], ah[0], ah[1], ah[2], ah[3],
                             bl[nt * 2], bl[nt * 2 + 1]);
                    mma16816(acc[mt][nt], al[0], al[1], al[2], al[3],
                             bh[nt * 2], bh[nt * 2 + 1]);
                }
            }
        }
        __syncthreads();
    }

    const int r0 = brow * 128 + wm * 64 + (lid >> 2);
    const int c0 = bcol * 128 + wn * 32 + (lid & 3) * 2;
    #pragma unroll
    for (int mt = 0; mt < 4; ++mt) {
        #pragma unroll
        for (int nt = 0; nt < 4; ++nt) {
            float* p = C + (size_t)(r0 + mt * 16) * N + c0 + nt * 8;
            *(float2*)p                   = make_float2(acc[mt][nt][0], acc[mt][nt][1]);
            *(float2*)(p + (size_t)8 * N) = make_float2(acc[mt][nt][2], acc[mt][nt][3]);
        }
    }
}

// ---------------------------------------------------------------------------
// HMMA flash attention (bf16x3), causal.
// CTA = 128 queries of one head. 8 warps x 16 q-rows (full key width per warp
// -> softmax reductions stay inside quads). K-tiles of 64 keys.
// Smem: Q hi/lo (128x64), K hi/lo (64x64), VT hi/lo (64x64), rows padded to
// 144B. P fragments come straight from S accumulators (no smem round trip).
// ---------------------------------------------------------------------------
#define AROWB 144
#define SQ_HI   0
#define SQ_LO   18432
#define SK_HI   36864
#define ATT_SMEM 73728     // SK_HI + 4*9216
#define NEG_BIG (-1e30f)

__global__ __launch_bounds__(256, 2) void attn_mma(float* __restrict__ hout) {
    extern __shared__ char smem[];
    const uint32_t sb = smem_u32(smem);

    const int tid = threadIdx.x;
    const int w   = tid >> 5;
    const int lid = tid & 31;
    const int qi  = gridDim.x - 1 - blockIdx.x;   // big tiles first
    const int h   = blockIdx.y;
    const int b   = blockIdx.z;
    const int head = b * NH + h;
    const int qbase = qi * 128;

    const __nv_bfloat16* Qh = g_q_hi + ((size_t)head * SEQ + qbase) * HD;
    const __nv_bfloat16* Ql = g_q_lo + ((size_t)head * SEQ + qbase) * HD;
    const __nv_bfloat16* Kh = g_k_hi + (size_t)head * SEQ * HD;
    const __nv_bfloat16* Kl = g_k_lo + (size_t)head * SEQ * HD;
    const __nv_bfloat16* Vh = g_vt_hi + (size_t)head * HD * SEQ;
    const __nv_bfloat16* Vl = g_vt_lo + (size_t)head * HD * SEQ;

    // Stage Q (hi+lo): 2 x 128 rows x 8 chunks = 2048 cp -> 8/thread
    #pragma unroll
    for (int it = 0; it < 8; ++it) {
        int idx  = it * 256 + tid;
        int prec = idx >> 10;
        int rem  = idx & 1023;
        int r    = rem >> 3;
        int c8   = rem & 7;
        const __nv_bfloat16* src = (prec ? Ql : Qh) + (size_t)r * HD + c8 * 8;
        CP_ASYNC16(sb + (prec ? SQ_LO : SQ_HI) + r * AROWB + c8 * 16, src);
    }
    CP_COMMIT();

    const uint32_t offA = (((lid >> 3) & 1) * 8 + (lid & 7)) * AROWB + (lid >> 4) * 16;
    const uint32_t offB = ((lid >> 4) * 8 + (lid & 7)) * AROWB + ((lid >> 3) & 1) * 16;
    const uint32_t qA_hi = sb + SQ_HI + w * 16 * AROWB + offA;
    const uint32_t qA_lo = sb + SQ_LO + w * 16 * AROWB + offA;

    float o[8][4];
    #pragma unroll
    for (int nt = 0; nt < 8; ++nt)
        #pragma unroll
        for (int e = 0; e < 4; ++e) o[nt][e] = 0.f;
    float m_i[2] = {NEG_BIG, NEG_BIG};
    float l_i[2] = {0.f, 0.f};

    const int ntiles = 2 * qi + 2;
    for (int jt = 0; jt < ntiles; ++jt) {
        __syncthreads();   // previous iteration done with K/VT smem
        // Stage K + VT (hi+lo): 4 bufs x 64 rows x 8 chunks = 2048 -> 8/thread
        #pragma unroll
        for (int it = 0; it < 8; ++it) {
            int idx = it * 256 + tid;
            int buf = idx >> 9;           // 0:Khi 1:Klo 2:VThi 3:VTlo
            int rem = idx & 511;
            int r   = rem >> 3;
            int c8  = rem & 7;
            const __nv_bfloat16* src;
            if (buf == 0)      src = Kh + (size_t)(jt * 64 + r) * HD + c8 * 8;
            else if (buf == 1) src = Kl + (size_t)(jt * 64 + r) * HD + c8 * 8;
            else if (buf == 2) src = Vh + (size_t)r * SEQ + jt * 64 + c8 * 8;
            else               src = Vl + (size_t)r * SEQ + jt * 64 + c8 * 8;
            CP_ASYNC16(sb + SK_HI + buf * 9216 + r * AROWB + c8 * 16, src);
        }
        CP_COMMIT();
        CP_WAIT(0);
        __syncthreads();

        // ---- S = Q @ K^T (bf16x3) ----
        float s[8][4];
        #pragma unroll
        for (int nt = 0; nt < 8; ++nt)
            #pragma unroll
            for (int e = 0; e < 4; ++e) s[nt][e] = 0.f;

        #pragma unroll
        for (int kc = 0; kc < 4; ++kc) {
            const uint32_t ko = kc * 32;
            uint32_t ah[4], al[4];
            ldsm_x4(ah[0], ah[1], ah[2], ah[3], qA_hi + ko);
            ldsm_x4(al[0], al[1], al[2], al[3], qA_lo + ko);
            #pragma unroll
            for (int p = 0; p < 4; ++p) {
                uint32_t bh[4], bl[4];
                ldsm_x4(bh[0], bh[1], bh[2], bh[3],
                        sb + SK_HI + p * 16 * AROWB + offB + ko);
                ldsm_x4(bl[0], bl[1], bl[2], bl[3],
                        sb + SK_HI + 9216 + p * 16 * AROWB + offB + ko);
                #pragma unroll
                for (int half = 0; half < 2; ++half) {
                    int nt = p * 2 + half;
                    mma16816(s[nt], ah[0], ah[1], ah[2], ah[3],
                             bh[half * 2], bh[half * 2 + 1]);
                    mma16816(s[nt], ah[0], ah[1], ah[2], ah[3],
                             bl[half * 2], bl[half * 2 + 1]);
                    mma16816(s[nt], al[0], al[1], al[2], al[3],
                             bh[half * 2], bh[half * 2 + 1]);
                }
            }
        }

        // ---- causal mask (diagonal tiles only) ----
        if (jt >= 2 * qi) {
            #pragma unroll
            for (int i = 0; i < 2; ++i) {
                int qg = qbase + w * 16 + (lid >> 2) + i * 8;
                #pragma unroll
                for (int nt = 0; nt < 8; ++nt) {
                    int kg = jt * 64 + nt * 8 + (lid & 3) * 2;
                    if (kg > qg)     s[nt][2*i]     = NEG_BIG;
                    if (kg + 1 > qg) s[nt][2*i + 1] = NEG_BIG;
                }
            }
        }

        // ---- online softmax (quad reductions) ----
        #pragma unroll
        for (int i = 0; i < 2; ++i) {
            float rm = NEG_BIG;
            #pragma unroll
            for (int nt = 0; nt < 8; ++nt)
                rm = fmaxf(rm, fmaxf(s[nt][2*i], s[nt][2*i+1]));
            rm = fmaxf(rm, __shfl_xor_sync(0xffffffffu, rm, 1));
            rm = fmaxf(rm, __shfl_xor_sync(0xffffffffu, rm, 2));
            float mnew = fmaxf(m_i[i], rm);
            float corr = __expf(m_i[i] - mnew);
            float rs = 0.f;
            #pragma unroll
            for (int nt = 0; nt < 8; ++nt) {
                float p0 = __expf(s[nt][2*i]     - mnew);
                float p1 = __expf(s[nt][2*i + 1] - mnew);
                s[nt][2*i] = p0; s[nt][2*i+1] = p1;
                rs += p0 + p1;
            }
            rs += __shfl_xor_sync(0xffffffffu, rs, 1);
            rs += __shfl_xor_sync(0xffffffffu, rs, 2);
            l_i[i] = l_i[i] * corr + rs;
            m_i[i] = mnew;
            #pragma unroll
            for (int nt = 0; nt < 8; ++nt) {
                o[nt][2*i]     *= corr;
                o[nt][2*i + 1] *= corr;
            }
        }

        // ---- O += P @ V (bf16x3; P from registers) ----
        #pragma unroll
        for (int kc = 0; kc < 4; ++kc) {
            // A fragments of P for keys 16kc..16kc+15
            uint32_t ph[4], pl[4];
            {
                float c0 = s[2*kc][0],   c1 = s[2*kc][1];
                float c2 = s[2*kc][2],   c3 = s[2*kc][3];
                float d0 = s[2*kc+1][0], d1 = s[2*kc+1][1];
                float d2 = s[2*kc+1][2], d3 = s[2*kc+1][3];
                ph[0] = pack_bf16x2(c0, c1);
                ph[1] = pack_bf16x2(c2, c3);
                ph[2] = pack_bf16x2(d0, d1);
                ph[3] = pack_bf16x2(d2, d3);
                __nv_bfloat162* hp = (__nv_bfloat162*)ph;
                float2 h0 = __bfloat1622float2(hp[0]);
                float2 h1 = __bfloat1622float2(hp[1]);
                float2 h2 = __bfloat1622float2(hp[2]);
                float2 h3 = __bfloat1622float2(hp[3]);
                pl[0] = pack_bf16x2(c0 - h0.x, c1 - h0.y);
                pl[1] = pack_bf16x2(c2 - h1.x, c3 - h1.y);
                pl[2] = pack_bf16x2(d0 - h2.x, d1 - h2.y);
                pl[3] = pack_bf16x2(d2 - h3.x, d3 - h3.y);
            }
            const uint32_t ko = kc * 32;
            #pragma unroll
            for (int p = 0; p < 4; ++p) {
                uint32_t vh[4], vl[4];
                ldsm_x4(vh[0], vh[1], vh[2], vh[3],
                        sb + SK_HI + 2 * 9216 + p * 16 * AROWB + offB + ko);
                ldsm_x4(vl[0], vl[1], vl[2], vl[3],
                        sb + SK_HI + 3 * 9216 + p * 16 * AROWB + offB + ko);
                #pragma unroll
                for (int half = 0; half < 2; ++half) {
                    int nt = p * 2 + half;
                    mma16816(o[nt], ph[0], ph[1], ph[2], ph[3],
                             vh[half * 2], vh[half * 2 + 1]);
                    mma16816(o[nt], ph[0], ph[1], ph[2], ph[3],
                             vl[half * 2], vl[half * 2 + 1]);
                    mma16816(o[nt], pl[0], pl[1], pl[2], pl[3],
                             vh[half * 2], vh[half * 2 + 1]);
                }
            }
        }
    }

    // ---- epilogue: normalize, write h [b][s][dmodel] ----
    #pragma unroll
    for (int i = 0; i < 2; ++i) {
        float inv = 1.f / l_i[i];
        int q = qbase + w * 16 + (lid >> 2) + i * 8;
        float* op = hout + ((size_t)b * SEQ + q) * DMODEL + h * HD;
        #pragma unroll
        for (int nt = 0; nt < 8; ++nt) {
            int d = nt * 8 + (lid & 3) * 2;
            *(float2*)(op + d) = make_float2(o[nt][2*i] * inv, o[nt][2*i+1] * inv);
        }
    }
}

// ---------------------------------------------------------------------------
// Launch
// ---------------------------------------------------------------------------
extern "C" void kernel_launch(void* const* d_in, const int* in_sizes, int n_in,
                              void* d_out, int out_size) {
    const float* x    = (const float*)d_in[0];  // [2,2048,1024]
    const float* Wqkv = (const float*)d_in[1];  // [3072,1024]
    const float* Wo   = (const float*)d_in[2];  // [1024,1024]
    float* out = (float*)d_out;                 // [2,2048,1024]

    float *qkv_ptr = nullptr, *h_ptr = nullptr;
    cudaGetSymbolAddress((void**)&qkv_ptr, g_qkv);
    cudaGetSymbolAddress((void**)&h_ptr,   g_h);
    __nv_bfloat16 *xs_hi, *xs_lo, *wq_hi, *wq_lo, *wo_hi, *wo_lo, *hs_hi, *hs_lo;
    __nv_bfloat16 *q_hi, *q_lo, *k_hi, *k_lo, *vt_hi, *vt_lo;
    cudaGetSymbolAddress((void**)&xs_hi, g_xs_hi);
    cudaGetSymbolAddress((void**)&xs_lo, g_xs_lo);
    cudaGetSymbolAddress((void**)&wq_hi, g_wq_hi);
    cudaGetSymbolAddress((void**)&wq_lo, g_wq_lo);
    cudaGetSymbolAddress((void**)&wo_hi, g_wo_hi);
    cudaGetSymbolAddress((void**)&wo_lo, g_wo_lo);
    cudaGetSymbolAddress((void**)&hs_hi, g_hs_hi);
    cudaGetSymbolAddress((void**)&hs_lo, g_hs_lo);
    cudaGetSymbolAddress((void**)&q_hi,  g_q_hi);
    cudaGetSymbolAddress((void**)&q_lo,  g_q_lo);
    cudaGetSymbolAddress((void**)&k_hi,  g_k_hi);
    cudaGetSymbolAddress((void**)&k_lo,  g_k_lo);
    cudaGetSymbolAddress((void**)&vt_hi, g_vt_hi);
    cudaGetSymbolAddress((void**)&vt_lo, g_vt_lo);

    static bool attr_done = false;
    if (!attr_done) {
        cudaFuncSetAttribute(gemm_bf16x3,
                             cudaFuncAttributeMaxDynamicSharedMemorySize, GEMM_SMEM);
        cudaFuncSetAttribute(attn_mma,
                             cudaFuncAttributeMaxDynamicSharedMemorySize, ATT_SMEM);
        attr_done = true;
    }

    const int n_x  = TOKENS * DMODEL;
    const int n_wq = 3 * DMODEL * DMODEL;
    const int n_wo = DMODEL * DMODEL;

    // Pre-split GEMM operands
    split_bf16<<<n_x  / 2048, 256>>>(x,    xs_hi, xs_lo, n_x);
    split_bf16<<<n_wq / 2048, 256>>>(Wqkv, wq_hi, wq_lo, n_wq);
    split_bf16<<<n_wo / 2048, 256>>>(Wo,   wo_hi, wo_lo, n_wo);

    // 1) QKV projection
    {
        dim3 grid(3 * DMODEL / 128, TOKENS / 128);
        gemm_bf16x3<<<grid, 256, GEMM_SMEM>>>(xs_hi, xs_lo, wq_hi, wq_lo,
                                              qkv_ptr, TOKENS, 3 * DMODEL, DMODEL);
    }
    // 1b) Split qkv into per-head bf16 hi/lo (Q scaled, V transposed)
    {
        dim3 grid(SEQ / 64, NH, BATCH);
        split_qkv<<<grid, 256>>>(q_hi, q_lo, k_hi, k_lo, vt_hi, vt_lo);
    }
    // 2) HMMA causal flash attention -> g_h
    {
        dim3 grid(SEQ / 128, NH, BATCH);
        attn_mma<<<grid, 256, ATT_SMEM>>>(h_ptr);
    }
    // 3) Output projection
    split_bf16<<<n_x / 2048, 256>>>(h_ptr, hs_hi, hs_lo, n_x);
    {
        dim3 grid(DMODEL / 128, TOKENS / 128);
        gemm_bf16x3<<<grid, 256, GEMM_SMEM>>>(hs_hi, hs_lo, wo_hi, wo_lo,
                                              out, TOKENS, DMODEL, DMODEL);
    }
}

// round 6
// speedup vs baseline: 2.9821x; 1.1251x over previous
#include <cuda_runtime.h>
#include <cuda_bf16.h>
#include <cstdint>
#include <math.h>

// Problem constants (fixed by the reference)
#define BATCH   2
#define SEQ     2048
#define DMODEL  1024
#define NH      16
#define HD      64
#define TOKENS  (BATCH*SEQ)          // 4096
#define NHEADS_TOTAL (BATCH*NH)      // 32

// ---------------------------------------------------------------------------
// Scratch (__device__ globals; allocation in kernel_launch is forbidden)
// ---------------------------------------------------------------------------
__device__ float g_qkv[(size_t)TOKENS * 3 * DMODEL];  // [4096, 3072]
__device__ float g_h  [(size_t)TOKENS * DMODEL];      // [4096, 1024]

__device__ __nv_bfloat16 g_xs_hi[(size_t)TOKENS * DMODEL];
__device__ __nv_bfloat16 g_xs_lo[(size_t)TOKENS * DMODEL];
__device__ __nv_bfloat16 g_wq_hi[(size_t)3 * DMODEL * DMODEL];
__device__ __nv_bfloat16 g_wq_lo[(size_t)3 * DMODEL * DMODEL];
__device__ __nv_bfloat16 g_wo_hi[(size_t)DMODEL * DMODEL];
__device__ __nv_bfloat16 g_wo_lo[(size_t)DMODEL * DMODEL];
__device__ __nv_bfloat16 g_hs_hi[(size_t)TOKENS * DMODEL];
__device__ __nv_bfloat16 g_hs_lo[(size_t)TOKENS * DMODEL];

// Per-head attention operands (bf16 hi/lo)
// Q,K: [head][s][64]; VT: [head][64][s] (transposed)
#define HEADELEMS ((size_t)NHEADS_TOTAL * SEQ * HD)
__device__ __nv_bfloat16 g_q_hi[HEADELEMS];
__device__ __nv_bfloat16 g_q_lo[HEADELEMS];
__device__ __nv_bfloat16 g_k_hi[HEADELEMS];
__device__ __nv_bfloat16 g_k_lo[HEADELEMS];
__device__ __nv_bfloat16 g_vt_hi[HEADELEMS];
__device__ __nv_bfloat16 g_vt_lo[HEADELEMS];

// ---------------------------------------------------------------------------
// PTX helpers (sm_80-era instructions only — compute_100-safe)
// ---------------------------------------------------------------------------
__device__ __forceinline__ uint32_t smem_u32(const void* p) {
    uint32_t a;
    asm("{ .reg .u64 t; cvta.to.shared.u64 t, %1; cvt.u32.u64 %0, t; }"
        : "=r"(a) : "l"(p));
    return a;
}

#define CP_ASYNC16(dst, src) \
    asm volatile("cp.async.cg.shared.global [%0], [%1], 16;" \
                 :: "r"(dst), "l"(src) : "memory")
#define CP_COMMIT() asm volatile("cp.async.commit_group;" ::: "memory")
#define CP_WAIT(N)  asm volatile("cp.async.wait_group %0;" :: "n"(N) : "memory")

__device__ __forceinline__ void ldsm_x4(uint32_t& r0, uint32_t& r1,
                                        uint32_t& r2, uint32_t& r3, uint32_t addr) {
    asm volatile("ldmatrix.sync.aligned.m8n8.x4.shared.b16 {%0,%1,%2,%3}, [%4];"
                 : "=r"(r0), "=r"(r1), "=r"(r2), "=r"(r3) : "r"(addr));
}

__device__ __forceinline__ void mma16816(float* c, uint32_t a0, uint32_t a1,
                                         uint32_t a2, uint32_t a3,
                                         uint32_t b0, uint32_t b1) {
    asm volatile(
        "mma.sync.aligned.m16n8k16.row.col.f32.bf16.bf16.f32 "
        "{%0,%1,%2,%3}, {%4,%5,%6,%7}, {%8,%9}, {%0,%1,%2,%3};"
        : "+f"(c[0]), "+f"(c[1]), "+f"(c[2]), "+f"(c[3])
        : "r"(a0), "r"(a1), "r"(a2), "r"(a3), "r"(b0), "r"(b1));
}

__device__ __forceinline__ uint32_t pack_bf16x2(float a, float b) {
    __nv_bfloat162 h2 = __float22bfloat162_rn(make_float2(a, b));
    return *(uint32_t*)&h2;
}

// ---------------------------------------------------------------------------
// Split: fp32 -> bf16 hi + bf16 lo (residual). n multiple of 2048.
// ---------------------------------------------------------------------------
__global__ __launch_bounds__(256) void split_bf16(const float* __restrict__ in,
                                                  __nv_bfloat16* __restrict__ hi,
                                                  __nv_bfloat16* __restrict__ lo,
                                                  int n) {
    int base = (blockIdx.x * 256 + threadIdx.x) * 8;
    if (base >= n) return;
    float4 f0 = *(const float4*)(in + base);
    float4 f1 = *(const float4*)(in + base + 4);
    float f[8] = {f0.x, f0.y, f0.z, f0.w, f1.x, f1.y, f1.z, f1.w};
    uint32_t h[4], l[4];
    #pragma unroll
    for (int j = 0; j < 4; ++j) {
        __nv_bfloat162 h2 = __float22bfloat162_rn(make_float2(f[2*j], f[2*j+1]));
        float2 hf = __bfloat1622float2(h2);
        __nv_bfloat162 l2 = __float22bfloat162_rn(
            make_float2(f[2*j] - hf.x, f[2*j+1] - hf.y));
        h[j] = *(uint32_t*)&h2;
        l[j] = *(uint32_t*)&l2;
    }
    *(uint4*)(hi + base) = make_uint4(h[0], h[1], h[2], h[3]);
    *(uint4*)(lo + base) = make_uint4(l[0], l[1], l[2], l[3]);
}

// ---------------------------------------------------------------------------
// split_qkv: g_qkv [4096,3072] fp32 -> per-head bf16 hi/lo tensors.
// ---------------------------------------------------------------------------
__global__ __launch_bounds__(256, 4) void split_qkv(
    __nv_bfloat16* __restrict__ qhi, __nv_bfloat16* __restrict__ qlo,
    __nv_bfloat16* __restrict__ khi, __nv_bfloat16* __restrict__ klo,
    __nv_bfloat16* __restrict__ vthi, __nv_bfloat16* __restrict__ vtlo) {
    __shared__ __nv_bfloat16 vt_h[64][72];
    __shared__ __nv_bfloat16 vt_l[64][72];

    const int tid = threadIdx.x;
    const int s0  = blockIdx.x * 64;
    const int h   = blockIdx.y;
    const int b   = blockIdx.z;
    const int head = b * NH + h;

    #pragma unroll
    for (int it = 0; it < 2; ++it) {
        int unit = it * 256 + tid;       // 0..511
        int sl   = unit >> 3;            // 0..63
        int d0   = (unit & 7) * 8;
        int s    = s0 + sl;
        const float* base = g_qkv + ((size_t)(b * SEQ + s)) * (3 * DMODEL) + h * HD + d0;
        size_t qkidx = ((size_t)head * SEQ + s) * HD + d0;

        // ---- Q (scaled) ----
        {
            float4 f0 = *(const float4*)(base);
            float4 f1 = *(const float4*)(base + 4);
            float f[8] = {f0.x, f0.y, f0.z, f0.w, f1.x, f1.y, f1.z, f1.w};
            uint32_t hh[4], ll[4];
            #pragma unroll
            for (int j = 0; j < 4; ++j) {
                float a = f[2*j] * 0.125f, c = f[2*j+1] * 0.125f;
                __nv_bfloat162 h2 = __float22bfloat162_rn(make_float2(a, c));
                float2 hf = __bfloat1622float2(h2);
                __nv_bfloat162 l2 = __float22bfloat162_rn(make_float2(a - hf.x, c - hf.y));
                hh[j] = *(uint32_t*)&h2;
                ll[j] = *(uint32_t*)&l2;
            }
            *(uint4*)(qhi + qkidx) = make_uint4(hh[0], hh[1], hh[2], hh[3]);
            *(uint4*)(qlo + qkidx) = make_uint4(ll[0], ll[1], ll[2], ll[3]);
        }
        // ---- K ----
        {
            float4 f0 = *(const float4*)(base + DMODEL);
            float4 f1 = *(const float4*)(base + DMODEL + 4);
            float f[8] = {f0.x, f0.y, f0.z, f0.w, f1.x, f1.y, f1.z, f1.w};
            uint32_t hh[4], ll[4];
            #pragma unroll
            for (int j = 0; j < 4; ++j) {
                __nv_bfloat162 h2 = __float22bfloat162_rn(make_float2(f[2*j], f[2*j+1]));
                float2 hf = __bfloat1622float2(h2);
                __nv_bfloat162 l2 = __float22bfloat162_rn(
                    make_float2(f[2*j] - hf.x, f[2*j+1] - hf.y));
                hh[j] = *(uint32_t*)&h2;
                ll[j] = *(uint32_t*)&l2;
            }
            *(uint4*)(khi + qkidx) = make_uint4(hh[0], hh[1], hh[2], hh[3]);
            *(uint4*)(klo + qkidx) = make_uint4(ll[0], ll[1], ll[2], ll[3]);
        }
        // ---- V -> smem transpose ----
        {
            float4 f0 = *(const float4*)(base + 2 * DMODEL);
            float4 f1 = *(const float4*)(base + 2 * DMODEL + 4);
            float f[8] = {f0.x, f0.y, f0.z, f0.w, f1.x, f1.y, f1.z, f1.w};
            #pragma unroll
            for (int j = 0; j < 8; ++j) {
                __nv_bfloat16 hv = __float2bfloat16(f[j]);
                __nv_bfloat16 lv = __float2bfloat16(f[j] - __bfloat162float(hv));
                vt_h[d0 + j][sl] = hv;
                vt_l[d0 + j][sl] = lv;
            }
        }
    }
    __syncthreads();

    #pragma unroll
    for (int it = 0; it < 4; ++it) {
        int idx  = it * 256 + tid;       // 0..1023
        int prec = idx >> 9;
        int rem  = idx & 511;
        int r    = rem >> 3;
        int c    = (rem & 7) * 8;
        uint4 v = prec ? *(uint4*)&vt_l[r][c] : *(uint4*)&vt_h[r][c];
        __nv_bfloat16* dst = (prec ? vtlo : vthi) +
                             ((size_t)head * HD + r) * SEQ + s0 + c;
        *(uint4*)dst = v;
    }
}

// ---------------------------------------------------------------------------
// bf16x3 warp-MMA GEMM v2: C[M,N] = A[M,K] @ B[N,K]^T
// CTA tile 128x256, warp tile 64x64 (8 warps, 2x4), K-chunk 32, 3-stage
// cp.async pipeline. MMA:LDSM ratio 6:1 (was 4:1).
// ---------------------------------------------------------------------------
#define ROWB 80                         // 32 bf16 + 16B pad
#define G2_AT (128 * ROWB)              // 10240 per A tile
#define G2_BT (256 * ROWB)              // 20480 per B tile
#define G2_STAGE (2 * G2_AT + 2 * G2_BT)  // 61440
#define G2_SMEM (3 * G2_STAGE)          // 184320

__device__ __forceinline__ void g2_issue(
    uint32_t stage, const __nv_bfloat16* __restrict__ Ahi,
    const __nv_bfloat16* __restrict__ Alo,
    const __nv_bfloat16* __restrict__ Bhi,
    const __nv_bfloat16* __restrict__ Blo,
    int kc, int K, int tid) {
    // A hi/lo: 2 x 128 rows x 4 chunks = 1024 cp -> 4/thread
    #pragma unroll
    for (int i = 0; i < 4; ++i) {
        int idx  = i * 256 + tid;        // 0..1023
        int prec = idx >> 9;
        int rem  = idx & 511;
        int row  = rem >> 2;
        int c    = rem & 3;
        const __nv_bfloat16* src = (prec ? Alo : Ahi) + (size_t)row * K + kc * 32 + c * 8;
        CP_ASYNC16(stage + prec * G2_AT + row * ROWB + c * 16, src);
    }
    // B hi/lo: 2 x 256 rows x 4 chunks = 2048 cp -> 8/thread
    #pragma unroll
    for (int i = 0; i < 8; ++i) {
        int idx  = i * 256 + tid;        // 0..2047
        int prec = idx >> 10;
        int rem  = idx & 1023;
        int row  = rem >> 2;
        int c    = rem & 3;
        const __nv_bfloat16* src = (prec ? Blo : Bhi) + (size_t)row * K + kc * 32 + c * 8;
        CP_ASYNC16(stage + 2 * G2_AT + prec * G2_BT + row * ROWB + c * 16, src);
    }
}

__global__ __launch_bounds__(256, 1) void gemm_bf16x3(
    const __nv_bfloat16* __restrict__ Ahi, const __nv_bfloat16* __restrict__ Alo,
    const __nv_bfloat16* __restrict__ Bhi, const __nv_bfloat16* __restrict__ Blo,
    float* __restrict__ C, int M, int N, int K) {
    extern __shared__ char smem[];
    const uint32_t sb = smem_u32(smem);

    const int tid = threadIdx.x;
    const int wid = tid >> 5;
    const int lid = tid & 31;
    const int wm  = wid & 1;       // 0..1 -> 64 rows
    const int wn  = wid >> 1;      // 0..3 -> 64 cols

    const int brow = blockIdx.y;
    const int bcol = blockIdx.x;

    const __nv_bfloat16* Ah = Ahi + (size_t)brow * 128 * K;
    const __nv_bfloat16* Al = Alo + (size_t)brow * 128 * K;
    const __nv_bfloat16* Bh = Bhi + (size_t)bcol * 256 * K;
    const __nv_bfloat16* Bl = Blo + (size_t)bcol * 256 * K;

    const uint32_t offA = (((lid >> 3) & 1) * 8 + (lid & 7)) * ROWB + (lid >> 4) * 16;
    const uint32_t offB = ((lid >> 4) * 8 + (lid & 7)) * ROWB + ((lid >> 3) & 1) * 16;

    float acc[4][8][4];
    #pragma unroll
    for (int i = 0; i < 4; ++i)
        #pragma unroll
        for (int j = 0; j < 8; ++j)
            #pragma unroll
            for (int e = 0; e < 4; ++e) acc[i][j][e] = 0.f;

    const int nch = K / 32;      // 32
    g2_issue(sb + 0 * G2_STAGE, Ah, Al, Bh, Bl, 0, K, tid);
    CP_COMMIT();
    g2_issue(sb + 1 * G2_STAGE, Ah, Al, Bh, Bl, 1, K, tid);
    CP_COMMIT();

    for (int kc = 0; kc < nch; ++kc) {
        if (kc + 1 < nch) { CP_WAIT(1); } else { CP_WAIT(0); }
        __syncthreads();

        const uint32_t cur  = sb + (kc % 3) * G2_STAGE;
        const uint32_t aHiB = cur + wm * 64 * ROWB + offA;
        const uint32_t aLoB = cur + G2_AT + wm * 64 * ROWB + offA;
        const uint32_t bHiB = cur + 2 * G2_AT + wn * 64 * ROWB + offB;
        const uint32_t bLoB = cur + 2 * G2_AT + G2_BT + wn * 64 * ROWB + offB;

        #pragma unroll
        for (int k16 = 0; k16 < 2; ++k16) {
            const uint32_t ko = k16 * 32;

            uint32_t bh[16], bl[16];
            #pragma unroll
            for (int nb = 0; nb < 4; ++nb) {
                ldsm_x4(bh[nb*4], bh[nb*4+1], bh[nb*4+2], bh[nb*4+3],
                        bHiB + nb * 16 * ROWB + ko);
                ldsm_x4(bl[nb*4], bl[nb*4+1], bl[nb*4+2], bl[nb*4+3],
                        bLoB + nb * 16 * ROWB + ko);
            }

            #pragma unroll
            for (int mt = 0; mt < 4; ++mt) {
                uint32_t ah[4], al[4];
                ldsm_x4(ah[0], ah[1], ah[2], ah[3], aHiB + mt * 16 * ROWB + ko);
                ldsm_x4(al[0], al[1], al[2], al[3], aLoB + mt * 16 * ROWB + ko);
                #pragma unroll
                for (int nt = 0; nt < 8; ++nt) {
                    mma16816(acc[mt][nt], ah[0], ah[1], ah[2], ah[3],
                             bh[nt * 2], bh[nt * 2 + 1]);
                    mma16816(acc[mt][nt], ah[0], ah[1], ah[2], ah[3],
                             bl[nt * 2], bl[nt * 2 + 1]);
                    mma16816(acc[mt][nt], al[0], al[1], al[2], al[3],
                             bh[nt * 2], bh[nt * 2 + 1]);
                }
            }
        }

        if (kc + 2 < nch) {
            g2_issue(sb + ((kc + 2) % 3) * G2_STAGE, Ah, Al, Bh, Bl, kc + 2, K, tid);
            CP_COMMIT();
        }
    }

    // Epilogue
    const int r0 = brow * 128 + wm * 64 + (lid >> 2);
    const int c0 = bcol * 256 + wn * 64 + (lid & 3) * 2;
    #pragma unroll
    for (int mt = 0; mt < 4; ++mt) {
        #pragma unroll
        for (int nt = 0; nt < 8; ++nt) {
            float* p = C + (size_t)(r0 + mt * 16) * N + c0 + nt * 8;
            *(float2*)p                   = make_float2(acc[mt][nt][0], acc[mt][nt][1]);
            *(float2*)(p + (size_t)8 * N) = make_float2(acc[mt][nt][2], acc[mt][nt][3]);
        }
    }
}

// ---------------------------------------------------------------------------
// HMMA flash attention (bf16x3), causal — now with double-buffered K/VT.
// ---------------------------------------------------------------------------
#define AROWB 144
#define SQ_HI   0
#define SQ_LO   18432
#define SK_BASE 36864
#define KVSTAGE 36864              // 4 tiles x 64 x 144
#define ATT_SMEM (SK_BASE + 2 * KVSTAGE)   // 110592
#define NEG_BIG (-1e30f)

__device__ __forceinline__ void att_issue_kv(
    uint32_t kvbase, const __nv_bfloat16* __restrict__ Kh,
    const __nv_bfloat16* __restrict__ Kl,
    const __nv_bfloat16* __restrict__ Vh,
    const __nv_bfloat16* __restrict__ Vl, int jt, int tid) {
    #pragma unroll
    for (int it = 0; it < 8; ++it) {
        int idx = it * 256 + tid;
        int buf = idx >> 9;           // 0:Khi 1:Klo 2:VThi 3:VTlo
        int rem = idx & 511;
        int r   = rem >> 3;
        int c8  = rem & 7;
        const __nv_bfloat16* src;
        if (buf == 0)      src = Kh + (size_t)(jt * 64 + r) * HD + c8 * 8;
        else if (buf == 1) src = Kl + (size_t)(jt * 64 + r) * HD + c8 * 8;
        else if (buf == 2) src = Vh + (size_t)r * SEQ + jt * 64 + c8 * 8;
        else               src = Vl + (size_t)r * SEQ + jt * 64 + c8 * 8;
        CP_ASYNC16(kvbase + buf * 9216 + r * AROWB + c8 * 16, src);
    }
}

__global__ __launch_bounds__(256, 2) void attn_mma(float* __restrict__ hout) {
    extern __shared__ char smem[];
    const uint32_t sb = smem_u32(smem);

    const int tid = threadIdx.x;
    const int w   = tid >> 5;
    const int lid = tid & 31;
    const int qi  = gridDim.x - 1 - blockIdx.x;   // big tiles first
    const int h   = blockIdx.y;
    const int b   = blockIdx.z;
    const int head = b * NH + h;
    const int qbase = qi * 128;

    const __nv_bfloat16* Qh = g_q_hi + ((size_t)head * SEQ + qbase) * HD;
    const __nv_bfloat16* Ql = g_q_lo + ((size_t)head * SEQ + qbase) * HD;
    const __nv_bfloat16* Kh = g_k_hi + (size_t)head * SEQ * HD;
    const __nv_bfloat16* Kl = g_k_lo + (size_t)head * SEQ * HD;
    const __nv_bfloat16* Vh = g_vt_hi + (size_t)head * HD * SEQ;
    const __nv_bfloat16* Vl = g_vt_lo + (size_t)head * HD * SEQ;

    // Stage Q (hi+lo)
    #pragma unroll
    for (int it = 0; it < 8; ++it) {
        int idx  = it * 256 + tid;
        int prec = idx >> 10;
        int rem  = idx & 1023;
        int r    = rem >> 3;
        int c8   = rem & 7;
        const __nv_bfloat16* src = (prec ? Ql : Qh) + (size_t)r * HD + c8 * 8;
        CP_ASYNC16(sb + (prec ? SQ_LO : SQ_HI) + r * AROWB + c8 * 16, src);
    }
    CP_COMMIT();

    const int ntiles = 2 * qi + 2;     // >= 2 always
    // Prefetch KV tiles 0 and 1 into the two buffers
    att_issue_kv(sb + SK_BASE + 0 * KVSTAGE, Kh, Kl, Vh, Vl, 0, tid);
    CP_COMMIT();
    att_issue_kv(sb + SK_BASE + 1 * KVSTAGE, Kh, Kl, Vh, Vl, 1, tid);
    CP_COMMIT();

    const uint32_t offA = (((lid >> 3) & 1) * 8 + (lid & 7)) * AROWB + (lid >> 4) * 16;
    const uint32_t offB = ((lid >> 4) * 8 + (lid & 7)) * AROWB + ((lid >> 3) & 1) * 16;
    const uint32_t qA_hi = sb + SQ_HI + w * 16 * AROWB + offA;
    const uint32_t qA_lo = sb + SQ_LO + w * 16 * AROWB + offA;

    float o[8][4];
    #pragma unroll
    for (int nt = 0; nt < 8; ++nt)
        #pragma unroll
        for (int e = 0; e < 4; ++e) o[nt][e] = 0.f;
    float m_i[2] = {NEG_BIG, NEG_BIG};
    float l_i[2] = {0.f, 0.f};

    for (int jt = 0; jt < ntiles; ++jt) {
        if (jt < ntiles - 1) { CP_WAIT(1); } else { CP_WAIT(0); }
        __syncthreads();

        const uint32_t kvb = sb + SK_BASE + (jt & 1) * KVSTAGE;

        // ---- S = Q @ K^T (bf16x3) ----
        float s[8][4];
        #pragma unroll
        for (int nt = 0; nt < 8; ++nt)
            #pragma unroll
            for (int e = 0; e < 4; ++e) s[nt][e] = 0.f;

        #pragma unroll
        for (int kc = 0; kc < 4; ++kc) {
            const uint32_t ko = kc * 32;
            uint32_t ah[4], al[4];
            ldsm_x4(ah[0], ah[1], ah[2], ah[3], qA_hi + ko);
            ldsm_x4(al[0], al[1], al[2], al[3], qA_lo + ko);
            #pragma unroll
            for (int p = 0; p < 4; ++p) {
                uint32_t bh[4], bl[4];
                ldsm_x4(bh[0], bh[1], bh[2], bh[3],
                        kvb + p * 16 * AROWB + offB + ko);
                ldsm_x4(bl[0], bl[1], bl[2], bl[3],
                        kvb + 9216 + p * 16 * AROWB + offB + ko);
                #pragma unroll
                for (int half = 0; half < 2; ++half) {
                    int nt = p * 2 + half;
                    mma16816(s[nt], ah[0], ah[1], ah[2], ah[3],
                             bh[half * 2], bh[half * 2 + 1]);
                    mma16816(s[nt], ah[0], ah[1], ah[2], ah[3],
                             bl[half * 2], bl[half * 2 + 1]);
                    mma16816(s[nt], al[0], al[1], al[2], al[3],
                             bh[half * 2], bh[half * 2 + 1]);
                }
            }
        }

        // ---- causal mask (diagonal tiles only) ----
        if (jt >= 2 * qi) {
            #pragma unroll
            for (int i = 0; i < 2; ++i) {
                int qg = qbase + w * 16 + (lid >> 2) + i * 8;
                #pragma unroll
                for (int nt = 0; nt < 8; ++nt) {
                    int kg = jt * 64 + nt * 8 + (lid & 3) * 2;
                    if (kg > qg)     s[nt][2*i]     = NEG_BIG;
                    if (kg + 1 > qg) s[nt][2*i + 1] = NEG_BIG;
                }
            }
        }

        // ---- online softmax (quad reductions) ----
        #pragma unroll
        for (int i = 0; i < 2; ++i) {
            float rm = NEG_BIG;
            #pragma unroll
            for (int nt = 0; nt < 8; ++nt)
                rm = fmaxf(rm, fmaxf(s[nt][2*i], s[nt][2*i+1]));
            rm = fmaxf(rm, __shfl_xor_sync(0xffffffffu, rm, 1));
            rm = fmaxf(rm, __shfl_xor_sync(0xffffffffu, rm, 2));
            float mnew = fmaxf(m_i[i], rm);
            float corr = __expf(m_i[i] - mnew);
            float rs = 0.f;
            #pragma unroll
            for (int nt = 0; nt < 8; ++nt) {
                float p0 = __expf(s[nt][2*i]     - mnew);
                float p1 = __expf(s[nt][2*i + 1] - mnew);
                s[nt][2*i] = p0; s[nt][2*i+1] = p1;
                rs += p0 + p1;
            }
            rs += __shfl_xor_sync(0xffffffffu, rs, 1);
            rs += __shfl_xor_sync(0xffffffffu, rs, 2);
            l_i[i] = l_i[i] * corr + rs;
            m_i[i] = mnew;
            #pragma unroll
            for (int nt = 0; nt < 8; ++nt) {
                o[nt][2*i]     *= corr;
                o[nt][2*i + 1] *= corr;
            }
        }

        // ---- O += P @ V (bf16x3; P from registers) ----
        #pragma unroll
        for (int kc = 0; kc < 4; ++kc) {
            uint32_t ph[4], pl[4];
            {
                float c0 = s[2*kc][0],   c1 = s[2*kc][1];
                float c2 = s[2*kc][2],   c3 = s[2*kc][3];
                float d0 = s[2*kc+1][0], d1 = s[2*kc+1][1];
                float d2 = s[2*kc+1][2], d3 = s[2*kc+1][3];
                ph[0] = pack_bf16x2(c0, c1);
                ph[1] = pack_bf16x2(c2, c3);
                ph[2] = pack_bf16x2(d0, d1);
                ph[3] = pack_bf16x2(d2, d3);
                __nv_bfloat162* hp = (__nv_bfloat162*)ph;
                float2 h0 = __bfloat1622float2(hp[0]);
                float2 h1 = __bfloat1622float2(hp[1]);
                float2 h2 = __bfloat1622float2(hp[2]);
                float2 h3 = __bfloat1622float2(hp[3]);
                pl[0] = pack_bf16x2(c0 - h0.x, c1 - h0.y);
                pl[1] = pack_bf16x2(c2 - h1.x, c3 - h1.y);
                pl[2] = pack_bf16x2(d0 - h2.x, d1 - h2.y);
                pl[3] = pack_bf16x2(d2 - h3.x, d3 - h3.y);
            }
            const uint32_t ko = kc * 32;
            #pragma unroll
            for (int p = 0; p < 4; ++p) {
                uint32_t vh[4], vl[4];
                ldsm_x4(vh[0], vh[1], vh[2], vh[3],
                        kvb + 2 * 9216 + p * 16 * AROWB + offB + ko);
                ldsm_x4(vl[0], vl[1], vl[2], vl[3],
                        kvb + 3 * 9216 + p * 16 * AROWB + offB + ko);
                #pragma unroll
                for (int half = 0; half < 2; ++half) {
                    int nt = p * 2 + half;
                    mma16816(o[nt], ph[0], ph[1], ph[2], ph[3],
                             vh[half * 2], vh[half * 2 + 1]);
                    mma16816(o[nt], ph[0], ph[1], ph[2], ph[3],
                             vl[half * 2], vl[half * 2 + 1]);
                    mma16816(o[nt], pl[0], pl[1], pl[2], pl[3],
                             vh[half * 2], vh[half * 2 + 1]);
                }
            }
        }

        __syncthreads();   // all warps done reading buffer (jt&1)
        if (jt + 2 < ntiles) {
            att_issue_kv(sb + SK_BASE + (jt & 1) * KVSTAGE, Kh, Kl, Vh, Vl,
                         jt + 2, tid);
            CP_COMMIT();
        }
    }

    // ---- epilogue: normalize, write h [b][s][dmodel] ----
    #pragma unroll
    for (int i = 0; i < 2; ++i) {
        float inv = 1.f / l_i[i];
        int q = qbase + w * 16 + (lid >> 2) + i * 8;
        float* op = hout + ((size_t)b * SEQ + q) * DMODEL + h * HD;
        #pragma unroll
        for (int nt = 0; nt < 8; ++nt) {
            int d = nt * 8 + (lid & 3) * 2;
            *(float2*)(op + d) = make_float2(o[nt][2*i] * inv, o[nt][2*i+1] * inv);
        }
    }
}

// ---------------------------------------------------------------------------
// Launch
// ---------------------------------------------------------------------------
extern "C" void kernel_launch(void* const* d_in, const int* in_sizes, int n_in,
                              void* d_out, int out_size) {
    const float* x    = (const float*)d_in[0];  // [2,2048,1024]
    const float* Wqkv = (const float*)d_in[1];  // [3072,1024]
    const float* Wo   = (const float*)d_in[2];  // [1024,1024]
    float* out = (float*)d_out;                 // [2,2048,1024]

    float *qkv_ptr = nullptr, *h_ptr = nullptr;
    cudaGetSymbolAddress((void**)&qkv_ptr, g_qkv);
    cudaGetSymbolAddress((void**)&h_ptr,   g_h);
    __nv_bfloat16 *xs_hi, *xs_lo, *wq_hi, *wq_lo, *wo_hi, *wo_lo, *hs_hi, *hs_lo;
    __nv_bfloat16 *q_hi, *q_lo, *k_hi, *k_lo, *vt_hi, *vt_lo;
    cudaGetSymbolAddress((void**)&xs_hi, g_xs_hi);
    cudaGetSymbolAddress((void**)&xs_lo, g_xs_lo);
    cudaGetSymbolAddress((void**)&wq_hi, g_wq_hi);
    cudaGetSymbolAddress((void**)&wq_lo, g_wq_lo);
    cudaGetSymbolAddress((void**)&wo_hi, g_wo_hi);
    cudaGetSymbolAddress((void**)&wo_lo, g_wo_lo);
    cudaGetSymbolAddress((void**)&hs_hi, g_hs_hi);
    cudaGetSymbolAddress((void**)&hs_lo, g_hs_lo);
    cudaGetSymbolAddress((void**)&q_hi,  g_q_hi);
    cudaGetSymbolAddress((void**)&q_lo,  g_q_lo);
    cudaGetSymbolAddress((void**)&k_hi,  g_k_hi);
    cudaGetSymbolAddress((void**)&k_lo,  g_k_lo);
    cudaGetSymbolAddress((void**)&vt_hi, g_vt_hi);
    cudaGetSymbolAddress((void**)&vt_lo, g_vt_lo);

    static bool attr_done = false;
    if (!attr_done) {
        cudaFuncSetAttribute(gemm_bf16x3,
                             cudaFuncAttributeMaxDynamicSharedMemorySize, G2_SMEM);
        cudaFuncSetAttribute(attn_mma,
                             cudaFuncAttributeMaxDynamicSharedMemorySize, ATT_SMEM);
        attr_done = true;
    }

    const int n_x  = TOKENS * DMODEL;
    const int n_wq = 3 * DMODEL * DMODEL;
    const int n_wo = DMODEL * DMODEL;

    // Pre-split GEMM operands
    split_bf16<<<n_x  / 2048, 256>>>(x,    xs_hi, xs_lo, n_x);
    split_bf16<<<n_wq / 2048, 256>>>(Wqkv, wq_hi, wq_lo, n_wq);
    split_bf16<<<n_wo / 2048, 256>>>(Wo,   wo_hi, wo_lo, n_wo);

    // 1) QKV projection: [4096,1024] @ [3072,1024]^T
    {
        dim3 grid(3 * DMODEL / 256, TOKENS / 128);   // (12, 32)
        gemm_bf16x3<<<grid, 256, G2_SMEM>>>(xs_hi, xs_lo, wq_hi, wq_lo,
                                            qkv_ptr, TOKENS, 3 * DMODEL, DMODEL);
    }
    // 1b) Split qkv into per-head bf16 hi/lo (Q scaled, V transposed)
    {
        dim3 grid(SEQ / 64, NH, BATCH);
        split_qkv<<<grid, 256>>>(q_hi, q_lo, k_hi, k_lo, vt_hi, vt_lo);
    }
    // 2) HMMA causal flash attention -> g_h
    {
        dim3 grid(SEQ / 128, NH, BATCH);
        attn_mma<<<grid, 256, ATT_SMEM>>>(h_ptr);
    }
    // 3) Output projection: [4096,1024] @ [1024,1024]^T
    split_bf16<<<n_x / 2048, 256>>>(h_ptr, hs_hi, hs_lo, n_x);
    {
        dim3 grid(DMODEL / 256, TOKENS / 128);       // (4, 32)
        gemm_bf16x3<<<grid, 256, G2_SMEM>>>(hs_hi, hs_lo, wo_hi, wo_lo,
                                            out, TOKENS, DMODEL, DMODEL);
    }
}

// round 7
// speedup vs baseline: 4.3492x; 1.4585x over previous
#include <cuda_runtime.h>
#include <cuda_fp16.h>
#include <cstdint>
#include <math.h>

// Problem constants (fixed by the reference)
#define BATCH   2
#define SEQ     2048
#define DMODEL  1024
#define NH      16
#define HD      64
#define TOKENS  (BATCH*SEQ)          // 4096
#define NHEADS_TOTAL (BATCH*NH)      // 32

// ---------------------------------------------------------------------------
// Scratch (__device__ globals; allocation in kernel_launch is forbidden)
// ---------------------------------------------------------------------------
__device__ float g_qkv[(size_t)TOKENS * 3 * DMODEL];  // [4096, 3072]
__device__ float g_h  [(size_t)TOKENS * DMODEL];      // [4096, 1024]

__device__ __half g_xs_hi[(size_t)TOKENS * DMODEL];
__device__ __half g_xs_lo[(size_t)TOKENS * DMODEL];
__device__ __half g_wq  [(size_t)3 * DMODEL * DMODEL];   // rounded fp16
__device__ __half g_wo  [(size_t)DMODEL * DMODEL];       // rounded fp16
__device__ __half g_hs_hi[(size_t)TOKENS * DMODEL];
__device__ __half g_hs_lo[(size_t)TOKENS * DMODEL];

// Per-head attention operands
// Q hi/lo: [head][s][64]; K single: [head][s][64]; VT single: [head][64][s]
#define HEADELEMS ((size_t)NHEADS_TOTAL * SEQ * HD)
__device__ __half g_q_hi[HEADELEMS];
__device__ __half g_q_lo[HEADELEMS];
__device__ __half g_k  [HEADELEMS];
__device__ __half g_vt [HEADELEMS];

// ---------------------------------------------------------------------------
// PTX helpers (sm_80-era instructions only — compute_100-safe)
// ---------------------------------------------------------------------------
__device__ __forceinline__ uint32_t smem_u32(const void* p) {
    uint32_t a;
    asm("{ .reg .u64 t; cvta.to.shared.u64 t, %1; cvt.u32.u64 %0, t; }"
        : "=r"(a) : "l"(p));
    return a;
}

#define CP_ASYNC16(dst, src) \
    asm volatile("cp.async.cg.shared.global [%0], [%1], 16;" \
                 :: "r"(dst), "l"(src) : "memory")
#define CP_COMMIT() asm volatile("cp.async.commit_group;" ::: "memory")
#define CP_WAIT(N)  asm volatile("cp.async.wait_group %0;" :: "n"(N) : "memory")

__device__ __forceinline__ void ldsm_x4(uint32_t& r0, uint32_t& r1,
                                        uint32_t& r2, uint32_t& r3, uint32_t addr) {
    asm volatile("ldmatrix.sync.aligned.m8n8.x4.shared.b16 {%0,%1,%2,%3}, [%4];"
                 : "=r"(r0), "=r"(r1), "=r"(r2), "=r"(r3) : "r"(addr));
}

__device__ __forceinline__ void mma16816(float* c, uint32_t a0, uint32_t a1,
                                         uint32_t a2, uint32_t a3,
                                         uint32_t b0, uint32_t b1) {
    asm volatile(
        "mma.sync.aligned.m16n8k16.row.col.f32.f16.f16.f32 "
        "{%0,%1,%2,%3}, {%4,%5,%6,%7}, {%8,%9}, {%0,%1,%2,%3};"
        : "+f"(c[0]), "+f"(c[1]), "+f"(c[2]), "+f"(c[3])
        : "r"(a0), "r"(a1), "r"(a2), "r"(a3), "r"(b0), "r"(b1));
}

__device__ __forceinline__ uint32_t pack_half2(float a, float b) {
    __half2 h2 = __floats2half2_rn(a, b);
    return *(uint32_t*)&h2;
}

// ---------------------------------------------------------------------------
// split_fp16: fp32 -> fp16 hi + fp16 lo (exact residual). n multiple of 2048.
// ---------------------------------------------------------------------------
__global__ __launch_bounds__(256) void split_fp16(const float* __restrict__ in,
                                                  __half* __restrict__ hi,
                                                  __half* __restrict__ lo,
                                                  int n) {
    int base = (blockIdx.x * 256 + threadIdx.x) * 8;
    if (base >= n) return;
    float4 f0 = *(const float4*)(in + base);
    float4 f1 = *(const float4*)(in + base + 4);
    float f[8] = {f0.x, f0.y, f0.z, f0.w, f1.x, f1.y, f1.z, f1.w};
    uint32_t h[4], l[4];
    #pragma unroll
    for (int j = 0; j < 4; ++j) {
        __half2 h2 = __floats2half2_rn(f[2*j], f[2*j+1]);
        float2 hf = __half22float2(h2);
        __half2 l2 = __floats2half2_rn(f[2*j] - hf.x, f[2*j+1] - hf.y);
        h[j] = *(uint32_t*)&h2;
        l[j] = *(uint32_t*)&l2;
    }
    *(uint4*)(hi + base) = make_uint4(h[0], h[1], h[2], h[3]);
    *(uint4*)(lo + base) = make_uint4(l[0], l[1], l[2], l[3]);
}

// round_fp16: fp32 -> fp16 (single rounding). n multiple of 2048.
__global__ __launch_bounds__(256) void round_fp16(const float* __restrict__ in,
                                                  __half* __restrict__ out, int n) {
    int base = (blockIdx.x * 256 + threadIdx.x) * 8;
    if (base >= n) return;
    float4 f0 = *(const float4*)(in + base);
    float4 f1 = *(const float4*)(in + base + 4);
    __half2 a = __floats2half2_rn(f0.x, f0.y);
    __half2 b = __floats2half2_rn(f0.z, f0.w);
    __half2 c = __floats2half2_rn(f1.x, f1.y);
    __half2 d = __floats2half2_rn(f1.z, f1.w);
    *(uint4*)(out + base) = make_uint4(*(uint32_t*)&a, *(uint32_t*)&b,
                                       *(uint32_t*)&c, *(uint32_t*)&d);
}

// ---------------------------------------------------------------------------
// split_qkv: g_qkv [4096,3072] fp32 -> Q hi/lo (scaled), K single, VT single.
// Grid (SEQ/64, NH, BATCH), 256 threads.
// ---------------------------------------------------------------------------
__global__ __launch_bounds__(256, 4) void split_qkv(
    __half* __restrict__ qhi, __half* __restrict__ qlo,
    __half* __restrict__ kk,  __half* __restrict__ vt) {
    __shared__ __half vt_s[64][72];

    const int tid = threadIdx.x;
    const int s0  = blockIdx.x * 64;
    const int h   = blockIdx.y;
    const int b   = blockIdx.z;
    const int head = b * NH + h;

    #pragma unroll
    for (int it = 0; it < 2; ++it) {
        int unit = it * 256 + tid;       // 0..511
        int sl   = unit >> 3;            // 0..63
        int d0   = (unit & 7) * 8;
        int s    = s0 + sl;
        const float* base = g_qkv + ((size_t)(b * SEQ + s)) * (3 * DMODEL) + h * HD + d0;
        size_t qkidx = ((size_t)head * SEQ + s) * HD + d0;

        // ---- Q (scaled, hi/lo split) ----
        {
            float4 f0 = *(const float4*)(base);
            float4 f1 = *(const float4*)(base + 4);
            float f[8] = {f0.x, f0.y, f0.z, f0.w, f1.x, f1.y, f1.z, f1.w};
            uint32_t hh[4], ll[4];
            #pragma unroll
            for (int j = 0; j < 4; ++j) {
                float a = f[2*j] * 0.125f, c = f[2*j+1] * 0.125f;
                __half2 h2 = __floats2half2_rn(a, c);
                float2 hf = __half22float2(h2);
                __half2 l2 = __floats2half2_rn(a - hf.x, c - hf.y);
                hh[j] = *(uint32_t*)&h2;
                ll[j] = *(uint32_t*)&l2;
            }
            *(uint4*)(qhi + qkidx) = make_uint4(hh[0], hh[1], hh[2], hh[3]);
            *(uint4*)(qlo + qkidx) = make_uint4(ll[0], ll[1], ll[2], ll[3]);
        }
        // ---- K (single rounding) ----
        {
            float4 f0 = *(const float4*)(base + DMODEL);
            float4 f1 = *(const float4*)(base + DMODEL + 4);
            __half2 a = __floats2half2_rn(f0.x, f0.y);
            __half2 b2 = __floats2half2_rn(f0.z, f0.w);
            __half2 c = __floats2half2_rn(f1.x, f1.y);
            __half2 d = __floats2half2_rn(f1.z, f1.w);
            *(uint4*)(kk + qkidx) = make_uint4(*(uint32_t*)&a, *(uint32_t*)&b2,
                                               *(uint32_t*)&c, *(uint32_t*)&d);
        }
        // ---- V -> smem transpose (single rounding) ----
        {
            float4 f0 = *(const float4*)(base + 2 * DMODEL);
            float4 f1 = *(const float4*)(base + 2 * DMODEL + 4);
            float f[8] = {f0.x, f0.y, f0.z, f0.w, f1.x, f1.y, f1.z, f1.w};
            #pragma unroll
            for (int j = 0; j < 8; ++j)
                vt_s[d0 + j][sl] = __float2half_rn(f[j]);
        }
    }
    __syncthreads();

    // Write VT rows: 64 rows x 8 uint4 = 512 -> 2/thread
    #pragma unroll
    for (int it = 0; it < 2; ++it) {
        int idx = it * 256 + tid;        // 0..511
        int r   = idx >> 3;
        int c   = (idx & 7) * 8;
        uint4 v = *(uint4*)&vt_s[r][c];
        *(uint4*)(vt + ((size_t)head * HD + r) * SEQ + s0 + c) = v;
    }
}

// ---------------------------------------------------------------------------
// fp16x2 warp-MMA GEMM: C[M,N] = (Ahi+Alo)[M,K] @ B[N,K]^T  (B pre-rounded)
// CTA tile 128x256, warp tile 64x64 (8 warps), K-chunk 32, 4-stage pipeline.
// ---------------------------------------------------------------------------
#define ROWB 80                         // 32 fp16 (64B) + 16B pad
#define G3_AT (128 * ROWB)              // 10240 per A tile
#define G3_BT (256 * ROWB)              // 20480 B tile (single)
#define G3_STAGE (2 * G3_AT + G3_BT)    // 40960
#define G3_SMEM (4 * G3_STAGE)          // 163840

__device__ __forceinline__ void g3_issue(
    uint32_t stage, const __half* __restrict__ Ahi,
    const __half* __restrict__ Alo, const __half* __restrict__ B,
    int kc, int K, int tid) {
    // A hi/lo: 2 x 128 rows x 4 chunks = 1024 cp -> 4/thread
    #pragma unroll
    for (int i = 0; i < 4; ++i) {
        int idx  = i * 256 + tid;        // 0..1023
        int prec = idx >> 9;
        int rem  = idx & 511;
        int row  = rem >> 2;
        int c    = rem & 3;
        const __half* src = (prec ? Alo : Ahi) + (size_t)row * K + kc * 32 + c * 8;
        CP_ASYNC16(stage + prec * G3_AT + row * ROWB + c * 16, src);
    }
    // B: 256 rows x 4 chunks = 1024 cp -> 4/thread
    #pragma unroll
    for (int i = 0; i < 4; ++i) {
        int idx  = i * 256 + tid;        // 0..1023
        int row  = idx >> 2;
        int c    = idx & 3;
        const __half* src = B + (size_t)row * K + kc * 32 + c * 8;
        CP_ASYNC16(stage + 2 * G3_AT + row * ROWB + c * 16, src);
    }
}

__global__ __launch_bounds__(256, 1) void gemm_fp16x2(
    const __half* __restrict__ Ahi, const __half* __restrict__ Alo,
    const __half* __restrict__ B, float* __restrict__ C,
    int M, int N, int K) {
    extern __shared__ char smem[];
    const uint32_t sb = smem_u32(smem);

    const int tid = threadIdx.x;
    const int wid = tid >> 5;
    const int lid = tid & 31;
    const int wm  = wid & 1;       // 0..1 -> 64 rows
    const int wn  = wid >> 1;      // 0..3 -> 64 cols

    const int brow = blockIdx.y;
    const int bcol = blockIdx.x;

    const __half* Ah = Ahi + (size_t)brow * 128 * K;
    const __half* Al = Alo + (size_t)brow * 128 * K;
    const __half* Bb = B   + (size_t)bcol * 256 * K;

    const uint32_t offA = (((lid >> 3) & 1) * 8 + (lid & 7)) * ROWB + (lid >> 4) * 16;
    const uint32_t offB = ((lid >> 4) * 8 + (lid & 7)) * ROWB + ((lid >> 3) & 1) * 16;

    float acc[4][8][4];
    #pragma unroll
    for (int i = 0; i < 4; ++i)
        #pragma unroll
        for (int j = 0; j < 8; ++j)
            #pragma unroll
            for (int e = 0; e < 4; ++e) acc[i][j][e] = 0.f;

    const int nch = K / 32;      // 32
    g3_issue(sb + 0 * G3_STAGE, Ah, Al, Bb, 0, K, tid); CP_COMMIT();
    g3_issue(sb + 1 * G3_STAGE, Ah, Al, Bb, 1, K, tid); CP_COMMIT();
    g3_issue(sb + 2 * G3_STAGE, Ah, Al, Bb, 2, K, tid); CP_COMMIT();

    for (int kc = 0; kc < nch; ++kc) {
        int rem = nch - kc;
        if (rem >= 3)      { CP_WAIT(2); }
        else if (rem == 2) { CP_WAIT(1); }
        else               { CP_WAIT(0); }
        __syncthreads();

        const uint32_t cur  = sb + (kc & 3) * G3_STAGE;
        const uint32_t aHiB = cur + wm * 64 * ROWB + offA;
        const uint32_t aLoB = cur + G3_AT + wm * 64 * ROWB + offA;
        const uint32_t bB   = cur + 2 * G3_AT + wn * 64 * ROWB + offB;

        #pragma unroll
        for (int k16 = 0; k16 < 2; ++k16) {
            const uint32_t ko = k16 * 32;

            uint32_t bf[16];
            #pragma unroll
            for (int nb = 0; nb < 4; ++nb)
                ldsm_x4(bf[nb*4], bf[nb*4+1], bf[nb*4+2], bf[nb*4+3],
                        bB + nb * 16 * ROWB + ko);

            #pragma unroll
            for (int mt = 0; mt < 4; ++mt) {
                uint32_t ah[4], al[4];
                ldsm_x4(ah[0], ah[1], ah[2], ah[3], aHiB + mt * 16 * ROWB + ko);
                ldsm_x4(al[0], al[1], al[2], al[3], aLoB + mt * 16 * ROWB + ko);
                #pragma unroll
                for (int nt = 0; nt < 8; ++nt) {
                    mma16816(acc[mt][nt], ah[0], ah[1], ah[2], ah[3],
                             bf[nt * 2], bf[nt * 2 + 1]);
                    mma16816(acc[mt][nt], al[0], al[1], al[2], al[3],
                             bf[nt * 2], bf[nt * 2 + 1]);
                }
            }
        }

        if (kc + 3 < nch) {
            g3_issue(sb + ((kc + 3) & 3) * G3_STAGE, Ah, Al, Bb, kc + 3, K, tid);
            CP_COMMIT();
        }
    }

    // Epilogue
    const int r0 = brow * 128 + wm * 64 + (lid >> 2);
    const int c0 = bcol * 256 + wn * 64 + (lid & 3) * 2;
    #pragma unroll
    for (int mt = 0; mt < 4; ++mt) {
        #pragma unroll
        for (int nt = 0; nt < 8; ++nt) {
            float* p = C + (size_t)(r0 + mt * 16) * N + c0 + nt * 8;
            *(float2*)p                   = make_float2(acc[mt][nt][0], acc[mt][nt][1]);
            *(float2*)(p + (size_t)8 * N) = make_float2(acc[mt][nt][2], acc[mt][nt][3]);
        }
    }
}

// ---------------------------------------------------------------------------
// HMMA flash attention (fp16x2), causal, double-buffered K/VT (single-prec
// K and V tiles; Q and P split hi/lo on the A side).
// ---------------------------------------------------------------------------
#define AROWB 144
#define SQ_HI   0
#define SQ_LO   18432
#define SK_BASE 36864
#define KVSTAGE 18432              // K(9216) + VT(9216)
#define ATT_SMEM (SK_BASE + 2 * KVSTAGE)   // 73728
#define NEG_BIG (-1e30f)

__device__ __forceinline__ void att_issue_kv(
    uint32_t kvbase, const __half* __restrict__ Kk,
    const __half* __restrict__ Vt, int jt, int tid) {
    // K 64x64 + VT 64x64 = 1024 cp -> 4/thread
    #pragma unroll
    for (int it = 0; it < 4; ++it) {
        int idx = it * 256 + tid;     // 0..1023
        int buf = idx >> 9;           // 0:K 1:VT
        int rem = idx & 511;
        int r   = rem >> 3;
        int c8  = rem & 7;
        const __half* src = buf ? (Vt + (size_t)r * SEQ + jt * 64 + c8 * 8)
                                : (Kk + (size_t)(jt * 64 + r) * HD + c8 * 8);
        CP_ASYNC16(kvbase + buf * 9216 + r * AROWB + c8 * 16, src);
    }
}

__global__ __launch_bounds__(256, 2) void attn_mma(float* __restrict__ hout) {
    extern __shared__ char smem[];
    const uint32_t sb = smem_u32(smem);

    const int tid = threadIdx.x;
    const int w   = tid >> 5;
    const int lid = tid & 31;
    const int qi  = gridDim.x - 1 - blockIdx.x;   // big tiles first
    const int h   = blockIdx.y;
    const int b   = blockIdx.z;
    const int head = b * NH + h;
    const int qbase = qi * 128;

    const __half* Qh = g_q_hi + ((size_t)head * SEQ + qbase) * HD;
    const __half* Ql = g_q_lo + ((size_t)head * SEQ + qbase) * HD;
    const __half* Kk = g_k  + (size_t)head * SEQ * HD;
    const __half* Vt = g_vt + (size_t)head * HD * SEQ;

    // Stage Q (hi+lo): 2 x 128 x 8 = 2048 cp -> 8/thread
    #pragma unroll
    for (int it = 0; it < 8; ++it) {
        int idx  = it * 256 + tid;
        int prec = idx >> 10;
        int rem  = idx & 1023;
        int r    = rem >> 3;
        int c8   = rem & 7;
        const __half* src = (prec ? Ql : Qh) + (size_t)r * HD + c8 * 8;
        CP_ASYNC16(sb + (prec ? SQ_LO : SQ_HI) + r * AROWB + c8 * 16, src);
    }
    CP_COMMIT();

    const int ntiles = 2 * qi + 2;     // >= 2 always
    att_issue_kv(sb + SK_BASE + 0 * KVSTAGE, Kk, Vt, 0, tid);
    CP_COMMIT();
    att_issue_kv(sb + SK_BASE + 1 * KVSTAGE, Kk, Vt, 1, tid);
    CP_COMMIT();

    const uint32_t offA = (((lid >> 3) & 1) * 8 + (lid & 7)) * AROWB + (lid >> 4) * 16;
    const uint32_t offB = ((lid >> 4) * 8 + (lid & 7)) * AROWB + ((lid >> 3) & 1) * 16;
    const uint32_t qA_hi = sb + SQ_HI + w * 16 * AROWB + offA;
    const uint32_t qA_lo = sb + SQ_LO + w * 16 * AROWB + offA;

    float o[8][4];
    #pragma unroll
    for (int nt = 0; nt < 8; ++nt)
        #pragma unroll
        for (int e = 0; e < 4; ++e) o[nt][e] = 0.f;
    float m_i[2] = {NEG_BIG, NEG_BIG};
    float l_i[2] = {0.f, 0.f};

    for (int jt = 0; jt < ntiles; ++jt) {
        if (jt < ntiles - 1) { CP_WAIT(1); } else { CP_WAIT(0); }
        __syncthreads();

        const uint32_t kvb = sb + SK_BASE + (jt & 1) * KVSTAGE;

        // ---- S = Q @ K^T (fp16x2) ----
        float s[8][4];
        #pragma unroll
        for (int nt = 0; nt < 8; ++nt)
            #pragma unroll
            for (int e = 0; e < 4; ++e) s[nt][e] = 0.f;

        #pragma unroll
        for (int kc = 0; kc < 4; ++kc) {
            const uint32_t ko = kc * 32;
            uint32_t ah[4], al[4];
            ldsm_x4(ah[0], ah[1], ah[2], ah[3], qA_hi + ko);
            ldsm_x4(al[0], al[1], al[2], al[3], qA_lo + ko);
            #pragma unroll
            for (int p = 0; p < 4; ++p) {
                uint32_t bk[4];
                ldsm_x4(bk[0], bk[1], bk[2], bk[3],
                        kvb + p * 16 * AROWB + offB + ko);
                #pragma unroll
                for (int half = 0; half < 2; ++half) {
                    int nt = p * 2 + half;
                    mma16816(s[nt], ah[0], ah[1], ah[2], ah[3],
                             bk[half * 2], bk[half * 2 + 1]);
                    mma16816(s[nt], al[0], al[1], al[2], al[3],
                             bk[half * 2], bk[half * 2 + 1]);
                }
            }
        }

        // ---- causal mask (diagonal tiles only) ----
        if (jt >= 2 * qi) {
            #pragma unroll
            for (int i = 0; i < 2; ++i) {
                int qg = qbase + w * 16 + (lid >> 2) + i * 8;
                #pragma unroll
                for (int nt = 0; nt < 8; ++nt) {
                    int kg = jt * 64 + nt * 8 + (lid & 3) * 2;
                    if (kg > qg)     s[nt][2*i]     = NEG_BIG;
                    if (kg + 1 > qg) s[nt][2*i + 1] = NEG_BIG;
                }
            }
        }

        // ---- online softmax (quad reductions) ----
        #pragma unroll
        for (int i = 0; i < 2; ++i) {
            float rm = NEG_BIG;
            #pragma unroll
            for (int nt = 0; nt < 8; ++nt)
                rm = fmaxf(rm, fmaxf(s[nt][2*i], s[nt][2*i+1]));
            rm = fmaxf(rm, __shfl_xor_sync(0xffffffffu, rm, 1));
            rm = fmaxf(rm, __shfl_xor_sync(0xffffffffu, rm, 2));
            float mnew = fmaxf(m_i[i], rm);
            float corr = __expf(m_i[i] - mnew);
            float rs = 0.f;
            #pragma unroll
            for (int nt = 0; nt < 8; ++nt) {
                float p0 = __expf(s[nt][2*i]     - mnew);
                float p1 = __expf(s[nt][2*i + 1] - mnew);
                s[nt][2*i] = p0; s[nt][2*i+1] = p1;
                rs += p0 + p1;
            }
            rs += __shfl_xor_sync(0xffffffffu, rs, 1);
            rs += __shfl_xor_sync(0xffffffffu, rs, 2);
            l_i[i] = l_i[i] * corr + rs;
            m_i[i] = mnew;
            #pragma unroll
            for (int nt = 0; nt < 8; ++nt) {
                o[nt][2*i]     *= corr;
                o[nt][2*i + 1] *= corr;
            }
        }

        // ---- O += P @ V (fp16x2; P hi/lo from registers, V single) ----
        #pragma unroll
        for (int kc = 0; kc < 4; ++kc) {
            uint32_t ph[4], pl[4];
            {
                float c0 = s[2*kc][0],   c1 = s[2*kc][1];
                float c2 = s[2*kc][2],   c3 = s[2*kc][3];
                float d0 = s[2*kc+1][0], d1 = s[2*kc+1][1];
                float d2 = s[2*kc+1][2], d3 = s[2*kc+1][3];
                ph[0] = pack_half2(c0, c1);
                ph[1] = pack_half2(c2, c3);
                ph[2] = pack_half2(d0, d1);
                ph[3] = pack_half2(d2, d3);
                __half2* hp = (__half2*)ph;
                float2 h0 = __half22float2(hp[0]);
                float2 h1 = __half22float2(hp[1]);
                float2 h2 = __half22float2(hp[2]);
                float2 h3 = __half22float2(hp[3]);
                pl[0] = pack_half2(c0 - h0.x, c1 - h0.y);
                pl[1] = pack_half2(c2 - h1.x, c3 - h1.y);
                pl[2] = pack_half2(d0 - h2.x, d1 - h2.y);
                pl[3] = pack_half2(d2 - h3.x, d3 - h3.y);
            }
            const uint32_t ko = kc * 32;
            #pragma unroll
            for (int p = 0; p < 4; ++p) {
                uint32_t vf[4];
                ldsm_x4(vf[0], vf[1], vf[2], vf[3],
                        kvb + 9216 + p * 16 * AROWB + offB + ko);
                #pragma unroll
                for (int half = 0; half < 2; ++half) {
                    int nt = p * 2 + half;
                    mma16816(o[nt], ph[0], ph[1], ph[2], ph[3],
                             vf[half * 2], vf[half * 2 + 1]);
                    mma16816(o[nt], pl[0], pl[1], pl[2], pl[3],
                             vf[half * 2], vf[half * 2 + 1]);
                }
            }
        }

        __syncthreads();   // all warps done reading buffer (jt&1)
        if (jt + 2 < ntiles) {
            att_issue_kv(sb + SK_BASE + (jt & 1) * KVSTAGE, Kk, Vt, jt + 2, tid);
            CP_COMMIT();
        }
    }

    // ---- epilogue: normalize, write h [b][s][dmodel] ----
    #pragma unroll
    for (int i = 0; i < 2; ++i) {
        float inv = 1.f / l_i[i];
        int q = qbase + w * 16 + (lid >> 2) + i * 8;
        float* op = hout + ((size_t)b * SEQ + q) * DMODEL + h * HD;
        #pragma unroll
        for (int nt = 0; nt < 8; ++nt) {
            int d = nt * 8 + (lid & 3) * 2;
            *(float2*)(op + d) = make_float2(o[nt][2*i] * inv, o[nt][2*i+1] * inv);
        }
    }
}

// ---------------------------------------------------------------------------
// Launch
// ---------------------------------------------------------------------------
extern "C" void kernel_launch(void* const* d_in, const int* in_sizes, int n_in,
                              void* d_out, int out_size) {
    const float* x    = (const float*)d_in[0];  // [2,2048,1024]
    const float* Wqkv = (const float*)d_in[1];  // [3072,1024]
    const float* Wo   = (const float*)d_in[2];  // [1024,1024]
    float* out = (float*)d_out;                 // [2,2048,1024]

    float *qkv_ptr = nullptr, *h_ptr = nullptr;
    cudaGetSymbolAddress((void**)&qkv_ptr, g_qkv);
    cudaGetSymbolAddress((void**)&h_ptr,   g_h);
    __half *xs_hi, *xs_lo, *wq, *wo, *hs_hi, *hs_lo, *q_hi, *q_lo, *kk, *vt;
    cudaGetSymbolAddress((void**)&xs_hi, g_xs_hi);
    cudaGetSymbolAddress((void**)&xs_lo, g_xs_lo);
    cudaGetSymbolAddress((void**)&wq,    g_wq);
    cudaGetSymbolAddress((void**)&wo,    g_wo);
    cudaGetSymbolAddress((void**)&hs_hi, g_hs_hi);
    cudaGetSymbolAddress((void**)&hs_lo, g_hs_lo);
    cudaGetSymbolAddress((void**)&q_hi,  g_q_hi);
    cudaGetSymbolAddress((void**)&q_lo,  g_q_lo);
    cudaGetSymbolAddress((void**)&kk,    g_k);
    cudaGetSymbolAddress((void**)&vt,    g_vt);

    static bool attr_done = false;
    if (!attr_done) {
        cudaFuncSetAttribute(gemm_fp16x2,
                             cudaFuncAttributeMaxDynamicSharedMemorySize, G3_SMEM);
        cudaFuncSetAttribute(attn_mma,
                             cudaFuncAttributeMaxDynamicSharedMemorySize, ATT_SMEM);
        attr_done = true;
    }

    const int n_x  = TOKENS * DMODEL;
    const int n_wq = 3 * DMODEL * DMODEL;
    const int n_wo = DMODEL * DMODEL;

    // Pre-split / round operands
    split_fp16<<<n_x  / 2048, 256>>>(x, xs_hi, xs_lo, n_x);
    round_fp16<<<n_wq / 2048, 256>>>(Wqkv, wq, n_wq);
    round_fp16<<<n_wo / 2048, 256>>>(Wo, wo, n_wo);

    // 1) QKV projection: [4096,1024] @ [3072,1024]^T
    {
        dim3 grid(3 * DMODEL / 256, TOKENS / 128);   // (12, 32)
        gemm_fp16x2<<<grid, 256, G3_SMEM>>>(xs_hi, xs_lo, wq, qkv_ptr,
                                            TOKENS, 3 * DMODEL, DMODEL);
    }
    // 1b) Split qkv into per-head operands
    {
        dim3 grid(SEQ / 64, NH, BATCH);
        split_qkv<<<grid, 256>>>(q_hi, q_lo, kk, vt);
    }
    // 2) HMMA causal flash attention -> g_h
    {
        dim3 grid(SEQ / 128, NH, BATCH);
        attn_mma<<<grid, 256, ATT_SMEM>>>(h_ptr);
    }
    // 3) Output projection: [4096,1024] @ [1024,1024]^T
    split_fp16<<<n_x / 2048, 256>>>(h_ptr, hs_hi, hs_lo, n_x);
    {
        dim3 grid(DMODEL / 256, TOKENS / 128);       // (4, 32)
        gemm_fp16x2<<<grid, 256, G3_SMEM>>>(hs_hi, hs_lo, wo, out,
                                            TOKENS, DMODEL, DMODEL);
    }
}

// round 8
// speedup vs baseline: 4.4566x; 1.0247x over previous
#include <cuda_runtime.h>
#include <cuda_fp16.h>
#include <cstdint>
#include <math.h>

// Problem constants (fixed by the reference)
#define BATCH   2
#define SEQ     2048
#define DMODEL  1024
#define NH      16
#define HD      64
#define TOKENS  (BATCH*SEQ)          // 4096
#define NHEADS_TOTAL (BATCH*NH)      // 32

// ---------------------------------------------------------------------------
// Scratch (__device__ globals; allocation in kernel_launch is forbidden)
// ---------------------------------------------------------------------------
__device__ __half g_xs_hi[(size_t)TOKENS * DMODEL];
__device__ __half g_xs_lo[(size_t)TOKENS * DMODEL];
__device__ __half g_wq  [(size_t)3 * DMODEL * DMODEL];   // rounded fp16
__device__ __half g_wo  [(size_t)DMODEL * DMODEL];       // rounded fp16
__device__ __half g_hs_hi[(size_t)TOKENS * DMODEL];
__device__ __half g_hs_lo[(size_t)TOKENS * DMODEL];

// Per-head attention operands, all [head][s][64] natural layout
#define HEADELEMS ((size_t)NHEADS_TOTAL * SEQ * HD)
__device__ __half g_q_hi[HEADELEMS];
__device__ __half g_q_lo[HEADELEMS];
__device__ __half g_k  [HEADELEMS];
__device__ __half g_v  [HEADELEMS];

// ---------------------------------------------------------------------------
// PTX helpers (sm_80-era instructions only — compute_100-safe)
// ---------------------------------------------------------------------------
__device__ __forceinline__ uint32_t smem_u32(const void* p) {
    uint32_t a;
    asm("{ .reg .u64 t; cvta.to.shared.u64 t, %1; cvt.u32.u64 %0, t; }"
        : "=r"(a) : "l"(p));
    return a;
}

#define CP_ASYNC16(dst, src) \
    asm volatile("cp.async.cg.shared.global [%0], [%1], 16;" \
                 :: "r"(dst), "l"(src) : "memory")
#define CP_COMMIT() asm volatile("cp.async.commit_group;" ::: "memory")
#define CP_WAIT(N)  asm volatile("cp.async.wait_group %0;" :: "n"(N) : "memory")

__device__ __forceinline__ void ldsm_x4(uint32_t& r0, uint32_t& r1,
                                        uint32_t& r2, uint32_t& r3, uint32_t addr) {
    asm volatile("ldmatrix.sync.aligned.m8n8.x4.shared.b16 {%0,%1,%2,%3}, [%4];"
                 : "=r"(r0), "=r"(r1), "=r"(r2), "=r"(r3) : "r"(addr));
}

__device__ __forceinline__ void ldsm_x4_t(uint32_t& r0, uint32_t& r1,
                                          uint32_t& r2, uint32_t& r3, uint32_t addr) {
    asm volatile("ldmatrix.sync.aligned.m8n8.x4.trans.shared.b16 {%0,%1,%2,%3}, [%4];"
                 : "=r"(r0), "=r"(r1), "=r"(r2), "=r"(r3) : "r"(addr));
}

__device__ __forceinline__ void mma16816(float* c, uint32_t a0, uint32_t a1,
                                         uint32_t a2, uint32_t a3,
                                         uint32_t b0, uint32_t b1) {
    asm volatile(
        "mma.sync.aligned.m16n8k16.row.col.f32.f16.f16.f32 "
        "{%0,%1,%2,%3}, {%4,%5,%6,%7}, {%8,%9}, {%0,%1,%2,%3};"
        : "+f"(c[0]), "+f"(c[1]), "+f"(c[2]), "+f"(c[3])
        : "r"(a0), "r"(a1), "r"(a2), "r"(a3), "r"(b0), "r"(b1));
}

__device__ __forceinline__ uint32_t pack_half2(float a, float b) {
    __half2 h2 = __floats2half2_rn(a, b);
    return *(uint32_t*)&h2;
}

// ---------------------------------------------------------------------------
// split_fp16: fp32 -> fp16 hi + fp16 lo (exact residual). n multiple of 2048.
// ---------------------------------------------------------------------------
__global__ __launch_bounds__(256) void split_fp16(const float* __restrict__ in,
                                                  __half* __restrict__ hi,
                                                  __half* __restrict__ lo,
                                                  int n) {
    int base = (blockIdx.x * 256 + threadIdx.x) * 8;
    if (base >= n) return;
    float4 f0 = *(const float4*)(in + base);
    float4 f1 = *(const float4*)(in + base + 4);
    float f[8] = {f0.x, f0.y, f0.z, f0.w, f1.x, f1.y, f1.z, f1.w};
    uint32_t h[4], l[4];
    #pragma unroll
    for (int j = 0; j < 4; ++j) {
        __half2 h2 = __floats2half2_rn(f[2*j], f[2*j+1]);
        float2 hf = __half22float2(h2);
        __half2 l2 = __floats2half2_rn(f[2*j] - hf.x, f[2*j+1] - hf.y);
        h[j] = *(uint32_t*)&h2;
        l[j] = *(uint32_t*)&l2;
    }
    *(uint4*)(hi + base) = make_uint4(h[0], h[1], h[2], h[3]);
    *(uint4*)(lo + base) = make_uint4(l[0], l[1], l[2], l[3]);
}

// round_fp16: fp32 -> fp16 (single rounding). n multiple of 2048.
__global__ __launch_bounds__(256) void round_fp16(const float* __restrict__ in,
                                                  __half* __restrict__ out, int n) {
    int base = (blockIdx.x * 256 + threadIdx.x) * 8;
    if (base >= n) return;
    float4 f0 = *(const float4*)(in + base);
    float4 f1 = *(const float4*)(in + base + 4);
    __half2 a = __floats2half2_rn(f0.x, f0.y);
    __half2 b = __floats2half2_rn(f0.z, f0.w);
    __half2 c = __floats2half2_rn(f1.x, f1.y);
    __half2 d = __floats2half2_rn(f1.z, f1.w);
    *(uint4*)(out + base) = make_uint4(*(uint32_t*)&a, *(uint32_t*)&b,
                                       *(uint32_t*)&c, *(uint32_t*)&d);
}

// ---------------------------------------------------------------------------
// fp16x2 warp-MMA GEMM: C = (Ahi+Alo)[M,K] @ B[N,K]^T  (B pre-rounded fp16)
// CTA tile 128x256, warp tile 64x64 (8 warps), K-chunk 32, 4-stage pipeline.
// MODE 0: plain fp32 C store.
// MODE 1: fused QKV epilogue — writes g_q_hi/g_q_lo (scaled+split), g_k, g_v
//         in [head][s][64] layout directly from accumulators.
// ---------------------------------------------------------------------------
#define ROWB 80                         // 32 fp16 (64B) + 16B pad
#define G3_AT (128 * ROWB)              // 10240 per A tile
#define G3_BT (256 * ROWB)              // 20480 B tile (single)
#define G3_STAGE (2 * G3_AT + G3_BT)    // 40960
#define G3_SMEM (4 * G3_STAGE)          // 163840

__device__ __forceinline__ void g3_issue(
    uint32_t stage, const __half* __restrict__ Ahi,
    const __half* __restrict__ Alo, const __half* __restrict__ B,
    int kc, int K, int tid) {
    #pragma unroll
    for (int i = 0; i < 4; ++i) {
        int idx  = i * 256 + tid;        // 0..1023
        int prec = idx >> 9;
        int rem  = idx & 511;
        int row  = rem >> 2;
        int c    = rem & 3;
        const __half* src = (prec ? Alo : Ahi) + (size_t)row * K + kc * 32 + c * 8;
        CP_ASYNC16(stage + prec * G3_AT + row * ROWB + c * 16, src);
    }
    #pragma unroll
    for (int i = 0; i < 4; ++i) {
        int idx  = i * 256 + tid;        // 0..1023
        int row  = idx >> 2;
        int c    = idx & 3;
        const __half* src = B + (size_t)row * K + kc * 32 + c * 8;
        CP_ASYNC16(stage + 2 * G3_AT + row * ROWB + c * 16, src);
    }
}

template<int MODE>
__global__ __launch_bounds__(256, 1) void gemm_fp16x2(
    const __half* __restrict__ Ahi, const __half* __restrict__ Alo,
    const __half* __restrict__ B, float* __restrict__ C,
    int M, int N, int K) {
    extern __shared__ char smem[];
    const uint32_t sb = smem_u32(smem);

    const int tid = threadIdx.x;
    const int wid = tid >> 5;
    const int lid = tid & 31;
    const int wm  = wid & 1;       // 0..1 -> 64 rows
    const int wn  = wid >> 1;      // 0..3 -> 64 cols

    const int brow = blockIdx.y;
    const int bcol = blockIdx.x;

    const __half* Ah = Ahi + (size_t)brow * 128 * K;
    const __half* Al = Alo + (size_t)brow * 128 * K;
    const __half* Bb = B   + (size_t)bcol * 256 * K;

    const uint32_t offA = (((lid >> 3) & 1) * 8 + (lid & 7)) * ROWB + (lid >> 4) * 16;
    const uint32_t offB = ((lid >> 4) * 8 + (lid & 7)) * ROWB + ((lid >> 3) & 1) * 16;

    float acc[4][8][4];
    #pragma unroll
    for (int i = 0; i < 4; ++i)
        #pragma unroll
        for (int j = 0; j < 8; ++j)
            #pragma unroll
            for (int e = 0; e < 4; ++e) acc[i][j][e] = 0.f;

    const int nch = K / 32;      // 32
    g3_issue(sb + 0 * G3_STAGE, Ah, Al, Bb, 0, K, tid); CP_COMMIT();
    g3_issue(sb + 1 * G3_STAGE, Ah, Al, Bb, 1, K, tid); CP_COMMIT();
    g3_issue(sb + 2 * G3_STAGE, Ah, Al, Bb, 2, K, tid); CP_COMMIT();

    for (int kc = 0; kc < nch; ++kc) {
        int rem = nch - kc;
        if (rem >= 3)      { CP_WAIT(2); }
        else if (rem == 2) { CP_WAIT(1); }
        else               { CP_WAIT(0); }
        __syncthreads();

        const uint32_t cur  = sb + (kc & 3) * G3_STAGE;
        const uint32_t aHiB = cur + wm * 64 * ROWB + offA;
        const uint32_t aLoB = cur + G3_AT + wm * 64 * ROWB + offA;
        const uint32_t bB   = cur + 2 * G3_AT + wn * 64 * ROWB + offB;

        #pragma unroll
        for (int k16 = 0; k16 < 2; ++k16) {
            const uint32_t ko = k16 * 32;

            uint32_t bf[16];
            #pragma unroll
            for (int nb = 0; nb < 4; ++nb)
                ldsm_x4(bf[nb*4], bf[nb*4+1], bf[nb*4+2], bf[nb*4+3],
                        bB + nb * 16 * ROWB + ko);

            #pragma unroll
            for (int mt = 0; mt < 4; ++mt) {
                uint32_t ah[4], al[4];
                ldsm_x4(ah[0], ah[1], ah[2], ah[3], aHiB + mt * 16 * ROWB + ko);
                ldsm_x4(al[0], al[1], al[2], al[3], aLoB + mt * 16 * ROWB + ko);
                #pragma unroll
                for (int nt = 0; nt < 8; ++nt) {
                    mma16816(acc[mt][nt], ah[0], ah[1], ah[2], ah[3],
                             bf[nt * 2], bf[nt * 2 + 1]);
                    mma16816(acc[mt][nt], al[0], al[1], al[2], al[3],
                             bf[nt * 2], bf[nt * 2 + 1]);
                }
            }
        }

        if (kc + 3 < nch) {
            g3_issue(sb + ((kc + 3) & 3) * G3_STAGE, Ah, Al, Bb, kc + 3, K, tid);
            CP_COMMIT();
        }
    }

    if (MODE == 0) {
        // Plain fp32 epilogue
        const int r0 = brow * 128 + wm * 64 + (lid >> 2);
        const int c0 = bcol * 256 + wn * 64 + (lid & 3) * 2;
        #pragma unroll
        for (int mt = 0; mt < 4; ++mt) {
            #pragma unroll
            for (int nt = 0; nt < 8; ++nt) {
                float* p = C + (size_t)(r0 + mt * 16) * N + c0 + nt * 8;
                *(float2*)p                   = make_float2(acc[mt][nt][0], acc[mt][nt][1]);
                *(float2*)(p + (size_t)8 * N) = make_float2(acc[mt][nt][2], acc[mt][nt][3]);
            }
        }
    } else {
        // Fused QKV epilogue. Each warp's 64-col block = exactly one head of
        // one section (Q/K/V). brow covers 128 tokens of one batch.
        const int section = bcol >> 2;                // 0=Q 1=K 2=V
        const int head16  = (bcol & 3) * 4 + wn;      // 0..15
        const int headg   = (brow >> 4) * NH + head16;
        const int s0      = ((brow * 128) & (SEQ - 1)) + wm * 64 + (lid >> 2);
        const int d0      = (lid & 3) * 2;
        #pragma unroll
        for (int mt = 0; mt < 4; ++mt) {
            #pragma unroll
            for (int nt = 0; nt < 8; ++nt) {
                int d = d0 + nt * 8;
                #pragma unroll
                for (int i = 0; i < 2; ++i) {
                    int s = s0 + mt * 16 + i * 8;
                    size_t idx = ((size_t)headg * SEQ + s) * HD + d;
                    float v0 = acc[mt][nt][2*i], v1 = acc[mt][nt][2*i+1];
                    if (section == 0) {
                        v0 *= 0.125f; v1 *= 0.125f;
                        __half2 hh = __floats2half2_rn(v0, v1);
                        float2 hf = __half22float2(hh);
                        __half2 ll = __floats2half2_rn(v0 - hf.x, v1 - hf.y);
                        *(__half2*)(g_q_hi + idx) = hh;
                        *(__half2*)(g_q_lo + idx) = ll;
                    } else if (section == 1) {
                        *(__half2*)(g_k + idx) = __floats2half2_rn(v0, v1);
                    } else {
                        *(__half2*)(g_v + idx) = __floats2half2_rn(v0, v1);
                    }
                }
            }
        }
    }
}

// ---------------------------------------------------------------------------
// HMMA flash attention (fp16x2), causal, double-buffered K/V.
// K and V both natural [s][64]; V's B-fragments come from ldmatrix.trans.
// Epilogue writes hs hi/lo fp16 directly (fused h-split).
// ---------------------------------------------------------------------------
#define AROWB 144
#define SQ_HI   0
#define SQ_LO   18432
#define SK_BASE 36864
#define KVSTAGE 18432              // K(9216) + V(9216)
#define ATT_SMEM (SK_BASE + 2 * KVSTAGE)   // 73728
#define NEG_BIG (-1e30f)

__device__ __forceinline__ void att_issue_kv(
    uint32_t kvbase, const __half* __restrict__ Kk,
    const __half* __restrict__ Vv, int jt, int tid) {
    #pragma unroll
    for (int it = 0; it < 4; ++it) {
        int idx = it * 256 + tid;     // 0..1023
        int buf = idx >> 9;           // 0:K 1:V
        int rem = idx & 511;
        int r   = rem >> 3;
        int c8  = rem & 7;
        const __half* src = (buf ? Vv : Kk) + (size_t)(jt * 64 + r) * HD + c8 * 8;
        CP_ASYNC16(kvbase + buf * 9216 + r * AROWB + c8 * 16, src);
    }
}

__global__ __launch_bounds__(256, 2) void attn_mma() {
    extern __shared__ char smem[];
    const uint32_t sb = smem_u32(smem);

    const int tid = threadIdx.x;
    const int w   = tid >> 5;
    const int lid = tid & 31;
    const int qi  = gridDim.x - 1 - blockIdx.x;   // big tiles first
    const int h   = blockIdx.y;
    const int b   = blockIdx.z;
    const int head = b * NH + h;
    const int qbase = qi * 128;

    const __half* Qh = g_q_hi + ((size_t)head * SEQ + qbase) * HD;
    const __half* Ql = g_q_lo + ((size_t)head * SEQ + qbase) * HD;
    const __half* Kk = g_k + (size_t)head * SEQ * HD;
    const __half* Vv = g_v + (size_t)head * SEQ * HD;

    // Stage Q (hi+lo)
    #pragma unroll
    for (int it = 0; it < 8; ++it) {
        int idx  = it * 256 + tid;
        int prec = idx >> 10;
        int rem  = idx & 1023;
        int r    = rem >> 3;
        int c8   = rem & 7;
        const __half* src = (prec ? Ql : Qh) + (size_t)r * HD + c8 * 8;
        CP_ASYNC16(sb + (prec ? SQ_LO : SQ_HI) + r * AROWB + c8 * 16, src);
    }
    CP_COMMIT();

    const int ntiles = 2 * qi + 2;     // >= 2 always
    att_issue_kv(sb + SK_BASE + 0 * KVSTAGE, Kk, Vv, 0, tid);
    CP_COMMIT();
    att_issue_kv(sb + SK_BASE + 1 * KVSTAGE, Kk, Vv, 1, tid);
    CP_COMMIT();

    const uint32_t offA = (((lid >> 3) & 1) * 8 + (lid & 7)) * AROWB + (lid >> 4) * 16;
    const uint32_t offB = ((lid >> 4) * 8 + (lid & 7)) * AROWB + ((lid >> 3) & 1) * 16;
    const uint32_t qA_hi = sb + SQ_HI + w * 16 * AROWB + offA;
    const uint32_t qA_lo = sb + SQ_LO + w * 16 * AROWB + offA;

    float o[8][4];
    #pragma unroll
    for (int nt = 0; nt < 8; ++nt)
        #pragma unroll
        for (int e = 0; e < 4; ++e) o[nt][e] = 0.f;
    float m_i[2] = {NEG_BIG, NEG_BIG};
    float l_i[2] = {0.f, 0.f};

    for (int jt = 0; jt < ntiles; ++jt) {
        if (jt < ntiles - 1) { CP_WAIT(1); } else { CP_WAIT(0); }
        __syncthreads();

        const uint32_t kvb = sb + SK_BASE + (jt & 1) * KVSTAGE;

        // ---- S = Q @ K^T (fp16x2) ----
        float s[8][4];
        #pragma unroll
        for (int nt = 0; nt < 8; ++nt)
            #pragma unroll
            for (int e = 0; e < 4; ++e) s[nt][e] = 0.f;

        #pragma unroll
        for (int kc = 0; kc < 4; ++kc) {
            const uint32_t ko = kc * 32;
            uint32_t ah[4], al[4];
            ldsm_x4(ah[0], ah[1], ah[2], ah[3], qA_hi + ko);
            ldsm_x4(al[0], al[1], al[2], al[3], qA_lo + ko);
            #pragma unroll
            for (int p = 0; p < 4; ++p) {
                uint32_t bk[4];
                ldsm_x4(bk[0], bk[1], bk[2], bk[3],
                        kvb + p * 16 * AROWB + offB + ko);
                #pragma unroll
                for (int half = 0; half < 2; ++half) {
                    int nt = p * 2 + half;
                    mma16816(s[nt], ah[0], ah[1], ah[2], ah[3],
                             bk[half * 2], bk[half * 2 + 1]);
                    mma16816(s[nt], al[0], al[1], al[2], al[3],
                             bk[half * 2], bk[half * 2 + 1]);
                }
            }
        }

        // ---- causal mask (diagonal tiles only) ----
        if (jt >= 2 * qi) {
            #pragma unroll
            for (int i = 0; i < 2; ++i) {
                int qg = qbase + w * 16 + (lid >> 2) + i * 8;
                #pragma unroll
                for (int nt = 0; nt < 8; ++nt) {
                    int kg = jt * 64 + nt * 8 + (lid & 3) * 2;
                    if (kg > qg)     s[nt][2*i]     = NEG_BIG;
                    if (kg + 1 > qg) s[nt][2*i + 1] = NEG_BIG;
                }
            }
        }

        // ---- online softmax (quad reductions) ----
        #pragma unroll
        for (int i = 0; i < 2; ++i) {
            float rm = NEG_BIG;
            #pragma unroll
            for (int nt = 0; nt < 8; ++nt)
                rm = fmaxf(rm, fmaxf(s[nt][2*i], s[nt][2*i+1]));
            rm = fmaxf(rm, __shfl_xor_sync(0xffffffffu, rm, 1));
            rm = fmaxf(rm, __shfl_xor_sync(0xffffffffu, rm, 2));
            float mnew = fmaxf(m_i[i], rm);
            float corr = __expf(m_i[i] - mnew);
            float rs = 0.f;
            #pragma unroll
            for (int nt = 0; nt < 8; ++nt) {
                float p0 = __expf(s[nt][2*i]     - mnew);
                float p1 = __expf(s[nt][2*i + 1] - mnew);
                s[nt][2*i] = p0; s[nt][2*i+1] = p1;
                rs += p0 + p1;
            }
            rs += __shfl_xor_sync(0xffffffffu, rs, 1);
            rs += __shfl_xor_sync(0xffffffffu, rs, 2);
            l_i[i] = l_i[i] * corr + rs;
            m_i[i] = mnew;
            #pragma unroll
            for (int nt = 0; nt < 8; ++nt) {
                o[nt][2*i]     *= corr;
                o[nt][2*i + 1] *= corr;
            }
        }

        // ---- O += P @ V (fp16x2; P hi/lo from registers; V via ldsm.trans) ----
        #pragma unroll
        for (int kc = 0; kc < 4; ++kc) {
            uint32_t ph[4], pl[4];
            {
                float c0 = s[2*kc][0],   c1 = s[2*kc][1];
                float c2 = s[2*kc][2],   c3 = s[2*kc][3];
                float d0 = s[2*kc+1][0], d1 = s[2*kc+1][1];
                float d2 = s[2*kc+1][2], d3 = s[2*kc+1][3];
                ph[0] = pack_half2(c0, c1);
                ph[1] = pack_half2(c2, c3);
                ph[2] = pack_half2(d0, d1);
                ph[3] = pack_half2(d2, d3);
                __half2* hp = (__half2*)ph;
                float2 h0 = __half22float2(hp[0]);
                float2 h1 = __half22float2(hp[1]);
                float2 h2 = __half22float2(hp[2]);
                float2 h3 = __half22float2(hp[3]);
                pl[0] = pack_half2(c0 - h0.x, c1 - h0.y);
                pl[1] = pack_half2(c2 - h1.x, c3 - h1.y);
                pl[2] = pack_half2(d0 - h2.x, d1 - h2.y);
                pl[3] = pack_half2(d2 - h3.x, d3 - h3.y);
            }
            // V tile rows = tokens kc*16..+15; trans loads give [d][k] frags
            const uint32_t vrow = kvb + 9216 +
                (kc * 16 + ((lid >> 3) & 1) * 8 + (lid & 7)) * AROWB +
                (lid >> 4) * 16;
            #pragma unroll
            for (int p = 0; p < 4; ++p) {
                uint32_t vf[4];
                ldsm_x4_t(vf[0], vf[1], vf[2], vf[3], vrow + p * 32);
                #pragma unroll
                for (int half = 0; half < 2; ++half) {
                    int nt = p * 2 + half;
                    mma16816(o[nt], ph[0], ph[1], ph[2], ph[3],
                             vf[half * 2], vf[half * 2 + 1]);
                    mma16816(o[nt], pl[0], pl[1], pl[2], pl[3],
                             vf[half * 2], vf[half * 2 + 1]);
                }
            }
        }

        __syncthreads();   // all warps done reading buffer (jt&1)
        if (jt + 2 < ntiles) {
            att_issue_kv(sb + SK_BASE + (jt & 1) * KVSTAGE, Kk, Vv, jt + 2, tid);
            CP_COMMIT();
        }
    }

    // ---- epilogue: normalize, split to fp16 hi/lo, write hs (fused) ----
    #pragma unroll
    for (int i = 0; i < 2; ++i) {
        float inv = 1.f / l_i[i];
        int q = qbase + w * 16 + (lid >> 2) + i * 8;
        size_t rowidx = ((size_t)b * SEQ + q) * DMODEL + h * HD;
        #pragma unroll
        for (int nt = 0; nt < 8; ++nt) {
            int d = nt * 8 + (lid & 3) * 2;
            float v0 = o[nt][2*i] * inv, v1 = o[nt][2*i+1] * inv;
            __half2 hh = __floats2half2_rn(v0, v1);
            float2 hf = __half22float2(hh);
            __half2 ll = __floats2half2_rn(v0 - hf.x, v1 - hf.y);
            *(__half2*)(g_hs_hi + rowidx + d) = hh;
            *(__half2*)(g_hs_lo + rowidx + d) = ll;
        }
    }
}

// ---------------------------------------------------------------------------
// Launch
// ---------------------------------------------------------------------------
extern "C" void kernel_launch(void* const* d_in, const int* in_sizes, int n_in,
                              void* d_out, int out_size) {
    const float* x    = (const float*)d_in[0];  // [2,2048,1024]
    const float* Wqkv = (const float*)d_in[1];  // [3072,1024]
    const float* Wo   = (const float*)d_in[2];  // [1024,1024]
    float* out = (float*)d_out;                 // [2,2048,1024]

    __half *xs_hi, *xs_lo, *wq, *wo, *hs_hi, *hs_lo;
    cudaGetSymbolAddress((void**)&xs_hi, g_xs_hi);
    cudaGetSymbolAddress((void**)&xs_lo, g_xs_lo);
    cudaGetSymbolAddress((void**)&wq,    g_wq);
    cudaGetSymbolAddress((void**)&wo,    g_wo);
    cudaGetSymbolAddress((void**)&hs_hi, g_hs_hi);
    cudaGetSymbolAddress((void**)&hs_lo, g_hs_lo);

    static bool attr_done = false;
    if (!attr_done) {
        cudaFuncSetAttribute(gemm_fp16x2<0>,
                             cudaFuncAttributeMaxDynamicSharedMemorySize, G3_SMEM);
        cudaFuncSetAttribute(gemm_fp16x2<1>,
                             cudaFuncAttributeMaxDynamicSharedMemorySize, G3_SMEM);
        cudaFuncSetAttribute(attn_mma,
                             cudaFuncAttributeMaxDynamicSharedMemorySize, ATT_SMEM);
        attr_done = true;
    }

    const int n_x  = TOKENS * DMODEL;
    const int n_wq = 3 * DMODEL * DMODEL;
    const int n_wo = DMODEL * DMODEL;

    // Pre-split / round operands
    split_fp16<<<n_x  / 2048, 256>>>(x, xs_hi, xs_lo, n_x);
    round_fp16<<<n_wq / 2048, 256>>>(Wqkv, wq, n_wq);
    round_fp16<<<n_wo / 2048, 256>>>(Wo, wo, n_wo);

    // 1) QKV projection with fused per-head split epilogue
    {
        dim3 grid(3 * DMODEL / 256, TOKENS / 128);   // (12, 32)
        gemm_fp16x2<1><<<grid, 256, G3_SMEM>>>(xs_hi, xs_lo, wq, nullptr,
                                               TOKENS, 3 * DMODEL, DMODEL);
    }
    // 2) HMMA causal flash attention -> g_hs_hi/lo (fused split epilogue)
    {
        dim3 grid(SEQ / 128, NH, BATCH);
        attn_mma<<<grid, 256, ATT_SMEM>>>();
    }
    // 3) Output projection: [4096,1024] @ [1024,1024]^T -> out (fp32)
    {
        dim3 grid(DMODEL / 256, TOKENS / 128);       // (4, 32)
        gemm_fp16x2<0><<<grid, 256, G3_SMEM>>>(hs_hi, hs_lo, wo, out,
                                               TOKENS, DMODEL, DMODEL);
    }
}

// round 9
// speedup vs baseline: 4.4892x; 1.0073x over previous
#include <cuda_runtime.h>
#include <cuda_fp16.h>
#include <cstdint>
#include <math.h>

// Problem constants (fixed by the reference)
#define BATCH   2
#define SEQ     2048
#define DMODEL  1024
#define NH      16
#define HD      64
#define TOKENS  (BATCH*SEQ)          // 4096
#define NHEADS_TOTAL (BATCH*NH)      // 32

// ---------------------------------------------------------------------------
// Scratch (__device__ globals; allocation in kernel_launch is forbidden)
// ---------------------------------------------------------------------------
__device__ __half g_xs_hi[(size_t)TOKENS * DMODEL];
__device__ __half g_xs_lo[(size_t)TOKENS * DMODEL];
__device__ __half g_wq  [(size_t)3 * DMODEL * DMODEL];   // rounded fp16
__device__ __half g_wo  [(size_t)DMODEL * DMODEL];       // rounded fp16
__device__ __half g_hs_hi[(size_t)TOKENS * DMODEL];
__device__ __half g_hs_lo[(size_t)TOKENS * DMODEL];

// Per-head attention operands, all [head][s][64] natural layout
#define HEADELEMS ((size_t)NHEADS_TOTAL * SEQ * HD)
__device__ __half g_q_hi[HEADELEMS];
__device__ __half g_q_lo[HEADELEMS];
__device__ __half g_k  [HEADELEMS];
__device__ __half g_v  [HEADELEMS];

// ---------------------------------------------------------------------------
// PTX helpers (sm_80-era instructions only — compute_100-safe)
// ---------------------------------------------------------------------------
__device__ __forceinline__ uint32_t smem_u32(const void* p) {
    uint32_t a;
    asm("{ .reg .u64 t; cvta.to.shared.u64 t, %1; cvt.u32.u64 %0, t; }"
        : "=r"(a) : "l"(p));
    return a;
}

#define CP_ASYNC16(dst, src) \
    asm volatile("cp.async.cg.shared.global [%0], [%1], 16;" \
                 :: "r"(dst), "l"(src) : "memory")
#define CP_COMMIT() asm volatile("cp.async.commit_group;" ::: "memory")
#define CP_WAIT(N)  asm volatile("cp.async.wait_group %0;" :: "n"(N) : "memory")

__device__ __forceinline__ void ldsm_x4(uint32_t& r0, uint32_t& r1,
                                        uint32_t& r2, uint32_t& r3, uint32_t addr) {
    asm volatile("ldmatrix.sync.aligned.m8n8.x4.shared.b16 {%0,%1,%2,%3}, [%4];"
                 : "=r"(r0), "=r"(r1), "=r"(r2), "=r"(r3) : "r"(addr));
}

__device__ __forceinline__ void ldsm_x4_t(uint32_t& r0, uint32_t& r1,
                                          uint32_t& r2, uint32_t& r3, uint32_t addr) {
    asm volatile("ldmatrix.sync.aligned.m8n8.x4.trans.shared.b16 {%0,%1,%2,%3}, [%4];"
                 : "=r"(r0), "=r"(r1), "=r"(r2), "=r"(r3) : "r"(addr));
}

__device__ __forceinline__ void mma16816(float* c, uint32_t a0, uint32_t a1,
                                         uint32_t a2, uint32_t a3,
                                         uint32_t b0, uint32_t b1) {
    asm volatile(
        "mma.sync.aligned.m16n8k16.row.col.f32.f16.f16.f32 "
        "{%0,%1,%2,%3}, {%4,%5,%6,%7}, {%8,%9}, {%0,%1,%2,%3};"
        : "+f"(c[0]), "+f"(c[1]), "+f"(c[2]), "+f"(c[3])
        : "r"(a0), "r"(a1), "r"(a2), "r"(a3), "r"(b0), "r"(b1));
}

__device__ __forceinline__ uint32_t pack_half2(float a, float b) {
    __half2 h2 = __floats2half2_rn(a, b);
    return *(uint32_t*)&h2;
}

// ---------------------------------------------------------------------------
// split_fp16: fp32 -> fp16 hi + fp16 lo (exact residual). n multiple of 2048.
// ---------------------------------------------------------------------------
__global__ __launch_bounds__(256) void split_fp16(const float* __restrict__ in,
                                                  __half* __restrict__ hi,
                                                  __half* __restrict__ lo,
                                                  int n) {
    int base = (blockIdx.x * 256 + threadIdx.x) * 8;
    if (base >= n) return;
    float4 f0 = *(const float4*)(in + base);
    float4 f1 = *(const float4*)(in + base + 4);
    float f[8] = {f0.x, f0.y, f0.z, f0.w, f1.x, f1.y, f1.z, f1.w};
    uint32_t h[4], l[4];
    #pragma unroll
    for (int j = 0; j < 4; ++j) {
        __half2 h2 = __floats2half2_rn(f[2*j], f[2*j+1]);
        float2 hf = __half22float2(h2);
        __half2 l2 = __floats2half2_rn(f[2*j] - hf.x, f[2*j+1] - hf.y);
        h[j] = *(uint32_t*)&h2;
        l[j] = *(uint32_t*)&l2;
    }
    *(uint4*)(hi + base) = make_uint4(h[0], h[1], h[2], h[3]);
    *(uint4*)(lo + base) = make_uint4(l[0], l[1], l[2], l[3]);
}

// round_fp16: fp32 -> fp16 (single rounding). n multiple of 2048.
__global__ __launch_bounds__(256) void round_fp16(const float* __restrict__ in,
                                                  __half* __restrict__ out, int n) {
    int base = (blockIdx.x * 256 + threadIdx.x) * 8;
    if (base >= n) return;
    float4 f0 = *(const float4*)(in + base);
    float4 f1 = *(const float4*)(in + base + 4);
    __half2 a = __floats2half2_rn(f0.x, f0.y);
    __half2 b = __floats2half2_rn(f0.z, f0.w);
    __half2 c = __floats2half2_rn(f1.x, f1.y);
    __half2 d = __floats2half2_rn(f1.z, f1.w);
    *(uint4*)(out + base) = make_uint4(*(uint32_t*)&a, *(uint32_t*)&b,
                                       *(uint32_t*)&c, *(uint32_t*)&d);
}

// ---------------------------------------------------------------------------
// fp16x2 warp-MMA GEMM: C = (Ahi+Alo)[M,K] @ B[N,K]^T  (B pre-rounded fp16)
// CTA tile 128x256, 512 threads = 16 warps (2x8), warp tile 64x32.
// 4 warps/SMSP for latency hiding (evidence: attn kernel sustains ~480 TF/s
// at this warp density and the same 3.2:1 MMA:LDSM ratio).
// K-chunk 32, 4-stage cp.async pipeline.
// MODE 0: plain fp32 C store. MODE 1: fused per-head QKV split epilogue.
// ---------------------------------------------------------------------------
#define ROWB 80                         // 32 fp16 (64B) + 16B pad
#define G3_AT (128 * ROWB)              // 10240 per A tile
#define G3_BT (256 * ROWB)              // 20480 B tile (single)
#define G3_STAGE (2 * G3_AT + G3_BT)    // 40960
#define G3_SMEM (4 * G3_STAGE)          // 163840
#define GTHREADS 512

__device__ __forceinline__ void g3_issue(
    uint32_t stage, const __half* __restrict__ Ahi,
    const __half* __restrict__ Alo, const __half* __restrict__ B,
    int kc, int K, int tid) {
    // A hi/lo: 2 x 128 rows x 4 chunks = 1024 cp -> 2/thread
    #pragma unroll
    for (int i = 0; i < 2; ++i) {
        int idx  = i * GTHREADS + tid;   // 0..1023
        int prec = idx >> 9;
        int rem  = idx & 511;
        int row  = rem >> 2;
        int c    = rem & 3;
        const __half* src = (prec ? Alo : Ahi) + (size_t)row * K + kc * 32 + c * 8;
        CP_ASYNC16(stage + prec * G3_AT + row * ROWB + c * 16, src);
    }
    // B: 256 rows x 4 chunks = 1024 cp -> 2/thread
    #pragma unroll
    for (int i = 0; i < 2; ++i) {
        int idx  = i * GTHREADS + tid;   // 0..1023
        int row  = idx >> 2;
        int c    = idx & 3;
        const __half* src = B + (size_t)row * K + kc * 32 + c * 8;
        CP_ASYNC16(stage + 2 * G3_AT + row * ROWB + c * 16, src);
    }
}

template<int MODE>
__global__ __launch_bounds__(GTHREADS, 1) void gemm_fp16x2(
    const __half* __restrict__ Ahi, const __half* __restrict__ Alo,
    const __half* __restrict__ B, float* __restrict__ C,
    int M, int N, int K) {
    extern __shared__ char smem[];
    const uint32_t sb = smem_u32(smem);

    const int tid = threadIdx.x;
    const int wid = tid >> 5;
    const int lid = tid & 31;
    const int wm  = wid & 1;       // 0..1 -> 64 rows
    const int wn  = wid >> 1;      // 0..7 -> 32 cols

    const int brow = blockIdx.y;
    const int bcol = blockIdx.x;

    const __half* Ah = Ahi + (size_t)brow * 128 * K;
    const __half* Al = Alo + (size_t)brow * 128 * K;
    const __half* Bb = B   + (size_t)bcol * 256 * K;

    const uint32_t offA = (((lid >> 3) & 1) * 8 + (lid & 7)) * ROWB + (lid >> 4) * 16;
    const uint32_t offB = ((lid >> 4) * 8 + (lid & 7)) * ROWB + ((lid >> 3) & 1) * 16;

    float acc[4][4][4];
    #pragma unroll
    for (int i = 0; i < 4; ++i)
        #pragma unroll
        for (int j = 0; j < 4; ++j)
            #pragma unroll
            for (int e = 0; e < 4; ++e) acc[i][j][e] = 0.f;

    const int nch = K / 32;      // 32
    g3_issue(sb + 0 * G3_STAGE, Ah, Al, Bb, 0, K, tid); CP_COMMIT();
    g3_issue(sb + 1 * G3_STAGE, Ah, Al, Bb, 1, K, tid); CP_COMMIT();
    g3_issue(sb + 2 * G3_STAGE, Ah, Al, Bb, 2, K, tid); CP_COMMIT();

    for (int kc = 0; kc < nch; ++kc) {
        int rem = nch - kc;
        if (rem >= 3)      { CP_WAIT(2); }
        else if (rem == 2) { CP_WAIT(1); }
        else               { CP_WAIT(0); }
        __syncthreads();

        const uint32_t cur  = sb + (kc & 3) * G3_STAGE;
        const uint32_t aHiB = cur + wm * 64 * ROWB + offA;
        const uint32_t aLoB = cur + G3_AT + wm * 64 * ROWB + offA;
        const uint32_t bB   = cur + 2 * G3_AT + wn * 32 * ROWB + offB;

        #pragma unroll
        for (int k16 = 0; k16 < 2; ++k16) {
            const uint32_t ko = k16 * 32;

            uint32_t bf[8];
            #pragma unroll
            for (int nb = 0; nb < 2; ++nb)
                ldsm_x4(bf[nb*4], bf[nb*4+1], bf[nb*4+2], bf[nb*4+3],
                        bB + nb * 16 * ROWB + ko);

            #pragma unroll
            for (int mt = 0; mt < 4; ++mt) {
                uint32_t ah[4], al[4];
                ldsm_x4(ah[0], ah[1], ah[2], ah[3], aHiB + mt * 16 * ROWB + ko);
                ldsm_x4(al[0], al[1], al[2], al[3], aLoB + mt * 16 * ROWB + ko);
                // hi pass then lo pass: dependency distance 4 per accumulator
                #pragma unroll
                for (int nt = 0; nt < 4; ++nt)
                    mma16816(acc[mt][nt], ah[0], ah[1], ah[2], ah[3],
                             bf[nt * 2], bf[nt * 2 + 1]);
                #pragma unroll
                for (int nt = 0; nt < 4; ++nt)
                    mma16816(acc[mt][nt], al[0], al[1], al[2], al[3],
                             bf[nt * 2], bf[nt * 2 + 1]);
            }
        }

        if (kc + 3 < nch) {
            g3_issue(sb + ((kc + 3) & 3) * G3_STAGE, Ah, Al, Bb, kc + 3, K, tid);
            CP_COMMIT();
        }
    }

    if (MODE == 0) {
        // Plain fp32 epilogue
        const int r0 = brow * 128 + wm * 64 + (lid >> 2);
        const int c0 = bcol * 256 + wn * 32 + (lid & 3) * 2;
        #pragma unroll
        for (int mt = 0; mt < 4; ++mt) {
            #pragma unroll
            for (int nt = 0; nt < 4; ++nt) {
                float* p = C + (size_t)(r0 + mt * 16) * N + c0 + nt * 8;
                *(float2*)p                   = make_float2(acc[mt][nt][0], acc[mt][nt][1]);
                *(float2*)(p + (size_t)8 * N) = make_float2(acc[mt][nt][2], acc[mt][nt][3]);
            }
        }
    } else {
        // Fused QKV epilogue. Each warp's 32-col block = half a head.
        const int section = bcol >> 2;                // 0=Q 1=K 2=V
        const int head16  = (bcol & 3) * 4 + (wn >> 1);   // 0..15
        const int headg   = (brow >> 4) * NH + head16;
        const int s0      = ((brow * 128) & (SEQ - 1)) + wm * 64 + (lid >> 2);
        const int d0      = (wn & 1) * 32 + (lid & 3) * 2;
        #pragma unroll
        for (int mt = 0; mt < 4; ++mt) {
            #pragma unroll
            for (int nt = 0; nt < 4; ++nt) {
                int d = d0 + nt * 8;
                #pragma unroll
                for (int i = 0; i < 2; ++i) {
                    int s = s0 + mt * 16 + i * 8;
                    size_t idx = ((size_t)headg * SEQ + s) * HD + d;
                    float v0 = acc[mt][nt][2*i], v1 = acc[mt][nt][2*i+1];
                    if (section == 0) {
                        v0 *= 0.125f; v1 *= 0.125f;
                        __half2 hh = __floats2half2_rn(v0, v1);
                        float2 hf = __half22float2(hh);
                        __half2 ll = __floats2half2_rn(v0 - hf.x, v1 - hf.y);
                        *(__half2*)(g_q_hi + idx) = hh;
                        *(__half2*)(g_q_lo + idx) = ll;
                    } else if (section == 1) {
                        *(__half2*)(g_k + idx) = __floats2half2_rn(v0, v1);
                    } else {
                        *(__half2*)(g_v + idx) = __floats2half2_rn(v0, v1);
                    }
                }
            }
        }
    }
}

// ---------------------------------------------------------------------------
// HMMA flash attention (fp16x2), causal, double-buffered K/V (unchanged).
// ---------------------------------------------------------------------------
#define AROWB 144
#define SQ_HI   0
#define SQ_LO   18432
#define SK_BASE 36864
#define KVSTAGE 18432              // K(9216) + V(9216)
#define ATT_SMEM (SK_BASE + 2 * KVSTAGE)   // 73728
#define NEG_BIG (-1e30f)

__device__ __forceinline__ void att_issue_kv(
    uint32_t kvbase, const __half* __restrict__ Kk,
    const __half* __restrict__ Vv, int jt, int tid) {
    #pragma unroll
    for (int it = 0; it < 4; ++it) {
        int idx = it * 256 + tid;     // 0..1023
        int buf = idx >> 9;           // 0:K 1:V
        int rem = idx & 511;
        int r   = rem >> 3;
        int c8  = rem & 7;
        const __half* src = (buf ? Vv : Kk) + (size_t)(jt * 64 + r) * HD + c8 * 8;
        CP_ASYNC16(kvbase + buf * 9216 + r * AROWB + c8 * 16, src);
    }
}

__global__ __launch_bounds__(256, 2) void attn_mma() {
    extern __shared__ char smem[];
    const uint32_t sb = smem_u32(smem);

    const int tid = threadIdx.x;
    const int w   = tid >> 5;
    const int lid = tid & 31;
    const int qi  = gridDim.x - 1 - blockIdx.x;   // big tiles first
    const int h   = blockIdx.y;
    const int b   = blockIdx.z;
    const int head = b * NH + h;
    const int qbase = qi * 128;

    const __half* Qh = g_q_hi + ((size_t)head * SEQ + qbase) * HD;
    const __half* Ql = g_q_lo + ((size_t)head * SEQ + qbase) * HD;
    const __half* Kk = g_k + (size_t)head * SEQ * HD;
    const __half* Vv = g_v + (size_t)head * SEQ * HD;

    // Stage Q (hi+lo)
    #pragma unroll
    for (int it = 0; it < 8; ++it) {
        int idx  = it * 256 + tid;
        int prec = idx >> 10;
        int rem  = idx & 1023;
        int r    = rem >> 3;
        int c8   = rem & 7;
        const __half* src = (prec ? Ql : Qh) + (size_t)r * HD + c8 * 8;
        CP_ASYNC16(sb + (prec ? SQ_LO : SQ_HI) + r * AROWB + c8 * 16, src);
    }
    CP_COMMIT();

    const int ntiles = 2 * qi + 2;     // >= 2 always
    att_issue_kv(sb + SK_BASE + 0 * KVSTAGE, Kk, Vv, 0, tid);
    CP_COMMIT();
    att_issue_kv(sb + SK_BASE + 1 * KVSTAGE, Kk, Vv, 1, tid);
    CP_COMMIT();

    const uint32_t offA = (((lid >> 3) & 1) * 8 + (lid & 7)) * AROWB + (lid >> 4) * 16;
    const uint32_t offB = ((lid >> 4) * 8 + (lid & 7)) * AROWB + ((lid >> 3) & 1) * 16;
    const uint32_t qA_hi = sb + SQ_HI + w * 16 * AROWB + offA;
    const uint32_t qA_lo = sb + SQ_LO + w * 16 * AROWB + offA;

    float o[8][4];
    #pragma unroll
    for (int nt = 0; nt < 8; ++nt)
        #pragma unroll
        for (int e = 0; e < 4; ++e) o[nt][e] = 0.f;
    float m_i[2] = {NEG_BIG, NEG_BIG};
    float l_i[2] = {0.f, 0.f};

    for (int jt = 0; jt < ntiles; ++jt) {
        if (jt < ntiles - 1) { CP_WAIT(1); } else { CP_WAIT(0); }
        __syncthreads();

        const uint32_t kvb = sb + SK_BASE + (jt & 1) * KVSTAGE;

        // ---- S = Q @ K^T (fp16x2) ----
        float s[8][4];
        #pragma unroll
        for (int nt = 0; nt < 8; ++nt)
            #pragma unroll
            for (int e = 0; e < 4; ++e) s[nt][e] = 0.f;

        #pragma unroll
        for (int kc = 0; kc < 4; ++kc) {
            const uint32_t ko = kc * 32;
            uint32_t ah[4], al[4];
            ldsm_x4(ah[0], ah[1], ah[2], ah[3], qA_hi + ko);
            ldsm_x4(al[0], al[1], al[2], al[3], qA_lo + ko);
            #pragma unroll
            for (int p = 0; p < 4; ++p) {
                uint32_t bk[4];
                ldsm_x4(bk[0], bk[1], bk[2], bk[3],
                        kvb + p * 16 * AROWB + offB + ko);
                #pragma unroll
                for (int half = 0; half < 2; ++half) {
                    int nt = p * 2 + half;
                    mma16816(s[nt], ah[0], ah[1], ah[2], ah[3],
                             bk[half * 2], bk[half * 2 + 1]);
                    mma16816(s[nt], al[0], al[1], al[2], al[3],
                             bk[half * 2], bk[half * 2 + 1]);
                }
            }
        }

        // ---- causal mask (diagonal tiles only) ----
        if (jt >= 2 * qi) {
            #pragma unroll
            for (int i = 0; i < 2; ++i) {
                int qg = qbase + w * 16 + (lid >> 2) + i * 8;
                #pragma unroll
                for (int nt = 0; nt < 8; ++nt) {
                    int kg = jt * 64 + nt * 8 + (lid & 3) * 2;
                    if (kg > qg)     s[nt][2*i]     = NEG_BIG;
                    if (kg + 1 > qg) s[nt][2*i + 1] = NEG_BIG;
                }
            }
        }

        // ---- online softmax (quad reductions) ----
        #pragma unroll
        for (int i = 0; i < 2; ++i) {
            float rm = NEG_BIG;
            #pragma unroll
            for (int nt = 0; nt < 8; ++nt)
                rm = fmaxf(rm, fmaxf(s[nt][2*i], s[nt][2*i+1]));
            rm = fmaxf(rm, __shfl_xor_sync(0xffffffffu, rm, 1));
            rm = fmaxf(rm, __shfl_xor_sync(0xffffffffu, rm, 2));
            float mnew = fmaxf(m_i[i], rm);
            float corr = __expf(m_i[i] - mnew);
            float rs = 0.f;
            #pragma unroll
            for (int nt = 0; nt < 8; ++nt) {
                float p0 = __expf(s[nt][2*i]     - mnew);
                float p1 = __expf(s[nt][2*i + 1] - mnew);
                s[nt][2*i] = p0; s[nt][2*i+1] = p1;
                rs += p0 + p1;
            }
            rs += __shfl_xor_sync(0xffffffffu, rs, 1);
            rs += __shfl_xor_sync(0xffffffffu, rs, 2);
            l_i[i] = l_i[i] * corr + rs;
            m_i[i] = mnew;
            #pragma unroll
            for (int nt = 0; nt < 8; ++nt) {
                o[nt][2*i]     *= corr;
                o[nt][2*i + 1] *= corr;
            }
        }

        // ---- O += P @ V (fp16x2; P hi/lo from registers; V via ldsm.trans) ----
        #pragma unroll
        for (int kc = 0; kc < 4; ++kc) {
            uint32_t ph[4], pl[4];
            {
                float c0 = s[2*kc][0],   c1 = s[2*kc][1];
                float c2 = s[2*kc][2],   c3 = s[2*kc][3];
                float d0 = s[2*kc+1][0], d1 = s[2*kc+1][1];
                float d2 = s[2*kc+1][2], d3 = s[2*kc+1][3];
                ph[0] = pack_half2(c0, c1);
                ph[1] = pack_half2(c2, c3);
                ph[2] = pack_half2(d0, d1);
                ph[3] = pack_half2(d2, d3);
                __half2* hp = (__half2*)ph;
                float2 h0 = __half22float2(hp[0]);
                float2 h1 = __half22float2(hp[1]);
                float2 h2 = __half22float2(hp[2]);
                float2 h3 = __half22float2(hp[3]);
                pl[0] = pack_half2(c0 - h0.x, c1 - h0.y);
                pl[1] = pack_half2(c2 - h1.x, c3 - h1.y);
                pl[2] = pack_half2(d0 - h2.x, d1 - h2.y);
                pl[3] = pack_half2(d2 - h3.x, d3 - h3.y);
            }
            // V tile rows = tokens kc*16..+15; trans loads give [d][k] frags
            const uint32_t vrow = kvb + 9216 +
                (kc * 16 + ((lid >> 3) & 1) * 8 + (lid & 7)) * AROWB +
                (lid >> 4) * 16;
            #pragma unroll
            for (int p = 0; p < 4; ++p) {
                uint32_t vf[4];
                ldsm_x4_t(vf[0], vf[1], vf[2], vf[3], vrow + p * 32);
                #pragma unroll
                for (int half = 0; half < 2; ++half) {
                    int nt = p * 2 + half;
                    mma16816(o[nt], ph[0], ph[1], ph[2], ph[3],
                             vf[half * 2], vf[half * 2 + 1]);
                    mma16816(o[nt], pl[0], pl[1], pl[2], pl[3],
                             vf[half * 2], vf[half * 2 + 1]);
                }
            }
        }

        __syncthreads();   // all warps done reading buffer (jt&1)
        if (jt + 2 < ntiles) {
            att_issue_kv(sb + SK_BASE + (jt & 1) * KVSTAGE, Kk, Vv, jt + 2, tid);
            CP_COMMIT();
        }
    }

    // ---- epilogue: normalize, split to fp16 hi/lo, write hs (fused) ----
    #pragma unroll
    for (int i = 0; i < 2; ++i) {
        float inv = 1.f / l_i[i];
        int q = qbase + w * 16 + (lid >> 2) + i * 8;
        size_t rowidx = ((size_t)b * SEQ + q) * DMODEL + h * HD;
        #pragma unroll
        for (int nt = 0; nt < 8; ++nt) {
            int d = nt * 8 + (lid & 3) * 2;
            float v0 = o[nt][2*i] * inv, v1 = o[nt][2*i+1] * inv;
            __half2 hh = __floats2half2_rn(v0, v1);
            float2 hf = __half22float2(hh);
            __half2 ll = __floats2half2_rn(v0 - hf.x, v1 - hf.y);
            *(__half2*)(g_hs_hi + rowidx + d) = hh;
            *(__half2*)(g_hs_lo + rowidx + d) = ll;
        }
    }
}

// ---------------------------------------------------------------------------
// Launch
// ---------------------------------------------------------------------------
extern "C" void kernel_launch(void* const* d_in, const int* in_sizes, int n_in,
                              void* d_out, int out_size) {
    const float* x    = (const float*)d_in[0];  // [2,2048,1024]
    const float* Wqkv = (const float*)d_in[1];  // [3072,1024]
    const float* Wo   = (const float*)d_in[2];  // [1024,1024]
    float* out = (float*)d_out;                 // [2,2048,1024]

    __half *xs_hi, *xs_lo, *wq, *wo, *hs_hi, *hs_lo;
    cudaGetSymbolAddress((void**)&xs_hi, g_xs_hi);
    cudaGetSymbolAddress((void**)&xs_lo, g_xs_lo);
    cudaGetSymbolAddress((void**)&wq,    g_wq);
    cudaGetSymbolAddress((void**)&wo,    g_wo);
    cudaGetSymbolAddress((void**)&hs_hi, g_hs_hi);
    cudaGetSymbolAddress((void**)&hs_lo, g_hs_lo);

    static bool attr_done = false;
    if (!attr_done) {
        cudaFuncSetAttribute(gemm_fp16x2<0>,
                             cudaFuncAttributeMaxDynamicSharedMemorySize, G3_SMEM);
        cudaFuncSetAttribute(gemm_fp16x2<1>,
                             cudaFuncAttributeMaxDynamicSharedMemorySize, G3_SMEM);
        cudaFuncSetAttribute(attn_mma,
                             cudaFuncAttributeMaxDynamicSharedMemorySize, ATT_SMEM);
        attr_done = true;
    }

    const int n_x  = TOKENS * DMODEL;
    const int n_wq = 3 * DMODEL * DMODEL;
    const int n_wo = DMODEL * DMODEL;

    // Pre-split / round operands
    split_fp16<<<n_x  / 2048, 256>>>(x, xs_hi, xs_lo, n_x);
    round_fp16<<<n_wq / 2048, 256>>>(Wqkv, wq, n_wq);
    round_fp16<<<n_wo / 2048, 256>>>(Wo, wo, n_wo);

    // 1) QKV projection with fused per-head split epilogue
    {
        dim3 grid(3 * DMODEL / 256, TOKENS / 128);   // (12, 32)
        gemm_fp16x2<1><<<grid, GTHREADS, G3_SMEM>>>(xs_hi, xs_lo, wq, nullptr,
                                                    TOKENS, 3 * DMODEL, DMODEL);
    }
    // 2) HMMA causal flash attention -> g_hs_hi/lo (fused split epilogue)
    {
        dim3 grid(SEQ / 128, NH, BATCH);
        attn_mma<<<grid, 256, ATT_SMEM>>>();
    }
    // 3) Output projection: [4096,1024] @ [1024,1024]^T -> out (fp32)
    {
        dim3 grid(DMODEL / 256, TOKENS / 128);       // (4, 32)
        gemm_fp16x2<0><<<grid, GTHREADS, G3_SMEM>>>(hs_hi, hs_lo, wo, out,
                                                    TOKENS, DMODEL, DMODEL);
    }
}

// round 10
// speedup vs baseline: 4.4960x; 1.0015x over previous
#include <cuda_runtime.h>
#include <cuda_fp16.h>
#include <cstdint>
#include <math.h>

// Problem constants (fixed by the reference)
#define BATCH   2
#define SEQ     2048
#define DMODEL  1024
#define NH      16
#define HD      64
#define TOKENS  (BATCH*SEQ)          // 4096
#define NHEADS_TOTAL (BATCH*NH)      // 32

// ---------------------------------------------------------------------------
// Scratch (__device__ globals; allocation in kernel_launch is forbidden)
// ---------------------------------------------------------------------------
__device__ __half g_xs_hi[(size_t)TOKENS * DMODEL];
__device__ __half g_xs_lo[(size_t)TOKENS * DMODEL];
__device__ __half g_wq  [(size_t)3 * DMODEL * DMODEL];   // rounded fp16
__device__ __half g_wo  [(size_t)DMODEL * DMODEL];       // rounded fp16
__device__ __half g_hs_hi[(size_t)TOKENS * DMODEL];
__device__ __half g_hs_lo[(size_t)TOKENS * DMODEL];

// Per-head attention operands, all [head][s][64] natural layout
#define HEADELEMS ((size_t)NHEADS_TOTAL * SEQ * HD)
__device__ __half g_q_hi[HEADELEMS];
__device__ __half g_q_lo[HEADELEMS];
__device__ __half g_k  [HEADELEMS];
__device__ __half g_v  [HEADELEMS];

// ---------------------------------------------------------------------------
// PTX helpers (sm_80-era instructions only — compute_100-safe)
// ---------------------------------------------------------------------------
__device__ __forceinline__ uint32_t smem_u32(const void* p) {
    uint32_t a;
    asm("{ .reg .u64 t; cvta.to.shared.u64 t, %1; cvt.u32.u64 %0, t; }"
        : "=r"(a) : "l"(p));
    return a;
}

#define CP_ASYNC16(dst, src) \
    asm volatile("cp.async.cg.shared.global [%0], [%1], 16;" \
                 :: "r"(dst), "l"(src) : "memory")
#define CP_COMMIT() asm volatile("cp.async.commit_group;" ::: "memory")
#define CP_WAIT(N)  asm volatile("cp.async.wait_group %0;" :: "n"(N) : "memory")

__device__ __forceinline__ void ldsm_x4(uint32_t& r0, uint32_t& r1,
                                        uint32_t& r2, uint32_t& r3, uint32_t addr) {
    asm volatile("ldmatrix.sync.aligned.m8n8.x4.shared.b16 {%0,%1,%2,%3}, [%4];"
                 : "=r"(r0), "=r"(r1), "=r"(r2), "=r"(r3) : "r"(addr));
}

__device__ __forceinline__ void ldsm_x4_t(uint32_t& r0, uint32_t& r1,
                                          uint32_t& r2, uint32_t& r3, uint32_t addr) {
    asm volatile("ldmatrix.sync.aligned.m8n8.x4.trans.shared.b16 {%0,%1,%2,%3}, [%4];"
                 : "=r"(r0), "=r"(r1), "=r"(r2), "=r"(r3) : "r"(addr));
}

__device__ __forceinline__ void mma16816(float* c, uint32_t a0, uint32_t a1,
                                         uint32_t a2, uint32_t a3,
                                         uint32_t b0, uint32_t b1) {
    asm volatile(
        "mma.sync.aligned.m16n8k16.row.col.f32.f16.f16.f32 "
        "{%0,%1,%2,%3}, {%4,%5,%6,%7}, {%8,%9}, {%0,%1,%2,%3};"
        : "+f"(c[0]), "+f"(c[1]), "+f"(c[2]), "+f"(c[3])
        : "r"(a0), "r"(a1), "r"(a2), "r"(a3), "r"(b0), "r"(b1));
}

__device__ __forceinline__ uint32_t pack_half2(float a, float b) {
    __half2 h2 = __floats2half2_rn(a, b);
    return *(uint32_t*)&h2;
}

// ---------------------------------------------------------------------------
// split_fp16: fp32 -> fp16 hi + fp16 lo (exact residual). n multiple of 2048.
// ---------------------------------------------------------------------------
__global__ __launch_bounds__(256) void split_fp16(const float* __restrict__ in,
                                                  __half* __restrict__ hi,
                                                  __half* __restrict__ lo,
                                                  int n) {
    int base = (blockIdx.x * 256 + threadIdx.x) * 8;
    if (base >= n) return;
    float4 f0 = *(const float4*)(in + base);
    float4 f1 = *(const float4*)(in + base + 4);
    float f[8] = {f0.x, f0.y, f0.z, f0.w, f1.x, f1.y, f1.z, f1.w};
    uint32_t h[4], l[4];
    #pragma unroll
    for (int j = 0; j < 4; ++j) {
        __half2 h2 = __floats2half2_rn(f[2*j], f[2*j+1]);
        float2 hf = __half22float2(h2);
        __half2 l2 = __floats2half2_rn(f[2*j] - hf.x, f[2*j+1] - hf.y);
        h[j] = *(uint32_t*)&h2;
        l[j] = *(uint32_t*)&l2;
    }
    *(uint4*)(hi + base) = make_uint4(h[0], h[1], h[2], h[3]);
    *(uint4*)(lo + base) = make_uint4(l[0], l[1], l[2], l[3]);
}

// round_fp16: fp32 -> fp16 (single rounding). n multiple of 2048.
__global__ __launch_bounds__(256) void round_fp16(const float* __restrict__ in,
                                                  __half* __restrict__ out, int n) {
    int base = (blockIdx.x * 256 + threadIdx.x) * 8;
    if (base >= n) return;
    float4 f0 = *(const float4*)(in + base);
    float4 f1 = *(const float4*)(in + base + 4);
    __half2 a = __floats2half2_rn(f0.x, f0.y);
    __half2 b = __floats2half2_rn(f0.z, f0.w);
    __half2 c = __floats2half2_rn(f1.x, f1.y);
    __half2 d = __floats2half2_rn(f1.z, f1.w);
    *(uint4*)(out + base) = make_uint4(*(uint32_t*)&a, *(uint32_t*)&b,
                                       *(uint32_t*)&c, *(uint32_t*)&d);
}

// ---------------------------------------------------------------------------
// fp16x2 warp-MMA GEMM: C = (Ahi+Alo)[M,K] @ B[N,K]^T  (B pre-rounded fp16)
// CTA tile 128x128, 256 threads = 8 warps (2x4), warp tile 64x32.
// 3-stage pipeline, 90KB smem -> 2 CTAs/SM so one CTA's MMAs cover the
// other's CP_WAIT/__syncthreads bubbles (the mechanism attn_mma proves).
// MODE 0: plain fp32 C store. MODE 1: fused per-head QKV split epilogue.
// ---------------------------------------------------------------------------
#define ROWB 80                         // 32 fp16 (64B) + 16B pad
#define G3_AT (128 * ROWB)              // 10240 per A tile
#define G3_BT (128 * ROWB)              // 10240 B tile (single)
#define G3_STAGE (2 * G3_AT + G3_BT)    // 30720
#define G3_SMEM (3 * G3_STAGE)          // 92160
#define GTHREADS 256

__device__ __forceinline__ void g3_issue(
    uint32_t stage, const __half* __restrict__ Ahi,
    const __half* __restrict__ Alo, const __half* __restrict__ B,
    int kc, int K, int tid) {
    // A hi/lo: 2 x 128 rows x 4 chunks = 1024 cp -> 4/thread
    #pragma unroll
    for (int i = 0; i < 4; ++i) {
        int idx  = i * GTHREADS + tid;   // 0..1023
        int prec = idx >> 9;
        int rem  = idx & 511;
        int row  = rem >> 2;
        int c    = rem & 3;
        const __half* src = (prec ? Alo : Ahi) + (size_t)row * K + kc * 32 + c * 8;
        CP_ASYNC16(stage + prec * G3_AT + row * ROWB + c * 16, src);
    }
    // B: 128 rows x 4 chunks = 512 cp -> 2/thread
    #pragma unroll
    for (int i = 0; i < 2; ++i) {
        int idx  = i * GTHREADS + tid;   // 0..511
        int row  = idx >> 2;
        int c    = idx & 3;
        const __half* src = B + (size_t)row * K + kc * 32 + c * 8;
        CP_ASYNC16(stage + 2 * G3_AT + row * ROWB + c * 16, src);
    }
}

template<int MODE>
__global__ __launch_bounds__(GTHREADS, 2) void gemm_fp16x2(
    const __half* __restrict__ Ahi, const __half* __restrict__ Alo,
    const __half* __restrict__ B, float* __restrict__ C,
    int M, int N, int K) {
    extern __shared__ char smem[];
    const uint32_t sb = smem_u32(smem);

    const int tid = threadIdx.x;
    const int wid = tid >> 5;
    const int lid = tid & 31;
    const int wm  = wid & 1;       // 0..1 -> 64 rows
    const int wn  = wid >> 1;      // 0..3 -> 32 cols

    const int brow = blockIdx.y;
    const int bcol = blockIdx.x;

    const __half* Ah = Ahi + (size_t)brow * 128 * K;
    const __half* Al = Alo + (size_t)brow * 128 * K;
    const __half* Bb = B   + (size_t)bcol * 128 * K;

    const uint32_t offA = (((lid >> 3) & 1) * 8 + (lid & 7)) * ROWB + (lid >> 4) * 16;
    const uint32_t offB = ((lid >> 4) * 8 + (lid & 7)) * ROWB + ((lid >> 3) & 1) * 16;

    float acc[4][4][4];
    #pragma unroll
    for (int i = 0; i < 4; ++i)
        #pragma unroll
        for (int j = 0; j < 4; ++j)
            #pragma unroll
            for (int e = 0; e < 4; ++e) acc[i][j][e] = 0.f;

    const int nch = K / 32;      // 32
    g3_issue(sb + 0 * G3_STAGE, Ah, Al, Bb, 0, K, tid); CP_COMMIT();
    g3_issue(sb + 1 * G3_STAGE, Ah, Al, Bb, 1, K, tid); CP_COMMIT();

    for (int kc = 0; kc < nch; ++kc) {
        if (kc + 1 < nch) { CP_WAIT(1); } else { CP_WAIT(0); }
        __syncthreads();

        const uint32_t cur  = sb + (kc % 3) * G3_STAGE;
        const uint32_t aHiB = cur + wm * 64 * ROWB + offA;
        const uint32_t aLoB = cur + G3_AT + wm * 64 * ROWB + offA;
        const uint32_t bB   = cur + 2 * G3_AT + wn * 32 * ROWB + offB;

        #pragma unroll
        for (int k16 = 0; k16 < 2; ++k16) {
            const uint32_t ko = k16 * 32;

            uint32_t bf[8];
            #pragma unroll
            for (int nb = 0; nb < 2; ++nb)
                ldsm_x4(bf[nb*4], bf[nb*4+1], bf[nb*4+2], bf[nb*4+3],
                        bB + nb * 16 * ROWB + ko);

            #pragma unroll
            for (int mt = 0; mt < 4; ++mt) {
                uint32_t ah[4], al[4];
                ldsm_x4(ah[0], ah[1], ah[2], ah[3], aHiB + mt * 16 * ROWB + ko);
                ldsm_x4(al[0], al[1], al[2], al[3], aLoB + mt * 16 * ROWB + ko);
                // hi pass then lo pass: dependency distance 4 per accumulator
                #pragma unroll
                for (int nt = 0; nt < 4; ++nt)
                    mma16816(acc[mt][nt], ah[0], ah[1], ah[2], ah[3],
                             bf[nt * 2], bf[nt * 2 + 1]);
                #pragma unroll
                for (int nt = 0; nt < 4; ++nt)
                    mma16816(acc[mt][nt], al[0], al[1], al[2], al[3],
                             bf[nt * 2], bf[nt * 2 + 1]);
            }
        }

        if (kc + 2 < nch) {
            g3_issue(sb + ((kc + 2) % 3) * G3_STAGE, Ah, Al, Bb, kc + 2, K, tid);
            CP_COMMIT();
        }
    }

    if (MODE == 0) {
        // Plain fp32 epilogue
        const int r0 = brow * 128 + wm * 64 + (lid >> 2);
        const int c0 = bcol * 128 + wn * 32 + (lid & 3) * 2;
        #pragma unroll
        for (int mt = 0; mt < 4; ++mt) {
            #pragma unroll
            for (int nt = 0; nt < 4; ++nt) {
                float* p = C + (size_t)(r0 + mt * 16) * N + c0 + nt * 8;
                *(float2*)p                   = make_float2(acc[mt][nt][0], acc[mt][nt][1]);
                *(float2*)(p + (size_t)8 * N) = make_float2(acc[mt][nt][2], acc[mt][nt][3]);
            }
        }
    } else {
        // Fused QKV epilogue. CTA covers 128 cols = 2 heads; each warp's
        // 32-col block = half a head.
        const int section = bcol >> 3;                    // 0=Q 1=K 2=V
        const int head16  = (bcol & 7) * 2 + (wn >> 1);   // 0..15
        const int headg   = (brow >> 4) * NH + head16;
        const int s0      = ((brow * 128) & (SEQ - 1)) + wm * 64 + (lid >> 2);
        const int d0      = (wn & 1) * 32 + (lid & 3) * 2;
        #pragma unroll
        for (int mt = 0; mt < 4; ++mt) {
            #pragma unroll
            for (int nt = 0; nt < 4; ++nt) {
                int d = d0 + nt * 8;
                #pragma unroll
                for (int i = 0; i < 2; ++i) {
                    int s = s0 + mt * 16 + i * 8;
                    size_t idx = ((size_t)headg * SEQ + s) * HD + d;
                    float v0 = acc[mt][nt][2*i], v1 = acc[mt][nt][2*i+1];
                    if (section == 0) {
                        v0 *= 0.125f; v1 *= 0.125f;
                        __half2 hh = __floats2half2_rn(v0, v1);
                        float2 hf = __half22float2(hh);
                        __half2 ll = __floats2half2_rn(v0 - hf.x, v1 - hf.y);
                        *(__half2*)(g_q_hi + idx) = hh;
                        *(__half2*)(g_q_lo + idx) = ll;
                    } else if (section == 1) {
                        *(__half2*)(g_k + idx) = __floats2half2_rn(v0, v1);
                    } else {
                        *(__half2*)(g_v + idx) = __floats2half2_rn(v0, v1);
                    }
                }
            }
        }
    }
}

// ---------------------------------------------------------------------------
// HMMA flash attention (fp16x2), causal, double-buffered K/V (unchanged).
// ---------------------------------------------------------------------------
#define AROWB 144
#define SQ_HI   0
#define SQ_LO   18432
#define SK_BASE 36864
#define KVSTAGE 18432              // K(9216) + V(9216)
#define ATT_SMEM (SK_BASE + 2 * KVSTAGE)   // 73728
#define NEG_BIG (-1e30f)

__device__ __forceinline__ void att_issue_kv(
    uint32_t kvbase, const __half* __restrict__ Kk,
    const __half* __restrict__ Vv, int jt, int tid) {
    #pragma unroll
    for (int it = 0; it < 4; ++it) {
        int idx = it * 256 + tid;     // 0..1023
        int buf = idx >> 9;           // 0:K 1:V
        int rem = idx & 511;
        int r   = rem >> 3;
        int c8  = rem & 7;
        const __half* src = (buf ? Vv : Kk) + (size_t)(jt * 64 + r) * HD + c8 * 8;
        CP_ASYNC16(kvbase + buf * 9216 + r * AROWB + c8 * 16, src);
    }
}

__global__ __launch_bounds__(256, 2) void attn_mma() {
    extern __shared__ char smem[];
    const uint32_t sb = smem_u32(smem);

    const int tid = threadIdx.x;
    const int w   = tid >> 5;
    const int lid = tid & 31;
    const int qi  = gridDim.x - 1 - blockIdx.x;   // big tiles first
    const int h   = blockIdx.y;
    const int b   = blockIdx.z;
    const int head = b * NH + h;
    const int qbase = qi * 128;

    const __half* Qh = g_q_hi + ((size_t)head * SEQ + qbase) * HD;
    const __half* Ql = g_q_lo + ((size_t)head * SEQ + qbase) * HD;
    const __half* Kk = g_k + (size_t)head * SEQ * HD;
    const __half* Vv = g_v + (size_t)head * SEQ * HD;

    // Stage Q (hi+lo)
    #pragma unroll
    for (int it = 0; it < 8; ++it) {
        int idx  = it * 256 + tid;
        int prec = idx >> 10;
        int rem  = idx & 1023;
        int r    = rem >> 3;
        int c8   = rem & 7;
        const __half* src = (prec ? Ql : Qh) + (size_t)r * HD + c8 * 8;
        CP_ASYNC16(sb + (prec ? SQ_LO : SQ_HI) + r * AROWB + c8 * 16, src);
    }
    CP_COMMIT();

    const int ntiles = 2 * qi + 2;     // >= 2 always
    att_issue_kv(sb + SK_BASE + 0 * KVSTAGE, Kk, Vv, 0, tid);
    CP_COMMIT();
    att_issue_kv(sb + SK_BASE + 1 * KVSTAGE, Kk, Vv, 1, tid);
    CP_COMMIT();

    const uint32_t offA = (((lid >> 3) & 1) * 8 + (lid & 7)) * AROWB + (lid >> 4) * 16;
    const uint32_t offB = ((lid >> 4) * 8 + (lid & 7)) * AROWB + ((lid >> 3) & 1) * 16;
    const uint32_t qA_hi = sb + SQ_HI + w * 16 * AROWB + offA;
    const uint32_t qA_lo = sb + SQ_LO + w * 16 * AROWB + offA;

    float o[8][4];
    #pragma unroll
    for (int nt = 0; nt < 8; ++nt)
        #pragma unroll
        for (int e = 0; e < 4; ++e) o[nt][e] = 0.f;
    float m_i[2] = {NEG_BIG, NEG_BIG};
    float l_i[2] = {0.f, 0.f};

    for (int jt = 0; jt < ntiles; ++jt) {
        if (jt < ntiles - 1) { CP_WAIT(1); } else { CP_WAIT(0); }
        __syncthreads();

        const uint32_t kvb = sb + SK_BASE + (jt & 1) * KVSTAGE;

        // ---- S = Q @ K^T (fp16x2) ----
        float s[8][4];
        #pragma unroll
        for (int nt = 0; nt < 8; ++nt)
            #pragma unroll
            for (int e = 0; e < 4; ++e) s[nt][e] = 0.f;

        #pragma unroll
        for (int kc = 0; kc < 4; ++kc) {
            const uint32_t ko = kc * 32;
            uint32_t ah[4], al[4];
            ldsm_x4(ah[0], ah[1], ah[2], ah[3], qA_hi + ko);
            ldsm_x4(al[0], al[1], al[2], al[3], qA_lo + ko);
            #pragma unroll
            for (int p = 0; p < 4; ++p) {
                uint32_t bk[4];
                ldsm_x4(bk[0], bk[1], bk[2], bk[3],
                        kvb + p * 16 * AROWB + offB + ko);
                #pragma unroll
                for (int half = 0; half < 2; ++half) {
                    int nt = p * 2 + half;
                    mma16816(s[nt], ah[0], ah[1], ah[2], ah[3],
                             bk[half * 2], bk[half * 2 + 1]);
                    mma16816(s[nt], al[0], al[1], al[2], al[3],
                             bk[half * 2], bk[half * 2 + 1]);
                }
            }
        }

        // ---- causal mask (diagonal tiles only) ----
        if (jt >= 2 * qi) {
            #pragma unroll
            for (int i = 0; i < 2; ++i) {
                int qg = qbase + w * 16 + (lid >> 2) + i * 8;
                #pragma unroll
                for (int nt = 0; nt < 8; ++nt) {
                    int kg = jt * 64 + nt * 8 + (lid & 3) * 2;
                    if (kg > qg)     s[nt][2*i]     = NEG_BIG;
                    if (kg + 1 > qg) s[nt][2*i + 1] = NEG_BIG;
                }
            }
        }

        // ---- online softmax (quad reductions) ----
        #pragma unroll
        for (int i = 0; i < 2; ++i) {
            float rm = NEG_BIG;
            #pragma unroll
            for (int nt = 0; nt < 8; ++nt)
                rm = fmaxf(rm, fmaxf(s[nt][2*i], s[nt][2*i+1]));
            rm = fmaxf(rm, __shfl_xor_sync(0xffffffffu, rm, 1));
            rm = fmaxf(rm, __shfl_xor_sync(0xffffffffu, rm, 2));
            float mnew = fmaxf(m_i[i], rm);
            float corr = __expf(m_i[i] - mnew);
            float rs = 0.f;
            #pragma unroll
            for (int nt = 0; nt < 8; ++nt) {
                float p0 = __expf(s[nt][2*i]     - mnew);
                float p1 = __expf(s[nt][2*i + 1] - mnew);
                s[nt][2*i] = p0; s[nt][2*i+1] = p1;
                rs += p0 + p1;
            }
            rs += __shfl_xor_sync(0xffffffffu, rs, 1);
            rs += __shfl_xor_sync(0xffffffffu, rs, 2);
            l_i[i] = l_i[i] * corr + rs;
            m_i[i] = mnew;
            #pragma unroll
            for (int nt = 0; nt < 8; ++nt) {
                o[nt][2*i]     *= corr;
                o[nt][2*i + 1] *= corr;
            }
        }

        // ---- O += P @ V (fp16x2; P hi/lo from registers; V via ldsm.trans) ----
        #pragma unroll
        for (int kc = 0; kc < 4; ++kc) {
            uint32_t ph[4], pl[4];
            {
                float c0 = s[2*kc][0],   c1 = s[2*kc][1];
                float c2 = s[2*kc][2],   c3 = s[2*kc][3];
                float d0 = s[2*kc+1][0], d1 = s[2*kc+1][1];
                float d2 = s[2*kc+1][2], d3 = s[2*kc+1][3];
                ph[0] = pack_half2(c0, c1);
                ph[1] = pack_half2(c2, c3);
                ph[2] = pack_half2(d0, d1);
                ph[3] = pack_half2(d2, d3);
                __half2* hp = (__half2*)ph;
                float2 h0 = __half22float2(hp[0]);
                float2 h1 = __half22float2(hp[1]);
                float2 h2 = __half22float2(hp[2]);
                float2 h3 = __half22float2(hp[3]);
                pl[0] = pack_half2(c0 - h0.x, c1 - h0.y);
                pl[1] = pack_half2(c2 - h1.x, c3 - h1.y);
                pl[2] = pack_half2(d0 - h2.x, d1 - h2.y);
                pl[3] = pack_half2(d2 - h3.x, d3 - h3.y);
            }
            // V tile rows = tokens kc*16..+15; trans loads give [d][k] frags
            const uint32_t vrow = kvb + 9216 +
                (kc * 16 + ((lid >> 3) & 1) * 8 + (lid & 7)) * AROWB +
                (lid >> 4) * 16;
            #pragma unroll
            for (int p = 0; p < 4; ++p) {
                uint32_t vf[4];
                ldsm_x4_t(vf[0], vf[1], vf[2], vf[3], vrow + p * 32);
                #pragma unroll
                for (int half = 0; half < 2; ++half) {
                    int nt = p * 2 + half;
                    mma16816(o[nt], ph[0], ph[1], ph[2], ph[3],
                             vf[half * 2], vf[half * 2 + 1]);
                    mma16816(o[nt], pl[0], pl[1], pl[2], pl[3],
                             vf[half * 2], vf[half * 2 + 1]);
                }
            }
        }

        __syncthreads();   // all warps done reading buffer (jt&1)
        if (jt + 2 < ntiles) {
            att_issue_kv(sb + SK_BASE + (jt & 1) * KVSTAGE, Kk, Vv, jt + 2, tid);
            CP_COMMIT();
        }
    }

    // ---- epilogue: normalize, split to fp16 hi/lo, write hs (fused) ----
    #pragma unroll
    for (int i = 0; i < 2; ++i) {
        float inv = 1.f / l_i[i];
        int q = qbase + w * 16 + (lid >> 2) + i * 8;
        size_t rowidx = ((size_t)b * SEQ + q) * DMODEL + h * HD;
        #pragma unroll
        for (int nt = 0; nt < 8; ++nt) {
            int d = nt * 8 + (lid & 3) * 2;
            float v0 = o[nt][2*i] * inv, v1 = o[nt][2*i+1] * inv;
            __half2 hh = __floats2half2_rn(v0, v1);
            float2 hf = __half22float2(hh);
            __half2 ll = __floats2half2_rn(v0 - hf.x, v1 - hf.y);
            *(__half2*)(g_hs_hi + rowidx + d) = hh;
            *(__half2*)(g_hs_lo + rowidx + d) = ll;
        }
    }
}

// ---------------------------------------------------------------------------
// Launch
// ---------------------------------------------------------------------------
extern "C" void kernel_launch(void* const* d_in, const int* in_sizes, int n_in,
                              void* d_out, int out_size) {
    const float* x    = (const float*)d_in[0];  // [2,2048,1024]
    const float* Wqkv = (const float*)d_in[1];  // [3072,1024]
    const float* Wo   = (const float*)d_in[2];  // [1024,1024]
    float* out = (float*)d_out;                 // [2,2048,1024]

    __half *xs_hi, *xs_lo, *wq, *wo, *hs_hi, *hs_lo;
    cudaGetSymbolAddress((void**)&xs_hi, g_xs_hi);
    cudaGetSymbolAddress((void**)&xs_lo, g_xs_lo);
    cudaGetSymbolAddress((void**)&wq,    g_wq);
    cudaGetSymbolAddress((void**)&wo,    g_wo);
    cudaGetSymbolAddress((void**)&hs_hi, g_hs_hi);
    cudaGetSymbolAddress((void**)&hs_lo, g_hs_lo);

    static bool attr_done = false;
    if (!attr_done) {
        cudaFuncSetAttribute(gemm_fp16x2<0>,
                             cudaFuncAttributeMaxDynamicSharedMemorySize, G3_SMEM);
        cudaFuncSetAttribute(gemm_fp16x2<1>,
                             cudaFuncAttributeMaxDynamicSharedMemorySize, G3_SMEM);
        cudaFuncSetAttribute(attn_mma,
                             cudaFuncAttributeMaxDynamicSharedMemorySize, ATT_SMEM);
        attr_done = true;
    }

    const int n_x  = TOKENS * DMODEL;
    const int n_wq = 3 * DMODEL * DMODEL;
    const int n_wo = DMODEL * DMODEL;

    // Pre-split / round operands
    split_fp16<<<n_x  / 2048, 256>>>(x, xs_hi, xs_lo, n_x);
    round_fp16<<<n_wq / 2048, 256>>>(Wqkv, wq, n_wq);
    round_fp16<<<n_wo / 2048, 256>>>(Wo, wo, n_wo);

    // 1) QKV projection with fused per-head split epilogue
    {
        dim3 grid(3 * DMODEL / 128, TOKENS / 128);   // (24, 32)
        gemm_fp16x2<1><<<grid, GTHREADS, G3_SMEM>>>(xs_hi, xs_lo, wq, nullptr,
                                                    TOKENS, 3 * DMODEL, DMODEL);
    }
    // 2) HMMA causal flash attention -> g_hs_hi/lo (fused split epilogue)
    {
        dim3 grid(SEQ / 128, NH, BATCH);
        attn_mma<<<grid, 256, ATT_SMEM>>>();
    }
    // 3) Output projection: [4096,1024] @ [1024,1024]^T -> out (fp32)
    {
        dim3 grid(DMODEL / 128, TOKENS / 128);       // (8, 32)
        gemm_fp16x2<0><<<grid, GTHREADS, G3_SMEM>>>(hs_hi, hs_lo, wo, out,
                                                    TOKENS, DMODEL, DMODEL);
    }
}

// round 11
// speedup vs baseline: 5.8340x; 1.2976x over previous
#include <cuda_runtime.h>
#include <cuda_fp16.h>
#include <cstdint>
#include <math.h>

// Problem constants (fixed by the reference)
#define BATCH   2
#define SEQ     2048
#define DMODEL  1024
#define NH      16
#define HD      64
#define TOKENS  (BATCH*SEQ)          // 4096
#define NHEADS_TOTAL (BATCH*NH)      // 32

// ---------------------------------------------------------------------------
// Scratch (__device__ globals; allocation in kernel_launch is forbidden)
// ---------------------------------------------------------------------------
__device__ __half g_xs  [(size_t)TOKENS * DMODEL];       // x rounded fp16
__device__ __half g_wq  [(size_t)3 * DMODEL * DMODEL];   // rounded fp16
__device__ __half g_wo  [(size_t)DMODEL * DMODEL];       // rounded fp16
__device__ __half g_hs_hi[(size_t)TOKENS * DMODEL];
__device__ __half g_hs_lo[(size_t)TOKENS * DMODEL];

// Per-head attention operands, all [head][s][64] natural layout
#define HEADELEMS ((size_t)NHEADS_TOTAL * SEQ * HD)
__device__ __half g_q_hi[HEADELEMS];
__device__ __half g_q_lo[HEADELEMS];
__device__ __half g_k  [HEADELEMS];
__device__ __half g_v  [HEADELEMS];

// ---------------------------------------------------------------------------
// PTX helpers (sm_80-era instructions only — compute_100-safe)
// ---------------------------------------------------------------------------
__device__ __forceinline__ uint32_t smem_u32(const void* p) {
    uint32_t a;
    asm("{ .reg .u64 t; cvta.to.shared.u64 t, %1; cvt.u32.u64 %0, t; }"
        : "=r"(a) : "l"(p));
    return a;
}

#define CP_ASYNC16(dst, src) \
    asm volatile("cp.async.cg.shared.global [%0], [%1], 16;" \
                 :: "r"(dst), "l"(src) : "memory")
#define CP_COMMIT() asm volatile("cp.async.commit_group;" ::: "memory")
#define CP_WAIT(N)  asm volatile("cp.async.wait_group %0;" :: "n"(N) : "memory")

__device__ __forceinline__ void ldsm_x4(uint32_t& r0, uint32_t& r1,
                                        uint32_t& r2, uint32_t& r3, uint32_t addr) {
    asm volatile("ldmatrix.sync.aligned.m8n8.x4.shared.b16 {%0,%1,%2,%3}, [%4];"
                 : "=r"(r0), "=r"(r1), "=r"(r2), "=r"(r3) : "r"(addr));
}

__device__ __forceinline__ void ldsm_x4_t(uint32_t& r0, uint32_t& r1,
                                          uint32_t& r2, uint32_t& r3, uint32_t addr) {
    asm volatile("ldmatrix.sync.aligned.m8n8.x4.trans.shared.b16 {%0,%1,%2,%3}, [%4];"
                 : "=r"(r0), "=r"(r1), "=r"(r2), "=r"(r3) : "r"(addr));
}

__device__ __forceinline__ void mma16816(float* c, uint32_t a0, uint32_t a1,
                                         uint32_t a2, uint32_t a3,
                                         uint32_t b0, uint32_t b1) {
    asm volatile(
        "mma.sync.aligned.m16n8k16.row.col.f32.f16.f16.f32 "
        "{%0,%1,%2,%3}, {%4,%5,%6,%7}, {%8,%9}, {%0,%1,%2,%3};"
        : "+f"(c[0]), "+f"(c[1]), "+f"(c[2]), "+f"(c[3])
        : "r"(a0), "r"(a1), "r"(a2), "r"(a3), "r"(b0), "r"(b1));
}

__device__ __forceinline__ uint32_t pack_half2(float a, float b) {
    __half2 h2 = __floats2half2_rn(a, b);
    return *(uint32_t*)&h2;
}

// ---------------------------------------------------------------------------
// split_fp16: fp32 -> fp16 hi + fp16 lo (exact residual). n multiple of 2048.
// ---------------------------------------------------------------------------
__global__ __launch_bounds__(256) void split_fp16(const float* __restrict__ in,
                                                  __half* __restrict__ hi,
                                                  __half* __restrict__ lo,
                                                  int n) {
    int base = (blockIdx.x * 256 + threadIdx.x) * 8;
    if (base >= n) return;
    float4 f0 = *(const float4*)(in + base);
    float4 f1 = *(const float4*)(in + base + 4);
    float f[8] = {f0.x, f0.y, f0.z, f0.w, f1.x, f1.y, f1.z, f1.w};
    uint32_t h[4], l[4];
    #pragma unroll
    for (int j = 0; j < 4; ++j) {
        __half2 h2 = __floats2half2_rn(f[2*j], f[2*j+1]);
        float2 hf = __half22float2(h2);
        __half2 l2 = __floats2half2_rn(f[2*j] - hf.x, f[2*j+1] - hf.y);
        h[j] = *(uint32_t*)&h2;
        l[j] = *(uint32_t*)&l2;
    }
    *(uint4*)(hi + base) = make_uint4(h[0], h[1], h[2], h[3]);
    *(uint4*)(lo + base) = make_uint4(l[0], l[1], l[2], l[3]);
}

// round_fp16: fp32 -> fp16 (single rounding). n multiple of 2048.
__global__ __launch_bounds__(256) void round_fp16(const float* __restrict__ in,
                                                  __half* __restrict__ out, int n) {
    int base = (blockIdx.x * 256 + threadIdx.x) * 8;
    if (base >= n) return;
    float4 f0 = *(const float4*)(in + base);
    float4 f1 = *(const float4*)(in + base + 4);
    __half2 a = __floats2half2_rn(f0.x, f0.y);
    __half2 b = __floats2half2_rn(f0.z, f0.w);
    __half2 c = __floats2half2_rn(f1.x, f1.y);
    __half2 d = __floats2half2_rn(f1.z, f1.w);
    *(uint4*)(out + base) = make_uint4(*(uint32_t*)&a, *(uint32_t*)&b,
                                       *(uint32_t*)&c, *(uint32_t*)&d);
}

// ---------------------------------------------------------------------------
// fp16 warp-MMA GEMM: C = A[M,K] @ B[N,K]^T, A either single fp16 (DUAL_A=0)
// or hi+lo 2-pass (DUAL_A=1). CTA tile 128x128, 8 warps x (64x32), K-chunk 32,
// 3-stage cp.async pipeline, 2 CTAs/SM.
// MODE 0: plain fp32 C store. MODE 1: fused per-head QKV split epilogue.
// ---------------------------------------------------------------------------
#define ROWB 80                         // 32 fp16 (64B) + 16B pad
#define G3_AT (128 * ROWB)              // 10240 per tile (A or B)
#define GTHREADS 256

template<int DUAL_A>
__device__ __forceinline__ void g3_issue(
    uint32_t stage, const __half* __restrict__ Ahi,
    const __half* __restrict__ Alo, const __half* __restrict__ B,
    int kc, int K, int tid) {
    // A: (1+DUAL_A) x 128 rows x 4 chunks
    #pragma unroll
    for (int i = 0; i < 2 * (1 + DUAL_A); ++i) {
        int idx  = i * GTHREADS + tid;
        int prec = idx >> 9;             // 0 for first 512, 1 for second 512
        int rem  = idx & 511;
        int row  = rem >> 2;
        int c    = rem & 3;
        const __half* src = (prec ? Alo : Ahi) + (size_t)row * K + kc * 32 + c * 8;
        CP_ASYNC16(stage + prec * G3_AT + row * ROWB + c * 16, src);
    }
    // B: 128 rows x 4 chunks = 512 cp -> 2/thread
    #pragma unroll
    for (int i = 0; i < 2; ++i) {
        int idx  = i * GTHREADS + tid;
        int row  = idx >> 2;
        int c    = idx & 3;
        const __half* src = B + (size_t)row * K + kc * 32 + c * 8;
        CP_ASYNC16(stage + (1 + DUAL_A) * G3_AT + row * ROWB + c * 16, src);
    }
}

template<int MODE, int DUAL_A>
__global__ __launch_bounds__(GTHREADS, 2) void gemm_fp16(
    const __half* __restrict__ Ahi, const __half* __restrict__ Alo,
    const __half* __restrict__ B, float* __restrict__ C,
    int M, int N, int K) {
    constexpr int STAGE = (2 + DUAL_A) * G3_AT;   // A tiles + B tile
    extern __shared__ char smem[];
    const uint32_t sb = smem_u32(smem);

    const int tid = threadIdx.x;
    const int wid = tid >> 5;
    const int lid = tid & 31;
    const int wm  = wid & 1;       // 0..1 -> 64 rows
    const int wn  = wid >> 1;      // 0..3 -> 32 cols

    const int brow = blockIdx.y;
    const int bcol = blockIdx.x;

    const __half* Ah = Ahi + (size_t)brow * 128 * K;
    const __half* Al = DUAL_A ? (Alo + (size_t)brow * 128 * K) : Ah;
    const __half* Bb = B   + (size_t)bcol * 128 * K;

    const uint32_t offA = (((lid >> 3) & 1) * 8 + (lid & 7)) * ROWB + (lid >> 4) * 16;
    const uint32_t offB = ((lid >> 4) * 8 + (lid & 7)) * ROWB + ((lid >> 3) & 1) * 16;

    float acc[4][4][4];
    #pragma unroll
    for (int i = 0; i < 4; ++i)
        #pragma unroll
        for (int j = 0; j < 4; ++j)
            #pragma unroll
            for (int e = 0; e < 4; ++e) acc[i][j][e] = 0.f;

    const int nch = K / 32;      // 32
    g3_issue<DUAL_A>(sb + 0 * STAGE, Ah, Al, Bb, 0, K, tid); CP_COMMIT();
    g3_issue<DUAL_A>(sb + 1 * STAGE, Ah, Al, Bb, 1, K, tid); CP_COMMIT();

    for (int kc = 0; kc < nch; ++kc) {
        if (kc + 1 < nch) { CP_WAIT(1); } else { CP_WAIT(0); }
        __syncthreads();

        const uint32_t cur  = sb + (kc % 3) * STAGE;
        const uint32_t aHiB = cur + wm * 64 * ROWB + offA;
        const uint32_t aLoB = cur + G3_AT + wm * 64 * ROWB + offA;
        const uint32_t bB   = cur + (1 + DUAL_A) * G3_AT + wn * 32 * ROWB + offB;

        #pragma unroll
        for (int k16 = 0; k16 < 2; ++k16) {
            const uint32_t ko = k16 * 32;

            uint32_t bf[8];
            #pragma unroll
            for (int nb = 0; nb < 2; ++nb)
                ldsm_x4(bf[nb*4], bf[nb*4+1], bf[nb*4+2], bf[nb*4+3],
                        bB + nb * 16 * ROWB + ko);

            #pragma unroll
            for (int mt = 0; mt < 4; ++mt) {
                uint32_t ah[4];
                ldsm_x4(ah[0], ah[1], ah[2], ah[3], aHiB + mt * 16 * ROWB + ko);
                #pragma unroll
                for (int nt = 0; nt < 4; ++nt)
                    mma16816(acc[mt][nt], ah[0], ah[1], ah[2], ah[3],
                             bf[nt * 2], bf[nt * 2 + 1]);
                if (DUAL_A) {
                    uint32_t al[4];
                    ldsm_x4(al[0], al[1], al[2], al[3], aLoB + mt * 16 * ROWB + ko);
                    #pragma unroll
                    for (int nt = 0; nt < 4; ++nt)
                        mma16816(acc[mt][nt], al[0], al[1], al[2], al[3],
                                 bf[nt * 2], bf[nt * 2 + 1]);
                }
            }
        }

        if (kc + 2 < nch) {
            g3_issue<DUAL_A>(sb + ((kc + 2) % 3) * STAGE, Ah, Al, Bb, kc + 2, K, tid);
            CP_COMMIT();
        }
    }

    if (MODE == 0) {
        // Plain fp32 epilogue
        const int r0 = brow * 128 + wm * 64 + (lid >> 2);
        const int c0 = bcol * 128 + wn * 32 + (lid & 3) * 2;
        #pragma unroll
        for (int mt = 0; mt < 4; ++mt) {
            #pragma unroll
            for (int nt = 0; nt < 4; ++nt) {
                float* p = C + (size_t)(r0 + mt * 16) * N + c0 + nt * 8;
                *(float2*)p                   = make_float2(acc[mt][nt][0], acc[mt][nt][1]);
                *(float2*)(p + (size_t)8 * N) = make_float2(acc[mt][nt][2], acc[mt][nt][3]);
            }
        }
    } else {
        // Fused QKV epilogue. CTA covers 128 cols = 2 heads; each warp's
        // 32-col block = half a head.
        const int section = bcol >> 3;                    // 0=Q 1=K 2=V
        const int head16  = (bcol & 7) * 2 + (wn >> 1);   // 0..15
        const int headg   = (brow >> 4) * NH + head16;
        const int s0      = ((brow * 128) & (SEQ - 1)) + wm * 64 + (lid >> 2);
        const int d0      = (wn & 1) * 32 + (lid & 3) * 2;
        #pragma unroll
        for (int mt = 0; mt < 4; ++mt) {
            #pragma unroll
            for (int nt = 0; nt < 4; ++nt) {
                int d = d0 + nt * 8;
                #pragma unroll
                for (int i = 0; i < 2; ++i) {
                    int s = s0 + mt * 16 + i * 8;
                    size_t idx = ((size_t)headg * SEQ + s) * HD + d;
                    float v0 = acc[mt][nt][2*i], v1 = acc[mt][nt][2*i+1];
                    if (section == 0) {
                        v0 *= 0.125f; v1 *= 0.125f;
                        __half2 hh = __floats2half2_rn(v0, v1);
                        float2 hf = __half22float2(hh);
                        __half2 ll = __floats2half2_rn(v0 - hf.x, v1 - hf.y);
                        *(__half2*)(g_q_hi + idx) = hh;
                        *(__half2*)(g_q_lo + idx) = ll;
                    } else if (section == 1) {
                        *(__half2*)(g_k + idx) = __floats2half2_rn(v0, v1);
                    } else {
                        *(__half2*)(g_v + idx) = __floats2half2_rn(v0, v1);
                    }
                }
            }
        }
    }
}

// ---------------------------------------------------------------------------
// HMMA flash attention, causal, double-buffered K/V.
// S = (Qhi+Qlo)@K^T (2-pass); PV single-pass (P rounded to fp16, in [0,1]).
// Epilogue writes hs hi/lo fp16 (fused split for the dual-A O-projection).
// ---------------------------------------------------------------------------
#define AROWB 144
#define SQ_HI   0
#define SQ_LO   18432
#define SK_BASE 36864
#define KVSTAGE 18432              // K(9216) + V(9216)
#define ATT_SMEM (SK_BASE + 2 * KVSTAGE)   // 73728
#define NEG_BIG (-1e30f)

__device__ __forceinline__ void att_issue_kv(
    uint32_t kvbase, const __half* __restrict__ Kk,
    const __half* __restrict__ Vv, int jt, int tid) {
    #pragma unroll
    for (int it = 0; it < 4; ++it) {
        int idx = it * 256 + tid;     // 0..1023
        int buf = idx >> 9;           // 0:K 1:V
        int rem = idx & 511;
        int r   = rem >> 3;
        int c8  = rem & 7;
        const __half* src = (buf ? Vv : Kk) + (size_t)(jt * 64 + r) * HD + c8 * 8;
        CP_ASYNC16(kvbase + buf * 9216 + r * AROWB + c8 * 16, src);
    }
}

__global__ __launch_bounds__(256, 2) void attn_mma() {
    extern __shared__ char smem[];
    const uint32_t sb = smem_u32(smem);

    const int tid = threadIdx.x;
    const int w   = tid >> 5;
    const int lid = tid & 31;
    const int qi  = gridDim.x - 1 - blockIdx.x;   // big tiles first
    const int h   = blockIdx.y;
    const int b   = blockIdx.z;
    const int head = b * NH + h;
    const int qbase = qi * 128;

    const __half* Qh = g_q_hi + ((size_t)head * SEQ + qbase) * HD;
    const __half* Ql = g_q_lo + ((size_t)head * SEQ + qbase) * HD;
    const __half* Kk = g_k + (size_t)head * SEQ * HD;
    const __half* Vv = g_v + (size_t)head * SEQ * HD;

    // Stage Q (hi+lo)
    #pragma unroll
    for (int it = 0; it < 8; ++it) {
        int idx  = it * 256 + tid;
        int prec = idx >> 10;
        int rem  = idx & 1023;
        int r    = rem >> 3;
        int c8   = rem & 7;
        const __half* src = (prec ? Ql : Qh) + (size_t)r * HD + c8 * 8;
        CP_ASYNC16(sb + (prec ? SQ_LO : SQ_HI) + r * AROWB + c8 * 16, src);
    }
    CP_COMMIT();

    const int ntiles = 2 * qi + 2;     // >= 2 always
    att_issue_kv(sb + SK_BASE + 0 * KVSTAGE, Kk, Vv, 0, tid);
    CP_COMMIT();
    att_issue_kv(sb + SK_BASE + 1 * KVSTAGE, Kk, Vv, 1, tid);
    CP_COMMIT();

    const uint32_t offA = (((lid >> 3) & 1) * 8 + (lid & 7)) * AROWB + (lid >> 4) * 16;
    const uint32_t offB = ((lid >> 4) * 8 + (lid & 7)) * AROWB + ((lid >> 3) & 1) * 16;
    const uint32_t qA_hi = sb + SQ_HI + w * 16 * AROWB + offA;
    const uint32_t qA_lo = sb + SQ_LO + w * 16 * AROWB + offA;

    float o[8][4];
    #pragma unroll
    for (int nt = 0; nt < 8; ++nt)
        #pragma unroll
        for (int e = 0; e < 4; ++e) o[nt][e] = 0.f;
    float m_i[2] = {NEG_BIG, NEG_BIG};
    float l_i[2] = {0.f, 0.f};

    for (int jt = 0; jt < ntiles; ++jt) {
        if (jt < ntiles - 1) { CP_WAIT(1); } else { CP_WAIT(0); }
        __syncthreads();

        const uint32_t kvb = sb + SK_BASE + (jt & 1) * KVSTAGE;

        // ---- S = Q @ K^T (2-pass: Q hi + Q lo) ----
        float s[8][4];
        #pragma unroll
        for (int nt = 0; nt < 8; ++nt)
            #pragma unroll
            for (int e = 0; e < 4; ++e) s[nt][e] = 0.f;

        #pragma unroll
        for (int kc = 0; kc < 4; ++kc) {
            const uint32_t ko = kc * 32;
            uint32_t ah[4], al[4];
            ldsm_x4(ah[0], ah[1], ah[2], ah[3], qA_hi + ko);
            ldsm_x4(al[0], al[1], al[2], al[3], qA_lo + ko);
            #pragma unroll
            for (int p = 0; p < 4; ++p) {
                uint32_t bk[4];
                ldsm_x4(bk[0], bk[1], bk[2], bk[3],
                        kvb + p * 16 * AROWB + offB + ko);
                #pragma unroll
                for (int half = 0; half < 2; ++half) {
                    int nt = p * 2 + half;
                    mma16816(s[nt], ah[0], ah[1], ah[2], ah[3],
                             bk[half * 2], bk[half * 2 + 1]);
                    mma16816(s[nt], al[0], al[1], al[2], al[3],
                             bk[half * 2], bk[half * 2 + 1]);
                }
            }
        }

        // ---- causal mask (diagonal tiles only) ----
        if (jt >= 2 * qi) {
            #pragma unroll
            for (int i = 0; i < 2; ++i) {
                int qg = qbase + w * 16 + (lid >> 2) + i * 8;
                #pragma unroll
                for (int nt = 0; nt < 8; ++nt) {
                    int kg = jt * 64 + nt * 8 + (lid & 3) * 2;
                    if (kg > qg)     s[nt][2*i]     = NEG_BIG;
                    if (kg + 1 > qg) s[nt][2*i + 1] = NEG_BIG;
                }
            }
        }

        // ---- online softmax (quad reductions) ----
        #pragma unroll
        for (int i = 0; i < 2; ++i) {
            float rm = NEG_BIG;
            #pragma unroll
            for (int nt = 0; nt < 8; ++nt)
                rm = fmaxf(rm, fmaxf(s[nt][2*i], s[nt][2*i+1]));
            rm = fmaxf(rm, __shfl_xor_sync(0xffffffffu, rm, 1));
            rm = fmaxf(rm, __shfl_xor_sync(0xffffffffu, rm, 2));
            float mnew = fmaxf(m_i[i], rm);
            float corr = __expf(m_i[i] - mnew);
            float rs = 0.f;
            #pragma unroll
            for (int nt = 0; nt < 8; ++nt) {
                float p0 = __expf(s[nt][2*i]     - mnew);
                float p1 = __expf(s[nt][2*i + 1] - mnew);
                s[nt][2*i] = p0; s[nt][2*i+1] = p1;
                rs += p0 + p1;
            }
            rs += __shfl_xor_sync(0xffffffffu, rs, 1);
            rs += __shfl_xor_sync(0xffffffffu, rs, 2);
            l_i[i] = l_i[i] * corr + rs;
            m_i[i] = mnew;
            #pragma unroll
            for (int nt = 0; nt < 8; ++nt) {
                o[nt][2*i]     *= corr;
                o[nt][2*i + 1] *= corr;
            }
        }

        // ---- O += P @ V (single-pass: P rounded fp16; V via ldsm.trans) ----
        #pragma unroll
        for (int kc = 0; kc < 4; ++kc) {
            uint32_t ph[4];
            ph[0] = pack_half2(s[2*kc][0],   s[2*kc][1]);
            ph[1] = pack_half2(s[2*kc][2],   s[2*kc][3]);
            ph[2] = pack_half2(s[2*kc+1][0], s[2*kc+1][1]);
            ph[3] = pack_half2(s[2*kc+1][2], s[2*kc+1][3]);

            // V tile rows = tokens kc*16..+15; trans loads give [d][k] frags
            const uint32_t vrow = kvb + 9216 +
                (kc * 16 + ((lid >> 3) & 1) * 8 + (lid & 7)) * AROWB +
                (lid >> 4) * 16;
            #pragma unroll
            for (int p = 0; p < 4; ++p) {
                uint32_t vf[4];
                ldsm_x4_t(vf[0], vf[1], vf[2], vf[3], vrow + p * 32);
                #pragma unroll
                for (int half = 0; half < 2; ++half) {
                    int nt = p * 2 + half;
                    mma16816(o[nt], ph[0], ph[1], ph[2], ph[3],
                             vf[half * 2], vf[half * 2 + 1]);
                }
            }
        }

        __syncthreads();   // all warps done reading buffer (jt&1)
        if (jt + 2 < ntiles) {
            att_issue_kv(sb + SK_BASE + (jt & 1) * KVSTAGE, Kk, Vv, jt + 2, tid);
            CP_COMMIT();
        }
    }

    // ---- epilogue: normalize, split to fp16 hi/lo, write hs (fused) ----
    #pragma unroll
    for (int i = 0; i < 2; ++i) {
        float inv = 1.f / l_i[i];
        int q = qbase + w * 16 + (lid >> 2) + i * 8;
        size_t rowidx = ((size_t)b * SEQ + q) * DMODEL + h * HD;
        #pragma unroll
        for (int nt = 0; nt < 8; ++nt) {
            int d = nt * 8 + (lid & 3) * 2;
            float v0 = o[nt][2*i] * inv, v1 = o[nt][2*i+1] * inv;
            __half2 hh = __floats2half2_rn(v0, v1);
            float2 hf = __half22float2(hh);
            __half2 ll = __floats2half2_rn(v0 - hf.x, v1 - hf.y);
            *(__half2*)(g_hs_hi + rowidx + d) = hh;
            *(__half2*)(g_hs_lo + rowidx + d) = ll;
        }
    }
}

// ---------------------------------------------------------------------------
// Launch
// ---------------------------------------------------------------------------
extern "C" void kernel_launch(void* const* d_in, const int* in_sizes, int n_in,
                              void* d_out, int out_size) {
    const float* x    = (const float*)d_in[0];  // [2,2048,1024]
    const float* Wqkv = (const float*)d_in[1];  // [3072,1024]
    const float* Wo   = (const float*)d_in[2];  // [1024,1024]
    float* out = (float*)d_out;                 // [2,2048,1024]

    __half *xs, *wq, *wo, *hs_hi, *hs_lo;
    cudaGetSymbolAddress((void**)&xs,    g_xs);
    cudaGetSymbolAddress((void**)&wq,    g_wq);
    cudaGetSymbolAddress((void**)&wo,    g_wo);
    cudaGetSymbolAddress((void**)&hs_hi, g_hs_hi);
    cudaGetSymbolAddress((void**)&hs_lo, g_hs_lo);

    constexpr int SMEM_A1 = 3 * (2 * G3_AT);   // DUAL_A=0: 61440
    constexpr int SMEM_A2 = 3 * (3 * G3_AT);   // DUAL_A=1: 92160

    static bool attr_done = false;
    if (!attr_done) {
        cudaFuncSetAttribute(gemm_fp16<1, 0>,
                             cudaFuncAttributeMaxDynamicSharedMemorySize, SMEM_A1);
        cudaFuncSetAttribute(gemm_fp16<0, 1>,
                             cudaFuncAttributeMaxDynamicSharedMemorySize, SMEM_A2);
        cudaFuncSetAttribute(attn_mma,
                             cudaFuncAttributeMaxDynamicSharedMemorySize, ATT_SMEM);
        attr_done = true;
    }

    const int n_x  = TOKENS * DMODEL;
    const int n_wq = 3 * DMODEL * DMODEL;
    const int n_wo = DMODEL * DMODEL;

    // Round / split operands
    round_fp16<<<n_x  / 2048, 256>>>(x, xs, n_x);
    round_fp16<<<n_wq / 2048, 256>>>(Wqkv, wq, n_wq);
    round_fp16<<<n_wo / 2048, 256>>>(Wo, wo, n_wo);

    // 1) QKV projection (single-pass A) with fused per-head split epilogue
    {
        dim3 grid(3 * DMODEL / 128, TOKENS / 128);   // (24, 32)
        gemm_fp16<1, 0><<<grid, GTHREADS, SMEM_A1>>>(xs, nullptr, wq, nullptr,
                                                     TOKENS, 3 * DMODEL, DMODEL);
    }
    // 2) HMMA causal flash attention -> g_hs_hi/lo (fused split epilogue)
    {
        dim3 grid(SEQ / 128, NH, BATCH);
        attn_mma<<<grid, 256, ATT_SMEM>>>();
    }
    // 3) Output projection (2-pass A: hs hi+lo) -> out (fp32)
    {
        dim3 grid(DMODEL / 128, TOKENS / 128);       // (8, 32)
        gemm_fp16<0, 1><<<grid, GTHREADS, SMEM_A2>>>(hs_hi, hs_lo, wo, out,
                                                     TOKENS, DMODEL, DMODEL);
    }
}

// round 12
// speedup vs baseline: 6.9627x; 1.1935x over previous
#include <cuda_runtime.h>
#include <cuda_fp16.h>
#include <cstdint>
#include <math.h>

// Problem constants (fixed by the reference)
#define BATCH   2
#define SEQ     2048
#define DMODEL  1024
#define NH      16
#define HD      64
#define TOKENS  (BATCH*SEQ)          // 4096
#define NHEADS_TOTAL (BATCH*NH)      // 32

// ---------------------------------------------------------------------------
// Scratch (__device__ globals; allocation in kernel_launch is forbidden)
// ---------------------------------------------------------------------------
__device__ __half g_xs  [(size_t)TOKENS * DMODEL];       // x rounded fp16
__device__ __half g_wq  [(size_t)3 * DMODEL * DMODEL];   // rounded fp16
__device__ __half g_wo  [(size_t)DMODEL * DMODEL];       // rounded fp16
__device__ __half g_hs  [(size_t)TOKENS * DMODEL];       // attention out fp16

// Per-head attention operands, all [head][s][64] natural layout
#define HEADELEMS ((size_t)NHEADS_TOTAL * SEQ * HD)
__device__ __half g_q  [HEADELEMS];
__device__ __half g_k  [HEADELEMS];
__device__ __half g_v  [HEADELEMS];

// ---------------------------------------------------------------------------
// PTX helpers (sm_80-era instructions only — compute_100-safe)
// ---------------------------------------------------------------------------
__device__ __forceinline__ uint32_t smem_u32(const void* p) {
    uint32_t a;
    asm("{ .reg .u64 t; cvta.to.shared.u64 t, %1; cvt.u32.u64 %0, t; }"
        : "=r"(a) : "l"(p));
    return a;
}

#define CP_ASYNC16(dst, src) \
    asm volatile("cp.async.cg.shared.global [%0], [%1], 16;" \
                 :: "r"(dst), "l"(src) : "memory")
#define CP_COMMIT() asm volatile("cp.async.commit_group;" ::: "memory")
#define CP_WAIT(N)  asm volatile("cp.async.wait_group %0;" :: "n"(N) : "memory")

__device__ __forceinline__ void ldsm_x4(uint32_t& r0, uint32_t& r1,
                                        uint32_t& r2, uint32_t& r3, uint32_t addr) {
    asm volatile("ldmatrix.sync.aligned.m8n8.x4.shared.b16 {%0,%1,%2,%3}, [%4];"
                 : "=r"(r0), "=r"(r1), "=r"(r2), "=r"(r3) : "r"(addr));
}

__device__ __forceinline__ void ldsm_x4_t(uint32_t& r0, uint32_t& r1,
                                          uint32_t& r2, uint32_t& r3, uint32_t addr) {
    asm volatile("ldmatrix.sync.aligned.m8n8.x4.trans.shared.b16 {%0,%1,%2,%3}, [%4];"
                 : "=r"(r0), "=r"(r1), "=r"(r2), "=r"(r3) : "r"(addr));
}

__device__ __forceinline__ void mma16816(float* c, uint32_t a0, uint32_t a1,
                                         uint32_t a2, uint32_t a3,
                                         uint32_t b0, uint32_t b1) {
    asm volatile(
        "mma.sync.aligned.m16n8k16.row.col.f32.f16.f16.f32 "
        "{%0,%1,%2,%3}, {%4,%5,%6,%7}, {%8,%9}, {%0,%1,%2,%3};"
        : "+f"(c[0]), "+f"(c[1]), "+f"(c[2]), "+f"(c[3])
        : "r"(a0), "r"(a1), "r"(a2), "r"(a3), "r"(b0), "r"(b1));
}

__device__ __forceinline__ uint32_t pack_half2(float a, float b) {
    __half2 h2 = __floats2half2_rn(a, b);
    return *(uint32_t*)&h2;
}

// round_fp16: fp32 -> fp16 (single rounding). n multiple of 2048.
__global__ __launch_bounds__(256) void round_fp16(const float* __restrict__ in,
                                                  __half* __restrict__ out, int n) {
    int base = (blockIdx.x * 256 + threadIdx.x) * 8;
    if (base >= n) return;
    float4 f0 = *(const float4*)(in + base);
    float4 f1 = *(const float4*)(in + base + 4);
    __half2 a = __floats2half2_rn(f0.x, f0.y);
    __half2 b = __floats2half2_rn(f0.z, f0.w);
    __half2 c = __floats2half2_rn(f1.x, f1.y);
    __half2 d = __floats2half2_rn(f1.z, f1.w);
    *(uint4*)(out + base) = make_uint4(*(uint32_t*)&a, *(uint32_t*)&b,
                                       *(uint32_t*)&c, *(uint32_t*)&d);
}

// ---------------------------------------------------------------------------
// fp16 warp-MMA GEMM: C = A[M,K] @ B[N,K]^T, single-pass fp16 operands.
// CTA tile 128x128, 8 warps x (64x32), K-chunk 32, 3-stage cp.async pipeline,
// 2 CTAs/SM.
// MODE 0: plain fp32 C store. MODE 1: fused per-head QKV epilogue.
// ---------------------------------------------------------------------------
#define ROWB 80                         // 32 fp16 (64B) + 16B pad
#define G3_AT (128 * ROWB)              // 10240 per tile (A or B)
#define G3_STAGE (2 * G3_AT)            // 20480
#define G3_SMEM (3 * G3_STAGE)          // 61440
#define GTHREADS 256

__device__ __forceinline__ void g3_issue(
    uint32_t stage, const __half* __restrict__ A, const __half* __restrict__ B,
    int kc, int K, int tid) {
    // A + B: 2 x 128 rows x 4 chunks = 1024 cp -> 4/thread
    #pragma unroll
    for (int i = 0; i < 4; ++i) {
        int idx = i * GTHREADS + tid;    // 0..1023
        int mat = idx >> 9;              // 0:A 1:B
        int rem = idx & 511;
        int row = rem >> 2;
        int c   = rem & 3;
        const __half* src = (mat ? B : A) + (size_t)row * K + kc * 32 + c * 8;
        CP_ASYNC16(stage + mat * G3_AT + row * ROWB + c * 16, src);
    }
}

template<int MODE>
__global__ __launch_bounds__(GTHREADS, 2) void gemm_fp16(
    const __half* __restrict__ A, const __half* __restrict__ B,
    float* __restrict__ C, int M, int N, int K) {
    extern __shared__ char smem[];
    const uint32_t sb = smem_u32(smem);

    const int tid = threadIdx.x;
    const int wid = tid >> 5;
    const int lid = tid & 31;
    const int wm  = wid & 1;       // 0..1 -> 64 rows
    const int wn  = wid >> 1;      // 0..3 -> 32 cols

    const int brow = blockIdx.y;
    const int bcol = blockIdx.x;

    const __half* Ab = A + (size_t)brow * 128 * K;
    const __half* Bb = B + (size_t)bcol * 128 * K;

    const uint32_t offA = (((lid >> 3) & 1) * 8 + (lid & 7)) * ROWB + (lid >> 4) * 16;
    const uint32_t offB = ((lid >> 4) * 8 + (lid & 7)) * ROWB + ((lid >> 3) & 1) * 16;

    float acc[4][4][4];
    #pragma unroll
    for (int i = 0; i < 4; ++i)
        #pragma unroll
        for (int j = 0; j < 4; ++j)
            #pragma unroll
            for (int e = 0; e < 4; ++e) acc[i][j][e] = 0.f;

    const int nch = K / 32;      // 32
    g3_issue(sb + 0 * G3_STAGE, Ab, Bb, 0, K, tid); CP_COMMIT();
    g3_issue(sb + 1 * G3_STAGE, Ab, Bb, 1, K, tid); CP_COMMIT();

    for (int kc = 0; kc < nch; ++kc) {
        if (kc + 1 < nch) { CP_WAIT(1); } else { CP_WAIT(0); }
        __syncthreads();

        const uint32_t cur  = sb + (kc % 3) * G3_STAGE;
        const uint32_t aB   = cur + wm * 64 * ROWB + offA;
        const uint32_t bB   = cur + G3_AT + wn * 32 * ROWB + offB;

        #pragma unroll
        for (int k16 = 0; k16 < 2; ++k16) {
            const uint32_t ko = k16 * 32;

            uint32_t bf[8];
            #pragma unroll
            for (int nb = 0; nb < 2; ++nb)
                ldsm_x4(bf[nb*4], bf[nb*4+1], bf[nb*4+2], bf[nb*4+3],
                        bB + nb * 16 * ROWB + ko);

            #pragma unroll
            for (int mt = 0; mt < 4; ++mt) {
                uint32_t ah[4];
                ldsm_x4(ah[0], ah[1], ah[2], ah[3], aB + mt * 16 * ROWB + ko);
                #pragma unroll
                for (int nt = 0; nt < 4; ++nt)
                    mma16816(acc[mt][nt], ah[0], ah[1], ah[2], ah[3],
                             bf[nt * 2], bf[nt * 2 + 1]);
            }
        }

        if (kc + 2 < nch) {
            g3_issue(sb + ((kc + 2) % 3) * G3_STAGE, Ab, Bb, kc + 2, K, tid);
            CP_COMMIT();
        }
    }

    if (MODE == 0) {
        // Plain fp32 epilogue
        const int r0 = brow * 128 + wm * 64 + (lid >> 2);
        const int c0 = bcol * 128 + wn * 32 + (lid & 3) * 2;
        #pragma unroll
        for (int mt = 0; mt < 4; ++mt) {
            #pragma unroll
            for (int nt = 0; nt < 4; ++nt) {
                float* p = C + (size_t)(r0 + mt * 16) * N + c0 + nt * 8;
                *(float2*)p                   = make_float2(acc[mt][nt][0], acc[mt][nt][1]);
                *(float2*)(p + (size_t)8 * N) = make_float2(acc[mt][nt][2], acc[mt][nt][3]);
            }
        }
    } else {
        // Fused QKV epilogue. CTA covers 128 cols = 2 heads; each warp's
        // 32-col block = half a head. Q scaled by 1/8; all single fp16.
        const int section = bcol >> 3;                    // 0=Q 1=K 2=V
        const int head16  = (bcol & 7) * 2 + (wn >> 1);   // 0..15
        const int headg   = (brow >> 4) * NH + head16;
        const int s0      = ((brow * 128) & (SEQ - 1)) + wm * 64 + (lid >> 2);
        const int d0      = (wn & 1) * 32 + (lid & 3) * 2;
        __half* dst = (section == 0) ? g_q : (section == 1) ? g_k : g_v;
        const float scale = (section == 0) ? 0.125f : 1.0f;
        #pragma unroll
        for (int mt = 0; mt < 4; ++mt) {
            #pragma unroll
            for (int nt = 0; nt < 4; ++nt) {
                int d = d0 + nt * 8;
                #pragma unroll
                for (int i = 0; i < 2; ++i) {
                    int s = s0 + mt * 16 + i * 8;
                    size_t idx = ((size_t)headg * SEQ + s) * HD + d;
                    *(__half2*)(dst + idx) = __floats2half2_rn(
                        acc[mt][nt][2*i] * scale, acc[mt][nt][2*i+1] * scale);
                }
            }
        }
    }
}

// ---------------------------------------------------------------------------
// HMMA flash attention, causal, double-buffered K/V. All single-pass fp16:
// S = Q@K^T (1 pass), PV (1 pass, P rounded fp16 in [0,1]).
// Epilogue writes hs single fp16.
// ---------------------------------------------------------------------------
#define AROWB 144
#define SQ_BASE 0
#define SK_BASE 18432
#define KVSTAGE 18432              // K(9216) + V(9216)
#define ATT_SMEM (SK_BASE + 2 * KVSTAGE)   // 55296
#define NEG_BIG (-1e30f)

__device__ __forceinline__ void att_issue_kv(
    uint32_t kvbase, const __half* __restrict__ Kk,
    const __half* __restrict__ Vv, int jt, int tid) {
    #pragma unroll
    for (int it = 0; it < 4; ++it) {
        int idx = it * 256 + tid;     // 0..1023
        int buf = idx >> 9;           // 0:K 1:V
        int rem = idx & 511;
        int r   = rem >> 3;
        int c8  = rem & 7;
        const __half* src = (buf ? Vv : Kk) + (size_t)(jt * 64 + r) * HD + c8 * 8;
        CP_ASYNC16(kvbase + buf * 9216 + r * AROWB + c8 * 16, src);
    }
}

__global__ __launch_bounds__(256, 2) void attn_mma() {
    extern __shared__ char smem[];
    const uint32_t sb = smem_u32(smem);

    const int tid = threadIdx.x;
    const int w   = tid >> 5;
    const int lid = tid & 31;
    const int qi  = gridDim.x - 1 - blockIdx.x;   // big tiles first
    const int h   = blockIdx.y;
    const int b   = blockIdx.z;
    const int head = b * NH + h;
    const int qbase = qi * 128;

    const __half* Qq = g_q + ((size_t)head * SEQ + qbase) * HD;
    const __half* Kk = g_k + (size_t)head * SEQ * HD;
    const __half* Vv = g_v + (size_t)head * SEQ * HD;

    // Stage Q: 128 rows x 8 chunks = 1024 cp -> 4/thread
    #pragma unroll
    for (int it = 0; it < 4; ++it) {
        int idx = it * 256 + tid;
        int r   = idx >> 3;
        int c8  = idx & 7;
        CP_ASYNC16(sb + SQ_BASE + r * AROWB + c8 * 16,
                   Qq + (size_t)r * HD + c8 * 8);
    }
    CP_COMMIT();

    const int ntiles = 2 * qi + 2;     // >= 2 always
    att_issue_kv(sb + SK_BASE + 0 * KVSTAGE, Kk, Vv, 0, tid);
    CP_COMMIT();
    att_issue_kv(sb + SK_BASE + 1 * KVSTAGE, Kk, Vv, 1, tid);
    CP_COMMIT();

    const uint32_t offA = (((lid >> 3) & 1) * 8 + (lid & 7)) * AROWB + (lid >> 4) * 16;
    const uint32_t offB = ((lid >> 4) * 8 + (lid & 7)) * AROWB + ((lid >> 3) & 1) * 16;
    const uint32_t qA = sb + SQ_BASE + w * 16 * AROWB + offA;

    float o[8][4];
    #pragma unroll
    for (int nt = 0; nt < 8; ++nt)
        #pragma unroll
        for (int e = 0; e < 4; ++e) o[nt][e] = 0.f;
    float m_i[2] = {NEG_BIG, NEG_BIG};
    float l_i[2] = {0.f, 0.f};

    for (int jt = 0; jt < ntiles; ++jt) {
        if (jt < ntiles - 1) { CP_WAIT(1); } else { CP_WAIT(0); }
        __syncthreads();

        const uint32_t kvb = sb + SK_BASE + (jt & 1) * KVSTAGE;

        // ---- S = Q @ K^T (single pass) ----
        float s[8][4];
        #pragma unroll
        for (int nt = 0; nt < 8; ++nt)
            #pragma unroll
            for (int e = 0; e < 4; ++e) s[nt][e] = 0.f;

        #pragma unroll
        for (int kc = 0; kc < 4; ++kc) {
            const uint32_t ko = kc * 32;
            uint32_t ah[4];
            ldsm_x4(ah[0], ah[1], ah[2], ah[3], qA + ko);
            #pragma unroll
            for (int p = 0; p < 4; ++p) {
                uint32_t bk[4];
                ldsm_x4(bk[0], bk[1], bk[2], bk[3],
                        kvb + p * 16 * AROWB + offB + ko);
                #pragma unroll
                for (int half = 0; half < 2; ++half) {
                    int nt = p * 2 + half;
                    mma16816(s[nt], ah[0], ah[1], ah[2], ah[3],
                             bk[half * 2], bk[half * 2 + 1]);
                }
            }
        }

        // ---- causal mask (diagonal tiles only) ----
        if (jt >= 2 * qi) {
            #pragma unroll
            for (int i = 0; i < 2; ++i) {
                int qg = qbase + w * 16 + (lid >> 2) + i * 8;
                #pragma unroll
                for (int nt = 0; nt < 8; ++nt) {
                    int kg = jt * 64 + nt * 8 + (lid & 3) * 2;
                    if (kg > qg)     s[nt][2*i]     = NEG_BIG;
                    if (kg + 1 > qg) s[nt][2*i + 1] = NEG_BIG;
                }
            }
        }

        // ---- online softmax (quad reductions) ----
        #pragma unroll
        for (int i = 0; i < 2; ++i) {
            float rm = NEG_BIG;
            #pragma unroll
            for (int nt = 0; nt < 8; ++nt)
                rm = fmaxf(rm, fmaxf(s[nt][2*i], s[nt][2*i+1]));
            rm = fmaxf(rm, __shfl_xor_sync(0xffffffffu, rm, 1));
            rm = fmaxf(rm, __shfl_xor_sync(0xffffffffu, rm, 2));
            float mnew = fmaxf(m_i[i], rm);
            float corr = __expf(m_i[i] - mnew);
            float rs = 0.f;
            #pragma unroll
            for (int nt = 0; nt < 8; ++nt) {
                float p0 = __expf(s[nt][2*i]     - mnew);
                float p1 = __expf(s[nt][2*i + 1] - mnew);
                s[nt][2*i] = p0; s[nt][2*i+1] = p1;
                rs += p0 + p1;
            }
            rs += __shfl_xor_sync(0xffffffffu, rs, 1);
            rs += __shfl_xor_sync(0xffffffffu, rs, 2);
            l_i[i] = l_i[i] * corr + rs;
            m_i[i] = mnew;
            #pragma unroll
            for (int nt = 0; nt < 8; ++nt) {
                o[nt][2*i]     *= corr;
                o[nt][2*i + 1] *= corr;
            }
        }

        // ---- O += P @ V (single pass; V via ldsm.trans) ----
        #pragma unroll
        for (int kc = 0; kc < 4; ++kc) {
            uint32_t ph[4];
            ph[0] = pack_half2(s[2*kc][0],   s[2*kc][1]);
            ph[1] = pack_half2(s[2*kc][2],   s[2*kc][3]);
            ph[2] = pack_half2(s[2*kc+1][0], s[2*kc+1][1]);
            ph[3] = pack_half2(s[2*kc+1][2], s[2*kc+1][3]);

            // V tile rows = tokens kc*16..+15; trans loads give [d][k] frags
            const uint32_t vrow = kvb + 9216 +
                (kc * 16 + ((lid >> 3) & 1) * 8 + (lid & 7)) * AROWB +
                (lid >> 4) * 16;
            #pragma unroll
            for (int p = 0; p < 4; ++p) {
                uint32_t vf[4];
                ldsm_x4_t(vf[0], vf[1], vf[2], vf[3], vrow + p * 32);
                #pragma unroll
                for (int half = 0; half < 2; ++half) {
                    int nt = p * 2 + half;
                    mma16816(o[nt], ph[0], ph[1], ph[2], ph[3],
                             vf[half * 2], vf[half * 2 + 1]);
                }
            }
        }

        __syncthreads();   // all warps done reading buffer (jt&1)
        if (jt + 2 < ntiles) {
            att_issue_kv(sb + SK_BASE + (jt & 1) * KVSTAGE, Kk, Vv, jt + 2, tid);
            CP_COMMIT();
        }
    }

    // ---- epilogue: normalize, round to fp16, write hs ----
    #pragma unroll
    for (int i = 0; i < 2; ++i) {
        float inv = 1.f / l_i[i];
        int q = qbase + w * 16 + (lid >> 2) + i * 8;
        size_t rowidx = ((size_t)b * SEQ + q) * DMODEL + h * HD;
        #pragma unroll
        for (int nt = 0; nt < 8; ++nt) {
            int d = nt * 8 + (lid & 3) * 2;
            *(__half2*)(g_hs + rowidx + d) =
                __floats2half2_rn(o[nt][2*i] * inv, o[nt][2*i+1] * inv);
        }
    }
}

// ---------------------------------------------------------------------------
// Launch
// ---------------------------------------------------------------------------
extern "C" void kernel_launch(void* const* d_in, const int* in_sizes, int n_in,
                              void* d_out, int out_size) {
    const float* x    = (const float*)d_in[0];  // [2,2048,1024]
    const float* Wqkv = (const float*)d_in[1];  // [3072,1024]
    const float* Wo   = (const float*)d_in[2];  // [1024,1024]
    float* out = (float*)d_out;                 // [2,2048,1024]

    __half *xs, *wq, *wo, *hs;
    cudaGetSymbolAddress((void**)&xs, g_xs);
    cudaGetSymbolAddress((void**)&wq, g_wq);
    cudaGetSymbolAddress((void**)&wo, g_wo);
    cudaGetSymbolAddress((void**)&hs, g_hs);

    static bool attr_done = false;
    if (!attr_done) {
        cudaFuncSetAttribute(gemm_fp16<1>,
                             cudaFuncAttributeMaxDynamicSharedMemorySize, G3_SMEM);
        cudaFuncSetAttribute(gemm_fp16<0>,
                             cudaFuncAttributeMaxDynamicSharedMemorySize, G3_SMEM);
        cudaFuncSetAttribute(attn_mma,
                             cudaFuncAttributeMaxDynamicSharedMemorySize, ATT_SMEM);
        attr_done = true;
    }

    const int n_x  = TOKENS * DMODEL;
    const int n_wq = 3 * DMODEL * DMODEL;
    const int n_wo = DMODEL * DMODEL;

    // Round operands to fp16
    round_fp16<<<n_x  / 2048, 256>>>(x, xs, n_x);
    round_fp16<<<n_wq / 2048, 256>>>(Wqkv, wq, n_wq);
    round_fp16<<<n_wo / 2048, 256>>>(Wo, wo, n_wo);

    // 1) QKV projection with fused per-head epilogue
    {
        dim3 grid(3 * DMODEL / 128, TOKENS / 128);   // (24, 32)
        gemm_fp16<1><<<grid, GTHREADS, G3_SMEM>>>(xs, wq, nullptr,
                                                  TOKENS, 3 * DMODEL, DMODEL);
    }
    // 2) HMMA causal flash attention -> g_hs (fp16)
    {
        dim3 grid(SEQ / 128, NH, BATCH);
        attn_mma<<<grid, 256, ATT_SMEM>>>();
    }
    // 3) Output projection -> out (fp32)
    {
        dim3 grid(DMODEL / 128, TOKENS / 128);       // (8, 32)
        gemm_fp16<0><<<grid, GTHREADS, G3_SMEM>>>(hs, wo, out,
                                                  TOKENS, DMODEL, DMODEL);
    }
}

// round 13
// speedup vs baseline: 7.3244x; 1.0519x over previous
#include <cuda_runtime.h>
#include <cuda_fp16.h>
#include <cstdint>
#include <math.h>

// Problem constants (fixed by the reference)
#define BATCH   2
#define SEQ     2048
#define DMODEL  1024
#define NH      16
#define HD      64
#define TOKENS  (BATCH*SEQ)          // 4096
#define NHEADS_TOTAL (BATCH*NH)      // 32

// ---------------------------------------------------------------------------
// Scratch (__device__ globals; allocation in kernel_launch is forbidden)
// ---------------------------------------------------------------------------
__device__ __half g_xs  [(size_t)TOKENS * DMODEL];       // x rounded fp16
__device__ __half g_wq  [(size_t)3 * DMODEL * DMODEL];   // rounded fp16
__device__ __half g_wo  [(size_t)DMODEL * DMODEL];       // rounded fp16
__device__ __half g_hs  [(size_t)TOKENS * DMODEL];       // attention out fp16

// Per-head attention operands, all [head][s][64] natural layout
#define HEADELEMS ((size_t)NHEADS_TOTAL * SEQ * HD)
__device__ __half g_q  [HEADELEMS];
__device__ __half g_k  [HEADELEMS];
__device__ __half g_v  [HEADELEMS];

// ---------------------------------------------------------------------------
// PTX helpers (sm_80-era instructions only — compute_100-safe)
// ---------------------------------------------------------------------------
__device__ __forceinline__ uint32_t smem_u32(const void* p) {
    uint32_t a;
    asm("{ .reg .u64 t; cvta.to.shared.u64 t, %1; cvt.u32.u64 %0, t; }"
        : "=r"(a) : "l"(p));
    return a;
}

#define CP_ASYNC16(dst, src) \
    asm volatile("cp.async.cg.shared.global [%0], [%1], 16;" \
                 :: "r"(dst), "l"(src) : "memory")
#define CP_COMMIT() asm volatile("cp.async.commit_group;" ::: "memory")
#define CP_WAIT(N)  asm volatile("cp.async.wait_group %0;" :: "n"(N) : "memory")

__device__ __forceinline__ void ldsm_x4(uint32_t& r0, uint32_t& r1,
                                        uint32_t& r2, uint32_t& r3, uint32_t addr) {
    asm volatile("ldmatrix.sync.aligned.m8n8.x4.shared.b16 {%0,%1,%2,%3}, [%4];"
                 : "=r"(r0), "=r"(r1), "=r"(r2), "=r"(r3) : "r"(addr));
}

__device__ __forceinline__ void ldsm_x4_t(uint32_t& r0, uint32_t& r1,
                                          uint32_t& r2, uint32_t& r3, uint32_t addr) {
    asm volatile("ldmatrix.sync.aligned.m8n8.x4.trans.shared.b16 {%0,%1,%2,%3}, [%4];"
                 : "=r"(r0), "=r"(r1), "=r"(r2), "=r"(r3) : "r"(addr));
}

__device__ __forceinline__ void mma16816(float* c, uint32_t a0, uint32_t a1,
                                         uint32_t a2, uint32_t a3,
                                         uint32_t b0, uint32_t b1) {
    asm volatile(
        "mma.sync.aligned.m16n8k16.row.col.f32.f16.f16.f32 "
        "{%0,%1,%2,%3}, {%4,%5,%6,%7}, {%8,%9}, {%0,%1,%2,%3};"
        : "+f"(c[0]), "+f"(c[1]), "+f"(c[2]), "+f"(c[3])
        : "r"(a0), "r"(a1), "r"(a2), "r"(a3), "r"(b0), "r"(b1));
}

__device__ __forceinline__ uint32_t pack_half2(float a, float b) {
    __half2 h2 = __floats2half2_rn(a, b);
    return *(uint32_t*)&h2;
}

// round_fp16: fp32 -> fp16 (single rounding). n multiple of 2048.
__global__ __launch_bounds__(256) void round_fp16(const float* __restrict__ in,
                                                  __half* __restrict__ out, int n) {
    int base = (blockIdx.x * 256 + threadIdx.x) * 8;
    if (base >= n) return;
    float4 f0 = *(const float4*)(in + base);
    float4 f1 = *(const float4*)(in + base + 4);
    __half2 a = __floats2half2_rn(f0.x, f0.y);
    __half2 b = __floats2half2_rn(f0.z, f0.w);
    __half2 c = __floats2half2_rn(f1.x, f1.y);
    __half2 d = __floats2half2_rn(f1.z, f1.w);
    *(uint4*)(out + base) = make_uint4(*(uint32_t*)&a, *(uint32_t*)&b,
                                       *(uint32_t*)&c, *(uint32_t*)&d);
}

// ---------------------------------------------------------------------------
// fp16 warp-MMA GEMM: C = A[M,K] @ B[N,K]^T, single-pass fp16 operands.
// CTA tile 128x128, 8 warps x (64x32), K-chunk 64 (half the sync frequency),
// 144-byte padded rows (conflict-free), 3-stage cp.async, 2 CTAs/SM.
// MODE 0: plain fp32 C store. MODE 1: fused per-head QKV epilogue.
// ---------------------------------------------------------------------------
#define GROWB 144                       // 64 fp16 (128B) + 16B pad
#define G4_T  (128 * GROWB)             // 18432 per tile (A or B)
#define G4_STAGE (2 * G4_T)             // 36864
#define G4_SMEM (3 * G4_STAGE)          // 110592
#define GTHREADS 256

__device__ __forceinline__ void g4_issue(
    uint32_t stage, const __half* __restrict__ A, const __half* __restrict__ B,
    int kc, int K, int tid) {
    // A + B: 2 x 128 rows x 8 chunks = 2048 cp -> 8/thread
    #pragma unroll
    for (int i = 0; i < 8; ++i) {
        int idx = i * GTHREADS + tid;    // 0..2047
        int mat = idx >> 10;             // 0:A 1:B
        int rem = idx & 1023;
        int row = rem >> 3;
        int c   = rem & 7;
        const __half* src = (mat ? B : A) + (size_t)row * K + kc * 64 + c * 8;
        CP_ASYNC16(stage + mat * G4_T + row * GROWB + c * 16, src);
    }
}

template<int MODE>
__global__ __launch_bounds__(GTHREADS, 2) void gemm_fp16(
    const __half* __restrict__ A, const __half* __restrict__ B,
    float* __restrict__ C, int M, int N, int K) {
    extern __shared__ char smem[];
    const uint32_t sb = smem_u32(smem);

    const int tid = threadIdx.x;
    const int wid = tid >> 5;
    const int lid = tid & 31;
    const int wm  = wid & 1;       // 0..1 -> 64 rows
    const int wn  = wid >> 1;      // 0..3 -> 32 cols

    const int brow = blockIdx.y;
    const int bcol = blockIdx.x;

    const __half* Ab = A + (size_t)brow * 128 * K;
    const __half* Bb = B + (size_t)bcol * 128 * K;

    const uint32_t offA = (((lid >> 3) & 1) * 8 + (lid & 7)) * GROWB + (lid >> 4) * 16;
    const uint32_t offB = ((lid >> 4) * 8 + (lid & 7)) * GROWB + ((lid >> 3) & 1) * 16;

    float acc[4][4][4];
    #pragma unroll
    for (int i = 0; i < 4; ++i)
        #pragma unroll
        for (int j = 0; j < 4; ++j)
            #pragma unroll
            for (int e = 0; e < 4; ++e) acc[i][j][e] = 0.f;

    const int nch = K / 64;      // 16
    g4_issue(sb + 0 * G4_STAGE, Ab, Bb, 0, K, tid); CP_COMMIT();
    g4_issue(sb + 1 * G4_STAGE, Ab, Bb, 1, K, tid); CP_COMMIT();

    for (int kc = 0; kc < nch; ++kc) {
        if (kc + 1 < nch) { CP_WAIT(1); } else { CP_WAIT(0); }
        __syncthreads();

        const uint32_t cur = sb + (kc % 3) * G4_STAGE;
        const uint32_t aB  = cur + wm * 64 * GROWB + offA;
        const uint32_t bB  = cur + G4_T + wn * 32 * GROWB + offB;

        #pragma unroll
        for (int k16 = 0; k16 < 4; ++k16) {
            const uint32_t ko = k16 * 32;

            uint32_t bf[8];
            #pragma unroll
            for (int nb = 0; nb < 2; ++nb)
                ldsm_x4(bf[nb*4], bf[nb*4+1], bf[nb*4+2], bf[nb*4+3],
                        bB + nb * 16 * GROWB + ko);

            #pragma unroll
            for (int mt = 0; mt < 4; ++mt) {
                uint32_t ah[4];
                ldsm_x4(ah[0], ah[1], ah[2], ah[3], aB + mt * 16 * GROWB + ko);
                #pragma unroll
                for (int nt = 0; nt < 4; ++nt)
                    mma16816(acc[mt][nt], ah[0], ah[1], ah[2], ah[3],
                             bf[nt * 2], bf[nt * 2 + 1]);
            }
        }

        if (kc + 2 < nch) {
            g4_issue(sb + ((kc + 2) % 3) * G4_STAGE, Ab, Bb, kc + 2, K, tid);
            CP_COMMIT();
        }
    }

    if (MODE == 0) {
        // Plain fp32 epilogue
        const int r0 = brow * 128 + wm * 64 + (lid >> 2);
        const int c0 = bcol * 128 + wn * 32 + (lid & 3) * 2;
        #pragma unroll
        for (int mt = 0; mt < 4; ++mt) {
            #pragma unroll
            for (int nt = 0; nt < 4; ++nt) {
                float* p = C + (size_t)(r0 + mt * 16) * N + c0 + nt * 8;
                *(float2*)p                   = make_float2(acc[mt][nt][0], acc[mt][nt][1]);
                *(float2*)(p + (size_t)8 * N) = make_float2(acc[mt][nt][2], acc[mt][nt][3]);
            }
        }
    } else {
        // Fused QKV epilogue. CTA covers 128 cols = 2 heads; each warp's
        // 32-col block = half a head. Q scaled by 1/8; all single fp16.
        const int section = bcol >> 3;                    // 0=Q 1=K 2=V
        const int head16  = (bcol & 7) * 2 + (wn >> 1);   // 0..15
        const int headg   = (brow >> 4) * NH + head16;
        const int s0      = ((brow * 128) & (SEQ - 1)) + wm * 64 + (lid >> 2);
        const int d0      = (wn & 1) * 32 + (lid & 3) * 2;
        __half* dst = (section == 0) ? g_q : (section == 1) ? g_k : g_v;
        const float scale = (section == 0) ? 0.125f : 1.0f;
        #pragma unroll
        for (int mt = 0; mt < 4; ++mt) {
            #pragma unroll
            for (int nt = 0; nt < 4; ++nt) {
                int d = d0 + nt * 8;
                #pragma unroll
                for (int i = 0; i < 2; ++i) {
                    int s = s0 + mt * 16 + i * 8;
                    size_t idx = ((size_t)headg * SEQ + s) * HD + d;
                    *(__half2*)(dst + idx) = __floats2half2_rn(
                        acc[mt][nt][2*i] * scale, acc[mt][nt][2*i+1] * scale);
                }
            }
        }
    }
}

// ---------------------------------------------------------------------------
// HMMA flash attention, causal, single-pass fp16.
// Each double-buffered stage now carries TWO 64-key sub-tiles (K+V for 128
// keys); inner body runs 2 sub-iterations per CP_WAIT/__syncthreads pair.
// ntiles64 = 2qi+2 is always even -> exactly (qi+1) pairs, no remainder.
// ---------------------------------------------------------------------------
#define AROWB 144
#define SQ_BASE 0
#define SK_BASE 18432
#define SUBT    18432              // one sub-tile: K(9216) + V(9216)
#define KVSTAGE (2 * SUBT)         // 36864: 128 keys
#define ATT_SMEM (SK_BASE + 2 * KVSTAGE)   // 92160
#define NEG_BIG (-1e30f)

// Load one PAIR of 64-key sub-tiles (128 keys of K and V) into kvbase.
__device__ __forceinline__ void att_issue_pair(
    uint32_t kvbase, const __half* __restrict__ Kk,
    const __half* __restrict__ Vv, int jp, int tid) {
    #pragma unroll
    for (int it = 0; it < 8; ++it) {
        int idx = it * 256 + tid;     // 0..2047
        int sub = idx >> 10;          // 0,1
        int rem = idx & 1023;
        int buf = rem >> 9;           // 0:K 1:V
        int r2  = rem & 511;
        int r   = r2 >> 3;
        int c8  = r2 & 7;
        int key = jp * 128 + sub * 64 + r;
        const __half* src = (buf ? Vv : Kk) + (size_t)key * HD + c8 * 8;
        CP_ASYNC16(kvbase + sub * SUBT + buf * 9216 + r * AROWB + c8 * 16, src);
    }
}

__global__ __launch_bounds__(256, 2) void attn_mma() {
    extern __shared__ char smem[];
    const uint32_t sb = smem_u32(smem);

    const int tid = threadIdx.x;
    const int w   = tid >> 5;
    const int lid = tid & 31;
    const int qi  = gridDim.x - 1 - blockIdx.x;   // big tiles first
    const int h   = blockIdx.y;
    const int b   = blockIdx.z;
    const int head = b * NH + h;
    const int qbase = qi * 128;

    const __half* Qq = g_q + ((size_t)head * SEQ + qbase) * HD;
    const __half* Kk = g_k + (size_t)head * SEQ * HD;
    const __half* Vv = g_v + (size_t)head * SEQ * HD;

    // Stage Q: 128 rows x 8 chunks = 1024 cp -> 4/thread
    #pragma unroll
    for (int it = 0; it < 4; ++it) {
        int idx = it * 256 + tid;
        int r   = idx >> 3;
        int c8  = idx & 7;
        CP_ASYNC16(sb + SQ_BASE + r * AROWB + c8 * 16,
                   Qq + (size_t)r * HD + c8 * 8);
    }
    CP_COMMIT();

    const int npairs = qi + 1;         // pairs of 64-key tiles
    att_issue_pair(sb + SK_BASE + 0 * KVSTAGE, Kk, Vv, 0, tid);
    CP_COMMIT();
    att_issue_pair(sb + SK_BASE + 1 * KVSTAGE, Kk, Vv, 1, tid);
    CP_COMMIT();

    const uint32_t offA = (((lid >> 3) & 1) * 8 + (lid & 7)) * AROWB + (lid >> 4) * 16;
    const uint32_t offB = ((lid >> 4) * 8 + (lid & 7)) * AROWB + ((lid >> 3) & 1) * 16;
    const uint32_t qA = sb + SQ_BASE + w * 16 * AROWB + offA;

    float o[8][4];
    #pragma unroll
    for (int nt = 0; nt < 8; ++nt)
        #pragma unroll
        for (int e = 0; e < 4; ++e) o[nt][e] = 0.f;
    float m_i[2] = {NEG_BIG, NEG_BIG};
    float l_i[2] = {0.f, 0.f};

    for (int jp = 0; jp < npairs; ++jp) {
        if (jp < npairs - 1) { CP_WAIT(1); } else { CP_WAIT(0); }
        __syncthreads();

        const uint32_t pairb = sb + SK_BASE + (jp & 1) * KVSTAGE;

        #pragma unroll
        for (int sub = 0; sub < 2; ++sub) {
            const int jt = jp * 2 + sub;          // 64-key tile index
            const uint32_t kvb = pairb + sub * SUBT;

            // ---- S = Q @ K^T (single pass) ----
            float s[8][4];
            #pragma unroll
            for (int nt = 0; nt < 8; ++nt)
                #pragma unroll
                for (int e = 0; e < 4; ++e) s[nt][e] = 0.f;

            #pragma unroll
            for (int kc = 0; kc < 4; ++kc) {
                const uint32_t ko = kc * 32;
                uint32_t ah[4];
                ldsm_x4(ah[0], ah[1], ah[2], ah[3], qA + ko);
                #pragma unroll
                for (int p = 0; p < 4; ++p) {
                    uint32_t bk[4];
                    ldsm_x4(bk[0], bk[1], bk[2], bk[3],
                            kvb + p * 16 * AROWB + offB + ko);
                    #pragma unroll
                    for (int half = 0; half < 2; ++half) {
                        int nt = p * 2 + half;
                        mma16816(s[nt], ah[0], ah[1], ah[2], ah[3],
                                 bk[half * 2], bk[half * 2 + 1]);
                    }
                }
            }

            // ---- causal mask (diagonal tiles only) ----
            if (jt >= 2 * qi) {
                #pragma unroll
                for (int i = 0; i < 2; ++i) {
                    int qg = qbase + w * 16 + (lid >> 2) + i * 8;
                    #pragma unroll
                    for (int nt = 0; nt < 8; ++nt) {
                        int kg = jt * 64 + nt * 8 + (lid & 3) * 2;
                        if (kg > qg)     s[nt][2*i]     = NEG_BIG;
                        if (kg + 1 > qg) s[nt][2*i + 1] = NEG_BIG;
                    }
                }
            }

            // ---- online softmax (quad reductions) ----
            #pragma unroll
            for (int i = 0; i < 2; ++i) {
                float rm = NEG_BIG;
                #pragma unroll
                for (int nt = 0; nt < 8; ++nt)
                    rm = fmaxf(rm, fmaxf(s[nt][2*i], s[nt][2*i+1]));
                rm = fmaxf(rm, __shfl_xor_sync(0xffffffffu, rm, 1));
                rm = fmaxf(rm, __shfl_xor_sync(0xffffffffu, rm, 2));
                float mnew = fmaxf(m_i[i], rm);
                float corr = __expf(m_i[i] - mnew);
                float rs = 0.f;
                #pragma unroll
                for (int nt = 0; nt < 8; ++nt) {
                    float p0 = __expf(s[nt][2*i]     - mnew);
                    float p1 = __expf(s[nt][2*i + 1] - mnew);
                    s[nt][2*i] = p0; s[nt][2*i+1] = p1;
                    rs += p0 + p1;
                }
                rs += __shfl_xor_sync(0xffffffffu, rs, 1);
                rs += __shfl_xor_sync(0xffffffffu, rs, 2);
                l_i[i] = l_i[i] * corr + rs;
                m_i[i] = mnew;
                #pragma unroll
                for (int nt = 0; nt < 8; ++nt) {
                    o[nt][2*i]     *= corr;
                    o[nt][2*i + 1] *= corr;
                }
            }

            // ---- O += P @ V (single pass; V via ldsm.trans) ----
            #pragma unroll
            for (int kc = 0; kc < 4; ++kc) {
                uint32_t ph[4];
                ph[0] = pack_half2(s[2*kc][0],   s[2*kc][1]);
                ph[1] = pack_half2(s[2*kc][2],   s[2*kc][3]);
                ph[2] = pack_half2(s[2*kc+1][0], s[2*kc+1][1]);
                ph[3] = pack_half2(s[2*kc+1][2], s[2*kc+1][3]);

                const uint32_t vrow = kvb + 9216 +
                    (kc * 16 + ((lid >> 3) & 1) * 8 + (lid & 7)) * AROWB +
                    (lid >> 4) * 16;
                #pragma unroll
                for (int p = 0; p < 4; ++p) {
                    uint32_t vf[4];
                    ldsm_x4_t(vf[0], vf[1], vf[2], vf[3], vrow + p * 32);
                    #pragma unroll
                    for (int half = 0; half < 2; ++half) {
                        int nt = p * 2 + half;
                        mma16816(o[nt], ph[0], ph[1], ph[2], ph[3],
                                 vf[half * 2], vf[half * 2 + 1]);
                    }
                }
            }
        }

        __syncthreads();   // all warps done reading buffer (jp&1)
        if (jp + 2 < npairs) {
            att_issue_pair(sb + SK_BASE + (jp & 1) * KVSTAGE, Kk, Vv, jp + 2, tid);
            CP_COMMIT();
        }
    }

    // ---- epilogue: normalize, round to fp16, write hs ----
    #pragma unroll
    for (int i = 0; i < 2; ++i) {
        float inv = 1.f / l_i[i];
        int q = qbase + w * 16 + (lid >> 2) + i * 8;
        size_t rowidx = ((size_t)b * SEQ + q) * DMODEL + h * HD;
        #pragma unroll
        for (int nt = 0; nt < 8; ++nt) {
            int d = nt * 8 + (lid & 3) * 2;
            *(__half2*)(g_hs + rowidx + d) =
                __floats2half2_rn(o[nt][2*i] * inv, o[nt][2*i+1] * inv);
        }
    }
}

// ---------------------------------------------------------------------------
// Launch
// ---------------------------------------------------------------------------
extern "C" void kernel_launch(void* const* d_in, const int* in_sizes, int n_in,
                              void* d_out, int out_size) {
    const float* x    = (const float*)d_in[0];  // [2,2048,1024]
    const float* Wqkv = (const float*)d_in[1];  // [3072,1024]
    const float* Wo   = (const float*)d_in[2];  // [1024,1024]
    float* out = (float*)d_out;                 // [2,2048,1024]

    __half *xs, *wq, *wo, *hs;
    cudaGetSymbolAddress((void**)&xs, g_xs);
    cudaGetSymbolAddress((void**)&wq, g_wq);
    cudaGetSymbolAddress((void**)&wo, g_wo);
    cudaGetSymbolAddress((void**)&hs, g_hs);

    static bool attr_done = false;
    if (!attr_done) {
        cudaFuncSetAttribute(gemm_fp16<1>,
                             cudaFuncAttributeMaxDynamicSharedMemorySize, G4_SMEM);
        cudaFuncSetAttribute(gemm_fp16<0>,
                             cudaFuncAttributeMaxDynamicSharedMemorySize, G4_SMEM);
        cudaFuncSetAttribute(attn_mma,
                             cudaFuncAttributeMaxDynamicSharedMemorySize, ATT_SMEM);
        attr_done = true;
    }

    const int n_x  = TOKENS * DMODEL;
    const int n_wq = 3 * DMODEL * DMODEL;
    const int n_wo = DMODEL * DMODEL;

    // Round operands to fp16
    round_fp16<<<n_x  / 2048, 256>>>(x, xs, n_x);
    round_fp16<<<n_wq / 2048, 256>>>(Wqkv, wq, n_wq);
    round_fp16<<<n_wo / 2048, 256>>>(Wo, wo, n_wo);

    // 1) QKV projection with fused per-head epilogue
    {
        dim3 grid(3 * DMODEL / 128, TOKENS / 128);   // (24, 32)
        gemm_fp16<1><<<grid, GTHREADS, G4_SMEM>>>(xs, wq, nullptr,
                                                  TOKENS, 3 * DMODEL, DMODEL);
    }
    // 2) HMMA causal flash attention -> g_hs (fp16)
    {
        dim3 grid(SEQ / 128, NH, BATCH);
        attn_mma<<<grid, 256, ATT_SMEM>>>();
    }
    // 3) Output projection -> out (fp32)
    {
        dim3 grid(DMODEL / 128, TOKENS / 128);       // (8, 32)
        gemm_fp16<0><<<grid, GTHREADS, G4_SMEM>>>(hs, wo, out,
                                                  TOKENS, DMODEL, DMODEL);
    }
}

// round 14
// speedup vs baseline: 7.5224x; 1.0270x over previous
#include <cuda_runtime.h>
#include <cuda_fp16.h>
#include <cstdint>
#include <math.h>

// Problem constants (fixed by the reference)
#define BATCH   2
#define SEQ     2048
#define DMODEL  1024
#define NH      16
#define HD      64
#define TOKENS  (BATCH*SEQ)          // 4096
#define NHEADS_TOTAL (BATCH*NH)      // 32

// ---------------------------------------------------------------------------
// Scratch (__device__ globals; allocation in kernel_launch is forbidden)
// ---------------------------------------------------------------------------
__device__ __half g_xs  [(size_t)TOKENS * DMODEL];       // x rounded fp16
__device__ __half g_wq  [(size_t)3 * DMODEL * DMODEL];   // rounded fp16
__device__ __half g_wo  [(size_t)DMODEL * DMODEL];       // rounded fp16
__device__ __half g_hs  [(size_t)TOKENS * DMODEL];       // attention out fp16

// Per-head attention operands, all [head][s][64] natural layout
#define HEADELEMS ((size_t)NHEADS_TOTAL * SEQ * HD)
__device__ __half g_q  [HEADELEMS];
__device__ __half g_k  [HEADELEMS];
__device__ __half g_v  [HEADELEMS];

// ---------------------------------------------------------------------------
// PTX helpers (sm_80-era instructions only — compute_100-safe)
// ---------------------------------------------------------------------------
__device__ __forceinline__ uint32_t smem_u32(const void* p) {
    uint32_t a;
    asm("{ .reg .u64 t; cvta.to.shared.u64 t, %1; cvt.u32.u64 %0, t; }"
        : "=r"(a) : "l"(p));
    return a;
}

#define CP_ASYNC16(dst, src) \
    asm volatile("cp.async.cg.shared.global [%0], [%1], 16;" \
                 :: "r"(dst), "l"(src) : "memory")
#define CP_COMMIT() asm volatile("cp.async.commit_group;" ::: "memory")
#define CP_WAIT(N)  asm volatile("cp.async.wait_group %0;" :: "n"(N) : "memory")

__device__ __forceinline__ void ldsm_x4(uint32_t& r0, uint32_t& r1,
                                        uint32_t& r2, uint32_t& r3, uint32_t addr) {
    asm volatile("ldmatrix.sync.aligned.m8n8.x4.shared.b16 {%0,%1,%2,%3}, [%4];"
                 : "=r"(r0), "=r"(r1), "=r"(r2), "=r"(r3) : "r"(addr));
}

__device__ __forceinline__ void ldsm_x4_t(uint32_t& r0, uint32_t& r1,
                                          uint32_t& r2, uint32_t& r3, uint32_t addr) {
    asm volatile("ldmatrix.sync.aligned.m8n8.x4.trans.shared.b16 {%0,%1,%2,%3}, [%4];"
                 : "=r"(r0), "=r"(r1), "=r"(r2), "=r"(r3) : "r"(addr));
}

__device__ __forceinline__ void mma16816(float* c, uint32_t a0, uint32_t a1,
                                         uint32_t a2, uint32_t a3,
                                         uint32_t b0, uint32_t b1) {
    asm volatile(
        "mma.sync.aligned.m16n8k16.row.col.f32.f16.f16.f32 "
        "{%0,%1,%2,%3}, {%4,%5,%6,%7}, {%8,%9}, {%0,%1,%2,%3};"
        : "+f"(c[0]), "+f"(c[1]), "+f"(c[2]), "+f"(c[3])
        : "r"(a0), "r"(a1), "r"(a2), "r"(a3), "r"(b0), "r"(b1));
}

__device__ __forceinline__ uint32_t pack_half2(float a, float b) {
    __half2 h2 = __floats2half2_rn(a, b);
    return *(uint32_t*)&h2;
}

// ---------------------------------------------------------------------------
// round_all: one launch rounds x, Wqkv, Wo to fp16.
// Block ranges: [0,2048) -> x (4M elems), [2048,3584) -> Wqkv (3M),
// [3584,4096) -> Wo (1M). 2048 elems per block.
// ---------------------------------------------------------------------------
__global__ __launch_bounds__(256) void round_all(
    const float* __restrict__ x, const float* __restrict__ wq_f,
    const float* __restrict__ wo_f) {
    int bid = blockIdx.x;
    const float* in;
    __half* out;
    int blk;
    if (bid < 2048)      { in = x;    out = g_xs; blk = bid; }
    else if (bid < 3584) { in = wq_f; out = g_wq; blk = bid - 2048; }
    else                 { in = wo_f; out = g_wo; blk = bid - 3584; }
    int base = (blk * 256 + threadIdx.x) * 8;
    float4 f0 = *(const float4*)(in + base);
    float4 f1 = *(const float4*)(in + base + 4);
    __half2 a = __floats2half2_rn(f0.x, f0.y);
    __half2 b = __floats2half2_rn(f0.z, f0.w);
    __half2 c = __floats2half2_rn(f1.x, f1.y);
    __half2 d = __floats2half2_rn(f1.z, f1.w);
    *(uint4*)(out + base) = make_uint4(*(uint32_t*)&a, *(uint32_t*)&b,
                                       *(uint32_t*)&c, *(uint32_t*)&d);
}

// ---------------------------------------------------------------------------
// fp16 warp-MMA GEMM: C = A[M,K] @ B[N,K]^T, single-pass fp16 operands.
// CTA tile 128x128, 8 warps x (64x32), K-chunk 64, 144B padded rows,
// 3-stage cp.async, 2 CTAs/SM. A-fragment software prefetch (mt+1 issued
// before mt's MMAs) to widen the LDSM->HMMA dependency window.
// MODE 0: plain fp32 C store. MODE 1: fused per-head QKV epilogue.
// ---------------------------------------------------------------------------
#define GROWB 144                       // 64 fp16 (128B) + 16B pad
#define G4_T  (128 * GROWB)             // 18432 per tile (A or B)
#define G4_STAGE (2 * G4_T)             // 36864
#define G4_SMEM (3 * G4_STAGE)          // 110592
#define GTHREADS 256

__device__ __forceinline__ void g4_issue(
    uint32_t stage, const __half* __restrict__ A, const __half* __restrict__ B,
    int kc, int K, int tid) {
    #pragma unroll
    for (int i = 0; i < 8; ++i) {
        int idx = i * GTHREADS + tid;    // 0..2047
        int mat = idx >> 10;             // 0:A 1:B
        int rem = idx & 1023;
        int row = rem >> 3;
        int c   = rem & 7;
        const __half* src = (mat ? B : A) + (size_t)row * K + kc * 64 + c * 8;
        CP_ASYNC16(stage + mat * G4_T + row * GROWB + c * 16, src);
    }
}

template<int MODE>
__global__ __launch_bounds__(GTHREADS, 2) void gemm_fp16(
    const __half* __restrict__ A, const __half* __restrict__ B,
    float* __restrict__ C, int M, int N, int K) {
    extern __shared__ char smem[];
    const uint32_t sb = smem_u32(smem);

    const int tid = threadIdx.x;
    const int wid = tid >> 5;
    const int lid = tid & 31;
    const int wm  = wid & 1;       // 0..1 -> 64 rows
    const int wn  = wid >> 1;      // 0..3 -> 32 cols

    const int brow = blockIdx.y;
    const int bcol = blockIdx.x;

    const __half* Ab = A + (size_t)brow * 128 * K;
    const __half* Bb = B + (size_t)bcol * 128 * K;

    const uint32_t offA = (((lid >> 3) & 1) * 8 + (lid & 7)) * GROWB + (lid >> 4) * 16;
    const uint32_t offB = ((lid >> 4) * 8 + (lid & 7)) * GROWB + ((lid >> 3) & 1) * 16;

    float acc[4][4][4];
    #pragma unroll
    for (int i = 0; i < 4; ++i)
        #pragma unroll
        for (int j = 0; j < 4; ++j)
            #pragma unroll
            for (int e = 0; e < 4; ++e) acc[i][j][e] = 0.f;

    const int nch = K / 64;      // 16
    g4_issue(sb + 0 * G4_STAGE, Ab, Bb, 0, K, tid); CP_COMMIT();
    g4_issue(sb + 1 * G4_STAGE, Ab, Bb, 1, K, tid); CP_COMMIT();

    for (int kc = 0; kc < nch; ++kc) {
        if (kc + 1 < nch) { CP_WAIT(1); } else { CP_WAIT(0); }
        __syncthreads();

        const uint32_t cur = sb + (kc % 3) * G4_STAGE;
        const uint32_t aB  = cur + wm * 64 * GROWB + offA;
        const uint32_t bB  = cur + G4_T + wn * 32 * GROWB + offB;

        #pragma unroll
        for (int k16 = 0; k16 < 4; ++k16) {
            const uint32_t ko = k16 * 32;

            uint32_t bf[8];
            #pragma unroll
            for (int nb = 0; nb < 2; ++nb)
                ldsm_x4(bf[nb*4], bf[nb*4+1], bf[nb*4+2], bf[nb*4+3],
                        bB + nb * 16 * GROWB + ko);

            // A prefetch: issue ldsm for mt+1 before mt's MMAs
            uint32_t acur[4], anxt[4];
            ldsm_x4(acur[0], acur[1], acur[2], acur[3], aB + ko);
            #pragma unroll
            for (int mt = 0; mt < 4; ++mt) {
                if (mt < 3)
                    ldsm_x4(anxt[0], anxt[1], anxt[2], anxt[3],
                            aB + (mt + 1) * 16 * GROWB + ko);
                #pragma unroll
                for (int nt = 0; nt < 4; ++nt)
                    mma16816(acc[mt][nt], acur[0], acur[1], acur[2], acur[3],
                             bf[nt * 2], bf[nt * 2 + 1]);
                #pragma unroll
                for (int e = 0; e < 4; ++e) acur[e] = anxt[e];
            }
        }

        if (kc + 2 < nch) {
            g4_issue(sb + ((kc + 2) % 3) * G4_STAGE, Ab, Bb, kc + 2, K, tid);
            CP_COMMIT();
        }
    }

    if (MODE == 0) {
        // Plain fp32 epilogue
        const int r0 = brow * 128 + wm * 64 + (lid >> 2);
        const int c0 = bcol * 128 + wn * 32 + (lid & 3) * 2;
        #pragma unroll
        for (int mt = 0; mt < 4; ++mt) {
            #pragma unroll
            for (int nt = 0; nt < 4; ++nt) {
                float* p = C + (size_t)(r0 + mt * 16) * N + c0 + nt * 8;
                *(float2*)p                   = make_float2(acc[mt][nt][0], acc[mt][nt][1]);
                *(float2*)(p + (size_t)8 * N) = make_float2(acc[mt][nt][2], acc[mt][nt][3]);
            }
        }
    } else {
        // Fused QKV epilogue. CTA covers 128 cols = 2 heads; each warp's
        // 32-col block = half a head. Q scaled by 1/8; all single fp16.
        const int section = bcol >> 3;                    // 0=Q 1=K 2=V
        const int head16  = (bcol & 7) * 2 + (wn >> 1);   // 0..15
        const int headg   = (brow >> 4) * NH + head16;
        const int s0      = ((brow * 128) & (SEQ - 1)) + wm * 64 + (lid >> 2);
        const int d0      = (wn & 1) * 32 + (lid & 3) * 2;
        __half* dst = (section == 0) ? g_q : (section == 1) ? g_k : g_v;
        const float scale = (section == 0) ? 0.125f : 1.0f;
        #pragma unroll
        for (int mt = 0; mt < 4; ++mt) {
            #pragma unroll
            for (int nt = 0; nt < 4; ++nt) {
                int d = d0 + nt * 8;
                #pragma unroll
                for (int i = 0; i < 2; ++i) {
                    int s = s0 + mt * 16 + i * 8;
                    size_t idx = ((size_t)headg * SEQ + s) * HD + d;
                    *(__half2*)(dst + idx) = __floats2half2_rn(
                        acc[mt][nt][2*i] * scale, acc[mt][nt][2*i+1] * scale);
                }
            }
        }
    }
}

// ---------------------------------------------------------------------------
// HMMA flash attention, causal, single-pass fp16. Stages carry two 64-key
// sub-tiles per CP_WAIT/__syncthreads pair; Q fragment prefetched across kc.
// ---------------------------------------------------------------------------
#define AROWB 144
#define SQ_BASE 0
#define SK_BASE 18432
#define SUBT    18432              // one sub-tile: K(9216) + V(9216)
#define KVSTAGE (2 * SUBT)         // 36864: 128 keys
#define ATT_SMEM (SK_BASE + 2 * KVSTAGE)   // 92160
#define NEG_BIG (-1e30f)

// Load one PAIR of 64-key sub-tiles (128 keys of K and V) into kvbase.
__device__ __forceinline__ void att_issue_pair(
    uint32_t kvbase, const __half* __restrict__ Kk,
    const __half* __restrict__ Vv, int jp, int tid) {
    #pragma unroll
    for (int it = 0; it < 8; ++it) {
        int idx = it * 256 + tid;     // 0..2047
        int sub = idx >> 10;          // 0,1
        int rem = idx & 1023;
        int buf = rem >> 9;           // 0:K 1:V
        int r2  = rem & 511;
        int r   = r2 >> 3;
        int c8  = r2 & 7;
        int key = jp * 128 + sub * 64 + r;
        const __half* src = (buf ? Vv : Kk) + (size_t)key * HD + c8 * 8;
        CP_ASYNC16(kvbase + sub * SUBT + buf * 9216 + r * AROWB + c8 * 16, src);
    }
}

__global__ __launch_bounds__(256, 2) void attn_mma() {
    extern __shared__ char smem[];
    const uint32_t sb = smem_u32(smem);

    const int tid = threadIdx.x;
    const int w   = tid >> 5;
    const int lid = tid & 31;
    const int qi  = gridDim.x - 1 - blockIdx.x;   // big tiles first
    const int h   = blockIdx.y;
    const int b   = blockIdx.z;
    const int head = b * NH + h;
    const int qbase = qi * 128;

    const __half* Qq = g_q + ((size_t)head * SEQ + qbase) * HD;
    const __half* Kk = g_k + (size_t)head * SEQ * HD;
    const __half* Vv = g_v + (size_t)head * SEQ * HD;

    // Stage Q: 128 rows x 8 chunks = 1024 cp -> 4/thread
    #pragma unroll
    for (int it = 0; it < 4; ++it) {
        int idx = it * 256 + tid;
        int r   = idx >> 3;
        int c8  = idx & 7;
        CP_ASYNC16(sb + SQ_BASE + r * AROWB + c8 * 16,
                   Qq + (size_t)r * HD + c8 * 8);
    }
    CP_COMMIT();

    const int npairs = qi + 1;         // pairs of 64-key tiles
    att_issue_pair(sb + SK_BASE + 0 * KVSTAGE, Kk, Vv, 0, tid);
    CP_COMMIT();
    att_issue_pair(sb + SK_BASE + 1 * KVSTAGE, Kk, Vv, 1, tid);
    CP_COMMIT();

    const uint32_t offA = (((lid >> 3) & 1) * 8 + (lid & 7)) * AROWB + (lid >> 4) * 16;
    const uint32_t offB = ((lid >> 4) * 8 + (lid & 7)) * AROWB + ((lid >> 3) & 1) * 16;
    const uint32_t qA = sb + SQ_BASE + w * 16 * AROWB + offA;

    float o[8][4];
    #pragma unroll
    for (int nt = 0; nt < 8; ++nt)
        #pragma unroll
        for (int e = 0; e < 4; ++e) o[nt][e] = 0.f;
    float m_i[2] = {NEG_BIG, NEG_BIG};
    float l_i[2] = {0.f, 0.f};

    for (int jp = 0; jp < npairs; ++jp) {
        if (jp < npairs - 1) { CP_WAIT(1); } else { CP_WAIT(0); }
        __syncthreads();

        const uint32_t pairb = sb + SK_BASE + (jp & 1) * KVSTAGE;

        #pragma unroll
        for (int sub = 0; sub < 2; ++sub) {
            const int jt = jp * 2 + sub;          // 64-key tile index
            const uint32_t kvb = pairb + sub * SUBT;

            // ---- S = Q @ K^T (single pass, Q prefetched across kc) ----
            float s[8][4];
            #pragma unroll
            for (int nt = 0; nt < 8; ++nt)
                #pragma unroll
                for (int e = 0; e < 4; ++e) s[nt][e] = 0.f;

            uint32_t qcur[4], qnxt[4];
            ldsm_x4(qcur[0], qcur[1], qcur[2], qcur[3], qA);
            #pragma unroll
            for (int kc = 0; kc < 4; ++kc) {
                const uint32_t ko = kc * 32;
                if (kc < 3)
                    ldsm_x4(qnxt[0], qnxt[1], qnxt[2], qnxt[3], qA + ko + 32);
                #pragma unroll
                for (int p = 0; p < 4; ++p) {
                    uint32_t bk[4];
                    ldsm_x4(bk[0], bk[1], bk[2], bk[3],
                            kvb + p * 16 * AROWB + offB + ko);
                    #pragma unroll
                    for (int half = 0; half < 2; ++half) {
                        int nt = p * 2 + half;
                        mma16816(s[nt], qcur[0], qcur[1], qcur[2], qcur[3],
                                 bk[half * 2], bk[half * 2 + 1]);
                    }
                }
                #pragma unroll
                for (int e = 0; e < 4; ++e) qcur[e] = qnxt[e];
            }

            // ---- causal mask (diagonal tiles only) ----
            if (jt >= 2 * qi) {
                #pragma unroll
                for (int i = 0; i < 2; ++i) {
                    int qg = qbase + w * 16 + (lid >> 2) + i * 8;
                    #pragma unroll
                    for (int nt = 0; nt < 8; ++nt) {
                        int kg = jt * 64 + nt * 8 + (lid & 3) * 2;
                        if (kg > qg)     s[nt][2*i]     = NEG_BIG;
                        if (kg + 1 > qg) s[nt][2*i + 1] = NEG_BIG;
                    }
                }
            }

            // ---- online softmax (quad reductions) ----
            #pragma unroll
            for (int i = 0; i < 2; ++i) {
                float rm = NEG_BIG;
                #pragma unroll
                for (int nt = 0; nt < 8; ++nt)
                    rm = fmaxf(rm, fmaxf(s[nt][2*i], s[nt][2*i+1]));
                rm = fmaxf(rm, __shfl_xor_sync(0xffffffffu, rm, 1));
                rm = fmaxf(rm, __shfl_xor_sync(0xffffffffu, rm, 2));
                float mnew = fmaxf(m_i[i], rm);
                float corr = __expf(m_i[i] - mnew);
                float rs = 0.f;
                #pragma unroll
                for (int nt = 0; nt < 8; ++nt) {
                    float p0 = __expf(s[nt][2*i]     - mnew);
                    float p1 = __expf(s[nt][2*i + 1] - mnew);
                    s[nt][2*i] = p0; s[nt][2*i+1] = p1;
                    rs += p0 + p1;
                }
                rs += __shfl_xor_sync(0xffffffffu, rs, 1);
                rs += __shfl_xor_sync(0xffffffffu, rs, 2);
                l_i[i] = l_i[i] * corr + rs;
                m_i[i] = mnew;
                #pragma unroll
                for (int nt = 0; nt < 8; ++nt) {
                    o[nt][2*i]     *= corr;
                    o[nt][2*i + 1] *= corr;
                }
            }

            // ---- O += P @ V (single pass; V via ldsm.trans) ----
            #pragma unroll
            for (int kc = 0; kc < 4; ++kc) {
                uint32_t ph[4];
                ph[0] = pack_half2(s[2*kc][0],   s[2*kc][1]);
                ph[1] = pack_half2(s[2*kc][2],   s[2*kc][3]);
                ph[2] = pack_half2(s[2*kc+1][0], s[2*kc+1][1]);
                ph[3] = pack_half2(s[2*kc+1][2], s[2*kc+1][3]);

                const uint32_t vrow = kvb + 9216 +
                    (kc * 16 + ((lid >> 3) & 1) * 8 + (lid & 7)) * AROWB +
                    (lid >> 4) * 16;
                #pragma unroll
                for (int p = 0; p < 4; ++p) {
                    uint32_t vf[4];
                    ldsm_x4_t(vf[0], vf[1], vf[2], vf[3], vrow + p * 32);
                    #pragma unroll
                    for (int half = 0; half < 2; ++half) {
                        int nt = p * 2 + half;
                        mma16816(o[nt], ph[0], ph[1], ph[2], ph[3],
                                 vf[half * 2], vf[half * 2 + 1]);
                    }
                }
            }
        }

        __syncthreads();   // all warps done reading buffer (jp&1)
        if (jp + 2 < npairs) {
            att_issue_pair(sb + SK_BASE + (jp & 1) * KVSTAGE, Kk, Vv, jp + 2, tid);
            CP_COMMIT();
        }
    }

    // ---- epilogue: normalize, round to fp16, write hs ----
    #pragma unroll
    for (int i = 0; i < 2; ++i) {
        float inv = 1.f / l_i[i];
        int q = qbase + w * 16 + (lid >> 2) + i * 8;
        size_t rowidx = ((size_t)b * SEQ + q) * DMODEL + h * HD;
        #pragma unroll
        for (int nt = 0; nt < 8; ++nt) {
            int d = nt * 8 + (lid & 3) * 2;
            *(__half2*)(g_hs + rowidx + d) =
                __floats2half2_rn(o[nt][2*i] * inv, o[nt][2*i+1] * inv);
        }
    }
}

// ---------------------------------------------------------------------------
// Launch
// ---------------------------------------------------------------------------
extern "C" void kernel_launch(void* const* d_in, const int* in_sizes, int n_in,
                              void* d_out, int out_size) {
    const float* x    = (const float*)d_in[0];  // [2,2048,1024]
    const float* Wqkv = (const float*)d_in[1];  // [3072,1024]
    const float* Wo   = (const float*)d_in[2];  // [1024,1024]
    float* out = (float*)d_out;                 // [2,2048,1024]

    __half *xs, *wq, *wo, *hs;
    cudaGetSymbolAddress((void**)&xs, g_xs);
    cudaGetSymbolAddress((void**)&wq, g_wq);
    cudaGetSymbolAddress((void**)&wo, g_wo);
    cudaGetSymbolAddress((void**)&hs, g_hs);

    static bool attr_done = false;
    if (!attr_done) {
        cudaFuncSetAttribute(gemm_fp16<1>,
                             cudaFuncAttributeMaxDynamicSharedMemorySize, G4_SMEM);
        cudaFuncSetAttribute(gemm_fp16<0>,
                             cudaFuncAttributeMaxDynamicSharedMemorySize, G4_SMEM);
        cudaFuncSetAttribute(attn_mma,
                             cudaFuncAttributeMaxDynamicSharedMemorySize, ATT_SMEM);
        attr_done = true;
    }

    // Round all operands to fp16 in ONE launch
    round_all<<<4096, 256>>>(x, Wqkv, Wo);

    // 1) QKV projection with fused per-head epilogue
    {
        dim3 grid(3 * DMODEL / 128, TOKENS / 128);   // (24, 32)
        gemm_fp16<1><<<grid, GTHREADS, G4_SMEM>>>(xs, wq, nullptr,
                                                  TOKENS, 3 * DMODEL, DMODEL);
    }
    // 2) HMMA causal flash attention -> g_hs (fp16)
    {
        dim3 grid(SEQ / 128, NH, BATCH);
        attn_mma<<<grid, 256, ATT_SMEM>>>();
    }
    // 3) Output projection -> out (fp32)
    {
        dim3 grid(DMODEL / 128, TOKENS / 128);       // (8, 32)
        gemm_fp16<0><<<grid, GTHREADS, G4_SMEM>>>(hs, wo, out,
                                                  TOKENS, DMODEL, DMODEL);
    }
}